// round 8
// baseline (speedup 1.0000x reference)
#include <cuda_runtime.h>
#include <cuda_bf16.h>
#include <cstdint>
#include <math.h>

// Problem constants
#define Bz   2
#define Tz   1024
#define Cz   1024
#define Hz   16
#define Lz   8
#define Dz   64
#define HIDz 4096
#define Vz   32000
#define NTOK (Bz * Tz)          // 2048
#define EPSz 1e-5f
#define QMAX 16256.0f           // 127*128 + 64

// ---------------------------------------------------------------------------
// PTX helpers (base ISA only)
// ---------------------------------------------------------------------------
__device__ __forceinline__ uint32_t smem_u32(const void* p) {
    uint32_t a;
    asm("{ .reg .u64 t; cvta.to.shared.u64 t, %1; cvt.u32.u64 %0, t; }"
        : "=r"(a) : "l"(p));
    return a;
}
__device__ __forceinline__ void ldsm_x4(uint32_t* r, uint32_t addr) {
    asm volatile("ldmatrix.sync.aligned.m8n8.x4.shared.b16 {%0,%1,%2,%3}, [%4];"
        : "=r"(r[0]), "=r"(r[1]), "=r"(r[2]), "=r"(r[3]) : "r"(addr));
}
__device__ __forceinline__ void ldsm_x4t(uint32_t* r, uint32_t addr) {
    asm volatile("ldmatrix.sync.aligned.m8n8.x4.trans.shared.b16 {%0,%1,%2,%3}, [%4];"
        : "=r"(r[0]), "=r"(r[1]), "=r"(r[2]), "=r"(r[3]) : "r"(addr));
}
__device__ __forceinline__ void mma16816(float* d, const uint32_t* a, const uint32_t* b) {
    asm volatile("mma.sync.aligned.m16n8k16.row.col.f32.bf16.bf16.f32 "
        "{%0,%1,%2,%3}, {%4,%5,%6,%7}, {%8,%9}, {%0,%1,%2,%3};"
        : "+f"(d[0]), "+f"(d[1]), "+f"(d[2]), "+f"(d[3])
        : "r"(a[0]), "r"(a[1]), "r"(a[2]), "r"(a[3]), "r"(b[0]), "r"(b[1]));
}
__device__ __forceinline__ void mma_s8(int* d, const uint32_t* a, const uint32_t* b) {
    asm volatile("mma.sync.aligned.m16n8k32.row.col.s32.s8.s8.s32 "
        "{%0,%1,%2,%3}, {%4,%5,%6,%7}, {%8,%9}, {%0,%1,%2,%3};"
        : "+r"(d[0]), "+r"(d[1]), "+r"(d[2]), "+r"(d[3])
        : "r"(a[0]), "r"(a[1]), "r"(a[2]), "r"(a[3]), "r"(b[0]), "r"(b[1]));
}
__device__ __forceinline__ void cp16(uint32_t saddr, const void* gaddr) {
    asm volatile("cp.async.ca.shared.global [%0], [%1], 16;"
                 :: "r"(saddr), "l"(gaddr) : "memory");
}
#define CP_COMMIT() asm volatile("cp.async.commit_group;" ::: "memory")
#define CP_WAIT1()  asm volatile("cp.async.wait_group 1;" ::: "memory")
#define CP_WAIT0()  asm volatile("cp.async.wait_group 0;" ::: "memory")

__device__ __forceinline__ uint32_t packbf(float x, float y) {
    __nv_bfloat162 t;
    t.x = __float2bfloat16(x);
    t.y = __float2bfloat16(y);
    return *(uint32_t*)&t;
}

// ---------------------------------------------------------------------------
// Scratch (device globals)
// ---------------------------------------------------------------------------
__device__ float g_x[NTOK * Cz];                 // residual stream
__device__ float g_attf[NTOK * Cz];              // attention out (fp32)
__device__ float g_ffnf[NTOK * HIDz];            // fc1+gelu out (fp32)
__device__ __nv_bfloat16 g_qkvh[NTOK * 3 * Cz];  // qkv bf16 hi/lo (attention)
__device__ __nv_bfloat16 g_qkvl[NTOK * 3 * Cz];
// int8 activations (hi=*1, lo=*0) + row scales
__device__ int8_t g_h1[NTOK * Cz];
__device__ int8_t g_h0[NTOK * Cz];
__device__ float  g_sah[NTOK];
__device__ int8_t g_at1[NTOK * Cz];
__device__ int8_t g_at0[NTOK * Cz];
__device__ float  g_saat[NTOK];
__device__ int8_t g_f1[NTOK * HIDz];
__device__ int8_t g_f0[NTOK * HIDz];
__device__ float  g_saf[NTOK];
// int8 weights [N,K] + per-row(N) scales
__device__ int8_t g_wq1[Lz * 3 * Cz * Cz];
__device__ int8_t g_wq0[Lz * 3 * Cz * Cz];
__device__ float  g_sbq[Lz * 3 * Cz];
__device__ int8_t g_wp1[Lz * Cz * Cz];
__device__ int8_t g_wp0[Lz * Cz * Cz];
__device__ float  g_sbp[Lz * Cz];
__device__ int8_t g_w11[Lz * HIDz * Cz];
__device__ int8_t g_w10[Lz * HIDz * Cz];
__device__ float  g_sb1[Lz * HIDz];
__device__ int8_t g_w21[Lz * Cz * HIDz];
__device__ int8_t g_w20[Lz * Cz * HIDz];
__device__ float  g_sb2[Lz * Cz];
__device__ int8_t g_t1[Vz * Cz];
__device__ int8_t g_t0[Vz * Cz];
__device__ float  g_st[Vz];

// ---------------------------------------------------------------------------
// colmax: per-output-row (column of W[K,N]) scale
// ---------------------------------------------------------------------------
__global__ void colmax_kernel(const float* __restrict__ W, float* __restrict__ sb,
                              int K, int N) {
    int n = blockIdx.x * 256 + threadIdx.x;
    const float* Wl = W + (size_t)blockIdx.z * K * N;
    float mx = 0.f;
    for (int k = 0; k < K; k++)
        mx = fmaxf(mx, fabsf(Wl[(size_t)k * N + n]));
    sb[blockIdx.z * N + n] = mx > 0.f ? mx / QMAX : 1.f;
}

// ---------------------------------------------------------------------------
// wtrans_q: transpose [K,N] -> [N,K] and quantize to int8 hi/lo
// ---------------------------------------------------------------------------
__global__ void wtrans_q(const float* __restrict__ W, const float* __restrict__ sb,
                         int8_t* __restrict__ T1, int8_t* __restrict__ T0,
                         int K, int N) {
    __shared__ float t[32][33];
    const float* Wl = W + (size_t)blockIdx.z * K * N;
    const float* sbl = sb + (size_t)blockIdx.z * N;
    int8_t* T1l = T1 + (size_t)blockIdx.z * K * N;
    int8_t* T0l = T0 + (size_t)blockIdx.z * K * N;
    int n0 = blockIdx.x * 32, k0 = blockIdx.y * 32;
    int tx = threadIdx.x, ty = threadIdx.y;
#pragma unroll
    for (int j = 0; j < 32; j += 8)
        t[ty + j][tx] = Wl[(size_t)(k0 + ty + j) * N + n0 + tx];
    __syncthreads();
#pragma unroll
    for (int j = 0; j < 32; j += 8) {
        int n = n0 + ty + j;
        float xs = t[tx][ty + j] / sbl[n];
        int q1 = __float2int_rn(xs * (1.f / 128.f));
        int q0 = __float2int_rn(xs - 128.f * (float)q1);
        size_t o = (size_t)n * K + k0 + tx;
        T1l[o] = (int8_t)q1;
        T0l[o] = (int8_t)q0;
    }
}

// ---------------------------------------------------------------------------
// quant8_rows: fp32 [M,K] -> int8 hi/lo + row scale. One block per row.
// ---------------------------------------------------------------------------
__global__ void quant8_rows(const float* __restrict__ X,
                            int8_t* __restrict__ A1, int8_t* __restrict__ A0,
                            float* __restrict__ sa, int K) {
    __shared__ float shm[8];
    int row = blockIdx.x, tid = threadIdx.x;
    int lane = tid & 31, wid = tid >> 5;
    const float* xr = X + (size_t)row * K;
    float mx = 0.f;
    for (int i = tid; i < K; i += 256) mx = fmaxf(mx, fabsf(xr[i]));
    for (int off = 16; off > 0; off >>= 1)
        mx = fmaxf(mx, __shfl_xor_sync(0xffffffffu, mx, off));
    if (lane == 0) shm[wid] = mx;
    __syncthreads();
    if (wid == 0) {
        float m2 = (lane < 8) ? shm[lane] : 0.f;
        for (int off = 4; off > 0; off >>= 1)
            m2 = fmaxf(m2, __shfl_xor_sync(0xffffffffu, m2, off));
        if (lane == 0) shm[0] = m2;
    }
    __syncthreads();
    float rm = shm[0];
    float scale = rm > 0.f ? rm / QMAX : 1.f;
    if (tid == 0) sa[row] = scale;
    float inv = 1.f / scale;
    char4* o1 = (char4*)(A1 + (size_t)row * K);
    char4* o0 = (char4*)(A0 + (size_t)row * K);
    const float4* x4 = (const float4*)xr;
    for (int q = tid; q < K / 4; q += 256) {
        float4 v = x4[q];
        char4 c1, c0;
        float xs;
        int q1;
        xs = v.x * inv; q1 = __float2int_rn(xs * (1.f / 128.f));
        c1.x = (signed char)q1; c0.x = (signed char)__float2int_rn(xs - 128.f * q1);
        xs = v.y * inv; q1 = __float2int_rn(xs * (1.f / 128.f));
        c1.y = (signed char)q1; c0.y = (signed char)__float2int_rn(xs - 128.f * q1);
        xs = v.z * inv; q1 = __float2int_rn(xs * (1.f / 128.f));
        c1.z = (signed char)q1; c0.z = (signed char)__float2int_rn(xs - 128.f * q1);
        xs = v.w * inv; q1 = __float2int_rn(xs * (1.f / 128.f));
        c1.w = (signed char)q1; c0.w = (signed char)__float2int_rn(xs - 128.f * q1);
        o1[q] = c1;
        o0[q] = c0;
    }
}

// ---------------------------------------------------------------------------
// ln_q: LayerNorm + int8 quantize (one block per row, C=1024)
// ---------------------------------------------------------------------------
__global__ void ln_q(const float* __restrict__ x,
                     int8_t* __restrict__ A1, int8_t* __restrict__ A0,
                     float* __restrict__ sa,
                     const float* __restrict__ g, const float* __restrict__ b) {
    __shared__ float vbuf[Cz];
    __shared__ float sh_s[8], sh_s2[8], shm[8];
    int row = blockIdx.x, tid = threadIdx.x;
    int lane = tid & 31, wid = tid >> 5;
    const float* xr = x + (size_t)row * Cz;
    float s = 0.f, s2 = 0.f;
    for (int i = tid; i < Cz; i += 256) {
        float v = xr[i];
        s += v; s2 += v * v;
    }
    for (int off = 16; off > 0; off >>= 1) {
        s  += __shfl_down_sync(0xffffffffu, s,  off);
        s2 += __shfl_down_sync(0xffffffffu, s2, off);
    }
    if (lane == 0) { sh_s[wid] = s; sh_s2[wid] = s2; }
    __syncthreads();
    if (wid == 0) {
        s  = (lane < 8) ? sh_s[lane]  : 0.f;
        s2 = (lane < 8) ? sh_s2[lane] : 0.f;
        for (int off = 4; off > 0; off >>= 1) {
            s  += __shfl_down_sync(0xffffffffu, s,  off);
            s2 += __shfl_down_sync(0xffffffffu, s2, off);
        }
        if (lane == 0) { sh_s[0] = s; sh_s2[0] = s2; }
    }
    __syncthreads();
    float mean = sh_s[0] * (1.f / Cz);
    float var  = sh_s2[0] * (1.f / Cz) - mean * mean;
    float rstd = rsqrtf(var + EPSz);
    float mx = 0.f;
    for (int i = tid; i < Cz; i += 256) {
        float v = (xr[i] - mean) * rstd * g[i] + b[i];
        vbuf[i] = v;
        mx = fmaxf(mx, fabsf(v));
    }
    for (int off = 16; off > 0; off >>= 1)
        mx = fmaxf(mx, __shfl_xor_sync(0xffffffffu, mx, off));
    if (lane == 0) shm[wid] = mx;
    __syncthreads();
    if (wid == 0) {
        float m2 = (lane < 8) ? shm[lane] : 0.f;
        for (int off = 4; off > 0; off >>= 1)
            m2 = fmaxf(m2, __shfl_xor_sync(0xffffffffu, m2, off));
        if (lane == 0) shm[0] = m2;
    }
    __syncthreads();
    float rm = shm[0];
    float scale = rm > 0.f ? rm / QMAX : 1.f;
    if (tid == 0) sa[row] = scale;
    float inv = 1.f / scale;
    char4 c1, c0;
    int i0 = tid * 4;
    float xs;
    int q1;
    xs = vbuf[i0 + 0] * inv; q1 = __float2int_rn(xs * (1.f / 128.f));
    c1.x = (signed char)q1; c0.x = (signed char)__float2int_rn(xs - 128.f * q1);
    xs = vbuf[i0 + 1] * inv; q1 = __float2int_rn(xs * (1.f / 128.f));
    c1.y = (signed char)q1; c0.y = (signed char)__float2int_rn(xs - 128.f * q1);
    xs = vbuf[i0 + 2] * inv; q1 = __float2int_rn(xs * (1.f / 128.f));
    c1.z = (signed char)q1; c0.z = (signed char)__float2int_rn(xs - 128.f * q1);
    xs = vbuf[i0 + 3] * inv; q1 = __float2int_rn(xs * (1.f / 128.f));
    c1.w = (signed char)q1; c0.w = (signed char)__float2int_rn(xs - 128.f * q1);
    ((char4*)(A1 + (size_t)row * Cz))[tid] = c1;
    ((char4*)(A0 + (size_t)row * Cz))[tid] = c0;
}

// ---------------------------------------------------------------------------
// gemm_q: int8 3-pass GEMM. Block 128x128, 8 warps (64x32), BK=64 int8,
// NSTG=3. SMEM geometry identical to validated R5 kernel (64B rows, pitch 80).
// C = sa[m]*sb[n]*(16384*H + 128*M)  (+bias,+gelu,+res)
// ---------------------------------------------------------------------------
#define QPITCH 80
#define Q_A1 0
#define Q_A0 10240
#define Q_B1 20480
#define Q_B0 30720
#define Q_STG 40960
#define Q_GSMEM (3 * Q_STG)

__global__ __launch_bounds__(256)
void gemm_q(const int8_t* __restrict__ A1, const int8_t* __restrict__ A0,
            const float* __restrict__ saA,
            const int8_t* __restrict__ B1, const int8_t* __restrict__ B0,
            const float* __restrict__ sbB,
            float* __restrict__ Cf,
            __nv_bfloat16* __restrict__ Ch, __nv_bfloat16* __restrict__ Cl,
            int M, int N, int K,
            const float* __restrict__ bias, const float* __restrict__ res,
            int gelu) {
    extern __shared__ __align__(128) char smem[];
    uint32_t smb = smem_u32(smem);
    int tid = threadIdx.x, wid = tid >> 5, lane = tid & 31;
    int m0 = blockIdx.y * 128, n0 = blockIdx.x * 128;
    int wm = wid & 1, wn = wid >> 1;

    const int8_t* Ag1 = A1 + (size_t)m0 * K;
    const int8_t* Ag0 = A0 + (size_t)m0 * K;
    const int8_t* Bg1 = B1 + (size_t)n0 * K;
    const int8_t* Bg0 = B0 + (size_t)n0 * K;

    int hacc[4][4][4], macc[4][4][4];
#pragma unroll
    for (int i = 0; i < 4; i++)
#pragma unroll
        for (int j = 0; j < 4; j++)
#pragma unroll
            for (int r = 0; r < 4; r++) { hacc[i][j][r] = 0; macc[i][j][r] = 0; }

    const int NC = K >> 6;

#define ISSUE_Q(c)                                                             \
    {                                                                          \
        uint32_t s0 = smb + ((c) % 3) * Q_STG;                                 \
        _Pragma("unroll")                                                      \
        for (int it = 0; it < 2; it++) {                                       \
            int i = it * 256 + tid;                                            \
            int row = i >> 2, seg = i & 3;                                     \
            uint32_t so = row * QPITCH + seg * 16;                             \
            size_t go = (size_t)row * K + (size_t)(c) * 64 + seg * 16;         \
            cp16(s0 + Q_A1 + so, Ag1 + go);                                    \
            cp16(s0 + Q_A0 + so, Ag0 + go);                                    \
            cp16(s0 + Q_B1 + so, Bg1 + go);                                    \
            cp16(s0 + Q_B0 + so, Bg0 + go);                                    \
        }                                                                      \
        CP_COMMIT();                                                           \
    }

    ISSUE_Q(0);
    ISSUE_Q(1);

    int r16 = lane & 15, hsel = lane >> 4;
    int bg = lane >> 3;
    int browoff = ((bg & 2) << 2) + (lane & 7);
    int b16off = (bg & 1) * 16;

    for (int c = 0; c < NC; c++) {
        if (c + 1 < NC) { CP_WAIT1(); } else { CP_WAIT0(); }
        __syncthreads();
        if (c + 2 < NC) ISSUE_Q(c + 2);
        uint32_t base = smb + (c % 3) * Q_STG;
#pragma unroll
        for (int kk2 = 0; kk2 < 2; kk2++) {
            uint32_t a1f[16], a0f[16], b1f[8], b0f[8];
#pragma unroll
            for (int mt = 0; mt < 4; mt++) {
                uint32_t ad = (uint32_t)((wm * 64 + mt * 16 + r16) * QPITCH +
                                         kk2 * 32 + hsel * 16);
                ldsm_x4(a1f + 4 * mt, base + Q_A1 + ad);
                ldsm_x4(a0f + 4 * mt, base + Q_A0 + ad);
            }
#pragma unroll
            for (int ntp = 0; ntp < 2; ntp++) {
                uint32_t bd = (uint32_t)((wn * 32 + ntp * 16 + browoff) * QPITCH +
                                         kk2 * 32 + b16off);
                ldsm_x4(b1f + 4 * ntp, base + Q_B1 + bd);
                ldsm_x4(b0f + 4 * ntp, base + Q_B0 + bd);
            }
#pragma unroll
            for (int mt = 0; mt < 4; mt++)
#pragma unroll
                for (int nt = 0; nt < 4; nt++) {
                    uint32_t* bp1 = b1f + (nt >> 1) * 4 + (nt & 1) * 2;
                    uint32_t* bp0 = b0f + (nt >> 1) * 4 + (nt & 1) * 2;
                    mma_s8(hacc[mt][nt], a1f + 4 * mt, bp1);
                    mma_s8(macc[mt][nt], a1f + 4 * mt, bp0);
                    mma_s8(macc[mt][nt], a0f + 4 * mt, bp1);
                }
        }
        __syncthreads();
    }
#undef ISSUE_Q

    int gid = lane >> 2, qid = lane & 3;
#pragma unroll
    for (int mt = 0; mt < 4; mt++) {
        float sam[2];
        sam[0] = saA[m0 + wm * 64 + mt * 16 + gid];
        sam[1] = saA[m0 + wm * 64 + mt * 16 + gid + 8];
#pragma unroll
        for (int nt = 0; nt < 4; nt++) {
            int n = n0 + wn * 32 + nt * 8 + 2 * qid;
            float sbn0 = sbB[n], sbn1 = sbB[n + 1];
            float bsum0 = bias ? bias[n] : 0.f;
            float bsum1 = bias ? bias[n + 1] : 0.f;
#pragma unroll
            for (int half = 0; half < 2; half++) {
                int m = m0 + wm * 64 + mt * 16 + gid + half * 8;
                float raw0 = 16384.f * (float)hacc[mt][nt][half * 2 + 0] +
                             128.f * (float)macc[mt][nt][half * 2 + 0];
                float raw1 = 16384.f * (float)hacc[mt][nt][half * 2 + 1] +
                             128.f * (float)macc[mt][nt][half * 2 + 1];
                float v0 = sam[half] * sbn0 * raw0 + bsum0;
                float v1 = sam[half] * sbn1 * raw1 + bsum1;
                if (gelu) {
                    v0 = 0.5f * v0 * (1.f + erff(v0 * 0.70710678118654752f));
                    v1 = 0.5f * v1 * (1.f + erff(v1 * 0.70710678118654752f));
                }
                if (res) {
                    const float* rr = res + (size_t)m * N + n;
                    v0 += rr[0];
                    v1 += rr[1];
                }
                if (Cf) {
                    float2 o;
                    o.x = v0; o.y = v1;
                    *(float2*)(Cf + (size_t)m * N + n) = o;
                }
                if (Ch) {
                    __nv_bfloat162 oh, ol;
                    oh.x = __float2bfloat16(v0);
                    oh.y = __float2bfloat16(v1);
                    ol.x = __float2bfloat16(v0 - __bfloat162float(oh.x));
                    ol.y = __float2bfloat16(v1 - __bfloat162float(oh.y));
                    *(__nv_bfloat162*)(Ch + (size_t)m * N + n) = oh;
                    *(__nv_bfloat162*)(Cl + (size_t)m * N + n) = ol;
                }
            }
        }
    }
}

// ---------------------------------------------------------------------------
// MMA flash attention (R5-validated; epilogue now writes fp32)
// ---------------------------------------------------------------------------
#define APITCH  144
#define AT_TILE 9216
#define AT_Q    0
#define AT_KV0  (2 * AT_TILE)
#define AT_KVS  (4 * AT_TILE)
#define AT_SMEM (AT_KV0 + 2 * AT_KVS)

__global__ __launch_bounds__(128)
void attn_mma(const __nv_bfloat16* __restrict__ qkvh,
              const __nv_bfloat16* __restrict__ qkvl,
              float* __restrict__ att) {
    extern __shared__ __align__(128) char smem[];
    uint32_t sb = smem_u32(smem);
    int tid = threadIdx.x, w = tid >> 5, lane = tid & 31;
    int qi = (int)gridDim.x - 1 - (int)blockIdx.x;
    int bh = blockIdx.y;
    int b = bh >> 4, h = bh & 15;
    const int RS = 3 * Cz;
    const size_t tokbase = (size_t)(b * Tz) * RS + h * Dz;

    int gid = lane >> 2, qid = lane & 3;
    int r16 = lane & 15, hsel = lane >> 4;
    int bg = lane >> 3;
    int browoff = ((bg & 2) << 2) + (lane & 7);
    int bkoff = (bg & 1) * 8;
    int t_row = (bg & 1) * 8 + (lane & 7);
    int t_col = (bg >> 1) * 8;

#define ISSUE_KV(kt)                                                           \
    {                                                                          \
        uint32_t s0 = sb + AT_KV0 + ((kt) & 1) * AT_KVS;                       \
        const __nv_bfloat16* srcs[4] = {                                       \
            qkvh + tokbase + Cz, qkvl + tokbase + Cz,                          \
            qkvh + tokbase + 2 * Cz, qkvl + tokbase + 2 * Cz };                \
        _Pragma("unroll")                                                      \
        for (int t = 0; t < 4; t++) {                                          \
            _Pragma("unroll")                                                  \
            for (int it = 0; it < 4; it++) {                                   \
                int i = it * 128 + tid;                                        \
                int r = i >> 3, s = i & 7;                                     \
                cp16(s0 + t * AT_TILE + r * APITCH + s * 16,                   \
                     srcs[t] + (size_t)((kt) * 64 + r) * RS + s * 8);          \
            }                                                                  \
        }                                                                      \
        CP_COMMIT();                                                           \
    }

    {
#pragma unroll
        for (int t = 0; t < 2; t++) {
            const __nv_bfloat16* src = (t ? qkvl : qkvh) + tokbase;
            uint32_t dst = sb + AT_Q + t * AT_TILE;
#pragma unroll
            for (int it = 0; it < 4; it++) {
                int i = it * 128 + tid;
                int r = i >> 3, s = i & 7;
                cp16(dst + r * APITCH + s * 16,
                     src + (size_t)(qi * 64 + r) * RS + s * 8);
            }
        }
        uint32_t s0 = sb + AT_KV0;
        const __nv_bfloat16* srcs[4] = {
            qkvh + tokbase + Cz, qkvl + tokbase + Cz,
            qkvh + tokbase + 2 * Cz, qkvl + tokbase + 2 * Cz };
#pragma unroll
        for (int t = 0; t < 4; t++) {
#pragma unroll
            for (int it = 0; it < 4; it++) {
                int i = it * 128 + tid;
                int r = i >> 3, s = i & 7;
                cp16(s0 + t * AT_TILE + r * APITCH + s * 16,
                     srcs[t] + (size_t)r * RS + s * 8);
            }
        }
        CP_COMMIT();
    }
    if (qi >= 1) ISSUE_KV(1);

    if (qi >= 1) { CP_WAIT1(); } else { CP_WAIT0(); }
    __syncthreads();

    uint32_t qfh[4][4], qfl[4][4];
#pragma unroll
    for (int kk = 0; kk < 4; kk++) {
        uint32_t ad = sb + AT_Q + (uint32_t)((w * 16 + r16) * APITCH +
                                             (kk * 16 + hsel * 8) * 2);
        ldsm_x4(qfh[kk], ad);
        ldsm_x4(qfl[kk], ad + AT_TILE);
    }

    float oacc[8][4];
#pragma unroll
    for (int i = 0; i < 8; i++)
#pragma unroll
        for (int j = 0; j < 4; j++) oacc[i][j] = 0.f;
    float mrow[2] = {-1e30f, -1e30f};
    float lrow[2] = {0.f, 0.f};

    for (int kt = 0; kt <= qi; kt++) {
        if (kt > 0) {
            if (kt < qi) { CP_WAIT1(); } else { CP_WAIT0(); }
            __syncthreads();
        }
        uint32_t kb = sb + AT_KV0 + (kt & 1) * AT_KVS;

        float s[8][4];
#pragma unroll
        for (int i = 0; i < 8; i++)
#pragma unroll
            for (int j = 0; j < 4; j++) s[i][j] = 0.f;
#pragma unroll
        for (int kk = 0; kk < 4; kk++) {
            uint32_t kh[16], kl[16];
#pragma unroll
            for (int np = 0; np < 4; np++) {
                uint32_t ad = kb + (uint32_t)((np * 16 + browoff) * APITCH +
                                              (kk * 16 + bkoff) * 2);
                ldsm_x4(kh + 4 * np, ad);
                ldsm_x4(kl + 4 * np, ad + AT_TILE);
            }
#pragma unroll
            for (int nt = 0; nt < 8; nt++) {
                uint32_t* bp = kh + (nt >> 1) * 4 + (nt & 1) * 2;
                uint32_t* bl2 = kl + (nt >> 1) * 4 + (nt & 1) * 2;
                mma16816(s[nt], qfh[kk], bp);
                mma16816(s[nt], qfh[kk], bl2);
                mma16816(s[nt], qfl[kk], bp);
            }
        }
#pragma unroll
        for (int nt = 0; nt < 8; nt++)
#pragma unroll
            for (int j = 0; j < 4; j++) s[nt][j] *= 0.125f;
        if (kt == qi) {
#pragma unroll
            for (int nt = 0; nt < 8; nt++)
#pragma unroll
                for (int j = 0; j < 4; j++) {
                    int kc = 8 * nt + 2 * qid + (j & 1);
                    int qr = w * 16 + gid + (j >> 1) * 8;
                    if (kc > qr) s[nt][j] = -1e30f;
                }
        }
        float mt0 = -1e30f, mt1 = -1e30f;
#pragma unroll
        for (int nt = 0; nt < 8; nt++) {
            mt0 = fmaxf(mt0, fmaxf(s[nt][0], s[nt][1]));
            mt1 = fmaxf(mt1, fmaxf(s[nt][2], s[nt][3]));
        }
        mt0 = fmaxf(mt0, __shfl_xor_sync(0xffffffffu, mt0, 1));
        mt0 = fmaxf(mt0, __shfl_xor_sync(0xffffffffu, mt0, 2));
        mt1 = fmaxf(mt1, __shfl_xor_sync(0xffffffffu, mt1, 1));
        mt1 = fmaxf(mt1, __shfl_xor_sync(0xffffffffu, mt1, 2));
        float mn0 = fmaxf(mrow[0], mt0), mn1 = fmaxf(mrow[1], mt1);
        float c0 = __expf(mrow[0] - mn0), c1 = __expf(mrow[1] - mn1);
        mrow[0] = mn0; mrow[1] = mn1;
        float rs0 = 0.f, rs1 = 0.f;
#pragma unroll
        for (int nt = 0; nt < 8; nt++) {
            s[nt][0] = __expf(s[nt][0] - mn0);
            s[nt][1] = __expf(s[nt][1] - mn0);
            s[nt][2] = __expf(s[nt][2] - mn1);
            s[nt][3] = __expf(s[nt][3] - mn1);
            rs0 += s[nt][0] + s[nt][1];
            rs1 += s[nt][2] + s[nt][3];
        }
        rs0 += __shfl_xor_sync(0xffffffffu, rs0, 1);
        rs0 += __shfl_xor_sync(0xffffffffu, rs0, 2);
        rs1 += __shfl_xor_sync(0xffffffffu, rs1, 1);
        rs1 += __shfl_xor_sync(0xffffffffu, rs1, 2);
        lrow[0] = lrow[0] * c0 + rs0;
        lrow[1] = lrow[1] * c1 + rs1;
#pragma unroll
        for (int nt = 0; nt < 8; nt++) {
            oacc[nt][0] *= c0; oacc[nt][1] *= c0;
            oacc[nt][2] *= c1; oacc[nt][3] *= c1;
        }
#pragma unroll
        for (int k2 = 0; k2 < 4; k2++) {
            uint32_t pah[4], pal[4];
            {
                float p00 = s[2 * k2][0],     p01 = s[2 * k2][1];
                float p10 = s[2 * k2][2],     p11 = s[2 * k2][3];
                float p20 = s[2 * k2 + 1][0], p21 = s[2 * k2 + 1][1];
                float p30 = s[2 * k2 + 1][2], p31 = s[2 * k2 + 1][3];
                pah[0] = packbf(p00, p01);
                pah[1] = packbf(p10, p11);
                pah[2] = packbf(p20, p21);
                pah[3] = packbf(p30, p31);
                __nv_bfloat162* hp;
                hp = (__nv_bfloat162*)&pah[0];
                pal[0] = packbf(p00 - __bfloat162float(hp->x), p01 - __bfloat162float(hp->y));
                hp = (__nv_bfloat162*)&pah[1];
                pal[1] = packbf(p10 - __bfloat162float(hp->x), p11 - __bfloat162float(hp->y));
                hp = (__nv_bfloat162*)&pah[2];
                pal[2] = packbf(p20 - __bfloat162float(hp->x), p21 - __bfloat162float(hp->y));
                hp = (__nv_bfloat162*)&pah[3];
                pal[3] = packbf(p30 - __bfloat162float(hp->x), p31 - __bfloat162float(hp->y));
            }
            uint32_t vh[16], vl[16];
#pragma unroll
            for (int np = 0; np < 4; np++) {
                uint32_t ad = kb + 2 * AT_TILE +
                              (uint32_t)((k2 * 16 + t_row) * APITCH +
                                         (np * 16 + t_col) * 2);
                ldsm_x4t(vh + 4 * np, ad);
                ldsm_x4t(vl + 4 * np, ad + AT_TILE);
            }
#pragma unroll
            for (int nt = 0; nt < 8; nt++) {
                uint32_t* bp = vh + (nt >> 1) * 4 + (nt & 1) * 2;
                uint32_t* bl2 = vl + (nt >> 1) * 4 + (nt & 1) * 2;
                mma16816(oacc[nt], pah, bp);
                mma16816(oacc[nt], pah, bl2);
                mma16816(oacc[nt], pal, bp);
            }
        }
        __syncthreads();
        if (kt + 2 <= qi) ISSUE_KV(kt + 2);
    }
#undef ISSUE_KV

    float inv0 = 1.f / lrow[0], inv1 = 1.f / lrow[1];
    int tok0 = b * Tz + qi * 64 + w * 16 + gid;
#pragma unroll
    for (int nt = 0; nt < 8; nt++) {
        int col = h * Dz + 8 * nt + 2 * qid;
        float2 o;
        o.x = oacc[nt][0] * inv0;
        o.y = oacc[nt][1] * inv0;
        *(float2*)(att + (size_t)tok0 * Cz + col) = o;
        o.x = oacc[nt][2] * inv1;
        o.y = oacc[nt][3] * inv1;
        *(float2*)(att + (size_t)(tok0 + 8) * Cz + col) = o;
    }
}

// ---------------------------------------------------------------------------
// Embedding
// ---------------------------------------------------------------------------
__global__ void embed_kernel(const int* __restrict__ idx,
                             const float* __restrict__ tok,
                             const float* __restrict__ pos,
                             float* __restrict__ x) {
    int row = blockIdx.x;
    int t   = row & (Tz - 1);
    int tokid = idx[row];
    const float* te = tok + (size_t)tokid * Cz;
    const float* pe = pos + (size_t)t * Cz;
    float* xr = x + (size_t)row * Cz;
    for (int i = threadIdx.x; i < Cz; i += blockDim.x)
        xr[i] = te[i] + pe[i];
}

// ---------------------------------------------------------------------------
// Launch
// ---------------------------------------------------------------------------
extern "C" void kernel_launch(void* const* d_in, const int* in_sizes, int n_in,
                              void* d_out, int out_size) {
    const int*   idx     = (const int*)  d_in[0];
    const float* tok_emb = (const float*)d_in[1];
    const float* pos_emb = (const float*)d_in[2];
    const float* qkv_w   = (const float*)d_in[3];
    const float* proj_w  = (const float*)d_in[4];
    const float* proj_b  = (const float*)d_in[5];
    const float* ln1_g   = (const float*)d_in[6];
    const float* ln1_b   = (const float*)d_in[7];
    const float* ln2_g   = (const float*)d_in[8];
    const float* ln2_b   = (const float*)d_in[9];
    const float* fc1_w   = (const float*)d_in[10];
    const float* fc1_b   = (const float*)d_in[11];
    const float* fc2_w   = (const float*)d_in[12];
    const float* fc2_b   = (const float*)d_in[13];
    const float* lnf_g   = (const float*)d_in[14];
    const float* lnf_b   = (const float*)d_in[15];
    float* out = (float*)d_out;

    float *x, *attf, *ffnf;
    cudaGetSymbolAddress((void**)&x,    g_x);
    cudaGetSymbolAddress((void**)&attf, g_attf);
    cudaGetSymbolAddress((void**)&ffnf, g_ffnf);
    __nv_bfloat16 *qkvh, *qkvl;
    cudaGetSymbolAddress((void**)&qkvh, g_qkvh);
    cudaGetSymbolAddress((void**)&qkvl, g_qkvl);
    int8_t *h1, *h0, *at1, *at0, *f1, *f0;
    float *sah, *saat, *saf;
    cudaGetSymbolAddress((void**)&h1,  g_h1);
    cudaGetSymbolAddress((void**)&h0,  g_h0);
    cudaGetSymbolAddress((void**)&sah, g_sah);
    cudaGetSymbolAddress((void**)&at1, g_at1);
    cudaGetSymbolAddress((void**)&at0, g_at0);
    cudaGetSymbolAddress((void**)&saat, g_saat);
    cudaGetSymbolAddress((void**)&f1,  g_f1);
    cudaGetSymbolAddress((void**)&f0,  g_f0);
    cudaGetSymbolAddress((void**)&saf, g_saf);
    int8_t *wq1, *wq0, *wp1, *wp0, *w11, *w10, *w21, *w20, *t1, *t0;
    float *sbq, *sbp, *sb1, *sb2, *st;
    cudaGetSymbolAddress((void**)&wq1, g_wq1);
    cudaGetSymbolAddress((void**)&wq0, g_wq0);
    cudaGetSymbolAddress((void**)&sbq, g_sbq);
    cudaGetSymbolAddress((void**)&wp1, g_wp1);
    cudaGetSymbolAddress((void**)&wp0, g_wp0);
    cudaGetSymbolAddress((void**)&sbp, g_sbp);
    cudaGetSymbolAddress((void**)&w11, g_w11);
    cudaGetSymbolAddress((void**)&w10, g_w10);
    cudaGetSymbolAddress((void**)&sb1, g_sb1);
    cudaGetSymbolAddress((void**)&w21, g_w21);
    cudaGetSymbolAddress((void**)&w20, g_w20);
    cudaGetSymbolAddress((void**)&sb2, g_sb2);
    cudaGetSymbolAddress((void**)&t1,  g_t1);
    cudaGetSymbolAddress((void**)&t0,  g_t0);
    cudaGetSymbolAddress((void**)&st,  g_st);

    cudaFuncSetAttribute(gemm_q,  cudaFuncAttributeMaxDynamicSharedMemorySize, Q_GSMEM);
    cudaFuncSetAttribute(attn_mma, cudaFuncAttributeMaxDynamicSharedMemorySize, AT_SMEM);

    // ---- weight prep ----
    dim3 tb(32, 8);
    colmax_kernel<<<dim3(3 * Cz / 256, 1, Lz), 256>>>(qkv_w, sbq, Cz, 3 * Cz);
    wtrans_q<<<dim3(3 * Cz / 32, Cz / 32, Lz), tb>>>(qkv_w, sbq, wq1, wq0, Cz, 3 * Cz);
    colmax_kernel<<<dim3(Cz / 256, 1, Lz), 256>>>(proj_w, sbp, Cz, Cz);
    wtrans_q<<<dim3(Cz / 32, Cz / 32, Lz), tb>>>(proj_w, sbp, wp1, wp0, Cz, Cz);
    colmax_kernel<<<dim3(HIDz / 256, 1, Lz), 256>>>(fc1_w, sb1, Cz, HIDz);
    wtrans_q<<<dim3(HIDz / 32, Cz / 32, Lz), tb>>>(fc1_w, sb1, w11, w10, Cz, HIDz);
    colmax_kernel<<<dim3(Cz / 256, 1, Lz), 256>>>(fc2_w, sb2, HIDz, Cz);
    wtrans_q<<<dim3(Cz / 32, HIDz / 32, Lz), tb>>>(fc2_w, sb2, w21, w20, HIDz, Cz);
    quant8_rows<<<Vz, 256>>>(tok_emb, t1, t0, st, Cz);

    embed_kernel<<<NTOK, 256>>>(idx, tok_emb, pos_emb, x);

    for (int l = 0; l < Lz; l++) {
        const int8_t* q1w = wq1 + (size_t)l * 3 * Cz * Cz;
        const int8_t* q0w = wq0 + (size_t)l * 3 * Cz * Cz;
        const float*  qs  = sbq + (size_t)l * 3 * Cz;
        const int8_t* p1w = wp1 + (size_t)l * Cz * Cz;
        const int8_t* p0w = wp0 + (size_t)l * Cz * Cz;
        const float*  ps  = sbp + (size_t)l * Cz;
        const int8_t* f1w = w11 + (size_t)l * HIDz * Cz;
        const int8_t* f0w = w10 + (size_t)l * HIDz * Cz;
        const float*  f1s = sb1 + (size_t)l * HIDz;
        const int8_t* g1w = w21 + (size_t)l * Cz * HIDz;
        const int8_t* g0w = w20 + (size_t)l * Cz * HIDz;
        const float*  g1s = sb2 + (size_t)l * Cz;
        const float* pb = proj_b + (size_t)l * Cz;
        const float* b1 = fc1_b  + (size_t)l * HIDz;
        const float* b2 = fc2_b  + (size_t)l * Cz;

        ln_q<<<NTOK, 256>>>(x, h1, h0, sah, ln1_g + l * Cz, ln1_b + l * Cz);
        gemm_q<<<dim3(3 * Cz / 128, NTOK / 128), 256, Q_GSMEM>>>(
            h1, h0, sah, q1w, q0w, qs, nullptr, qkvh, qkvl,
            NTOK, 3 * Cz, Cz, nullptr, nullptr, 0);
        attn_mma<<<dim3(Tz / 64, Bz * Hz), 128, AT_SMEM>>>(qkvh, qkvl, attf);
        quant8_rows<<<NTOK, 256>>>(attf, at1, at0, saat, Cz);
        gemm_q<<<dim3(Cz / 128, NTOK / 128), 256, Q_GSMEM>>>(
            at1, at0, saat, p1w, p0w, ps, x, nullptr, nullptr,
            NTOK, Cz, Cz, pb, x, 0);
        ln_q<<<NTOK, 256>>>(x, h1, h0, sah, ln2_g + l * Cz, ln2_b + l * Cz);
        gemm_q<<<dim3(HIDz / 128, NTOK / 128), 256, Q_GSMEM>>>(
            h1, h0, sah, f1w, f0w, f1s, ffnf, nullptr, nullptr,
            NTOK, HIDz, Cz, b1, nullptr, 1);
        quant8_rows<<<NTOK, 256>>>(ffnf, f1, f0, saf, HIDz);
        gemm_q<<<dim3(Cz / 128, NTOK / 128), 256, Q_GSMEM>>>(
            f1, f0, saf, g1w, g0w, g1s, x, nullptr, nullptr,
            NTOK, Cz, HIDz, b2, x, 0);
    }

    ln_q<<<NTOK, 256>>>(x, h1, h0, sah, lnf_g, lnf_b);
    gemm_q<<<dim3(Vz / 128, NTOK / 128), 256, Q_GSMEM>>>(
        h1, h0, sah, t1, t0, st, out, nullptr, nullptr,
        NTOK, Vz, Cz, nullptr, nullptr, 0);
}

// round 9
// speedup vs baseline: 2.9623x; 2.9623x over previous
#include <cuda_runtime.h>
#include <cuda_fp16.h>
#include <cstdint>
#include <math.h>

// Problem constants
#define Bz   2
#define Tz   1024
#define Cz   1024
#define Hz   16
#define Lz   8
#define Dz   64
#define HIDz 4096
#define Vz   32000
#define NTOK (Bz * Tz)          // 2048
#define EPSz 1e-5f

// ---------------------------------------------------------------------------
// PTX helpers (base ISA only)
// ---------------------------------------------------------------------------
__device__ __forceinline__ uint32_t smem_u32(const void* p) {
    uint32_t a;
    asm("{ .reg .u64 t; cvta.to.shared.u64 t, %1; cvt.u32.u64 %0, t; }"
        : "=r"(a) : "l"(p));
    return a;
}
__device__ __forceinline__ void ldsm_x4(uint32_t* r, uint32_t addr) {
    asm volatile("ldmatrix.sync.aligned.m8n8.x4.shared.b16 {%0,%1,%2,%3}, [%4];"
        : "=r"(r[0]), "=r"(r[1]), "=r"(r[2]), "=r"(r[3]) : "r"(addr));
}
__device__ __forceinline__ void ldsm_x4t(uint32_t* r, uint32_t addr) {
    asm volatile("ldmatrix.sync.aligned.m8n8.x4.trans.shared.b16 {%0,%1,%2,%3}, [%4];"
        : "=r"(r[0]), "=r"(r[1]), "=r"(r[2]), "=r"(r[3]) : "r"(addr));
}
__device__ __forceinline__ void mma_f16(float* d, const uint32_t* a, const uint32_t* b) {
    asm volatile("mma.sync.aligned.m16n8k16.row.col.f32.f16.f16.f32 "
        "{%0,%1,%2,%3}, {%4,%5,%6,%7}, {%8,%9}, {%0,%1,%2,%3};"
        : "+f"(d[0]), "+f"(d[1]), "+f"(d[2]), "+f"(d[3])
        : "r"(a[0]), "r"(a[1]), "r"(a[2]), "r"(a[3]), "r"(b[0]), "r"(b[1]));
}
__device__ __forceinline__ void cp16(uint32_t saddr, const void* gaddr) {
    asm volatile("cp.async.ca.shared.global [%0], [%1], 16;"
                 :: "r"(saddr), "l"(gaddr) : "memory");
}
#define CP_COMMIT() asm volatile("cp.async.commit_group;" ::: "memory")
#define CP_WAIT1()  asm volatile("cp.async.wait_group 1;" ::: "memory")
#define CP_WAIT0()  asm volatile("cp.async.wait_group 0;" ::: "memory")

__device__ __forceinline__ uint32_t packh(float x, float y) {
    __half2 t;
    t.x = __float2half(x);
    t.y = __float2half(y);
    return *(uint32_t*)&t;
}

// ---------------------------------------------------------------------------
// Scratch (device globals)
// ---------------------------------------------------------------------------
__device__ float g_x[NTOK * Cz];                 // residual stream
__device__ __half g_hh  [NTOK * Cz];
__device__ __half g_hl  [NTOK * Cz];
__device__ __half g_qkvh[NTOK * 3 * Cz];
__device__ __half g_qkvl[NTOK * 3 * Cz];
__device__ __half g_atth[NTOK * Cz];
__device__ __half g_attl[NTOK * Cz];
__device__ __half g_ffnh[NTOK * HIDz];
__device__ __half g_ffnl[NTOK * HIDz];

// Weights, transposed to [N,K]. qkv = fp16 pair (3-pass); rest = single fp16.
__device__ __half g_qkvT_h[Lz * 3 * Cz * Cz];
__device__ __half g_qkvT_l[Lz * 3 * Cz * Cz];
__device__ __half g_projT[Lz * Cz * Cz];
__device__ __half g_fc1T [Lz * HIDz * Cz];
__device__ __half g_fc2T [Lz * Cz * HIDz];
__device__ __half g_tokT [Vz * Cz];

// ---------------------------------------------------------------------------
// Weight prep
// ---------------------------------------------------------------------------
__global__ void wtrans_pair(const float* __restrict__ W,
                            __half* __restrict__ Th, __half* __restrict__ Tl,
                            int K, int N) {
    __shared__ float t[32][33];
    const float* Wl = W + (size_t)blockIdx.z * K * N;
    __half* Thl = Th + (size_t)blockIdx.z * K * N;
    __half* Tll = Tl + (size_t)blockIdx.z * K * N;
    int n0 = blockIdx.x * 32, k0 = blockIdx.y * 32;
    int tx = threadIdx.x, ty = threadIdx.y;
#pragma unroll
    for (int j = 0; j < 32; j += 8)
        t[ty + j][tx] = Wl[(size_t)(k0 + ty + j) * N + n0 + tx];
    __syncthreads();
#pragma unroll
    for (int j = 0; j < 32; j += 8) {
        float v = t[tx][ty + j];
        __half h = __float2half(v);
        size_t o = (size_t)(n0 + ty + j) * K + k0 + tx;
        Thl[o] = h;
        Tll[o] = __float2half(v - __half2float(h));
    }
}

__global__ void wtrans_one(const float* __restrict__ W,
                           __half* __restrict__ T, int K, int N) {
    __shared__ float t[32][33];
    const float* Wl = W + (size_t)blockIdx.z * K * N;
    __half* Tl2 = T + (size_t)blockIdx.z * K * N;
    int n0 = blockIdx.x * 32, k0 = blockIdx.y * 32;
    int tx = threadIdx.x, ty = threadIdx.y;
#pragma unroll
    for (int j = 0; j < 32; j += 8)
        t[ty + j][tx] = Wl[(size_t)(k0 + ty + j) * N + n0 + tx];
    __syncthreads();
#pragma unroll
    for (int j = 0; j < 32; j += 8)
        Tl2[(size_t)(n0 + ty + j) * K + k0 + tx] = __float2half(t[tx][ty + j]);
}

__global__ void wsplit_one(const float* __restrict__ W, __half* __restrict__ T, int n) {
    int i = blockIdx.x * blockDim.x + threadIdx.x;
    if (i < n) T[i] = __float2half(W[i]);
}

// ---------------------------------------------------------------------------
// gemm_h<NB>: fp16 mma GEMM. A = pair (Ah+Al), B = NB tiles (1 or 2).
// NB=1: 2-pass Ah*Bh + Al*Bh. NB=2: 3-pass + Ah*Bl.
// Block 128x128, 8 warps (64x32), BK=32, NSTG=3 cp.async pipeline (R5 config).
// ---------------------------------------------------------------------------
#define HPITCH 80

template <int NB>
__global__ __launch_bounds__(256)
void gemm_h(const __half* __restrict__ Ah, const __half* __restrict__ Al,
            const __half* __restrict__ Bh, const __half* __restrict__ Bl,
            float* __restrict__ Cf,
            __half* __restrict__ Ch, __half* __restrict__ Cl,
            int M, int N, int K,
            const float* __restrict__ bias, const float* __restrict__ res,
            int gelu) {
    constexpr int STG = (2 + NB) * 10240;
    constexpr int O_AH = 0, O_AL = 10240, O_BH = 20480, O_BL = 30720;
    extern __shared__ __align__(128) char smem[];
    uint32_t sb = smem_u32(smem);
    int tid = threadIdx.x, wid = tid >> 5, lane = tid & 31;
    int m0 = blockIdx.y * 128, n0 = blockIdx.x * 128;
    int wm = wid & 1, wn = wid >> 1;

    const __half* Agh = Ah + (size_t)m0 * K;
    const __half* Agl = Al + (size_t)m0 * K;
    const __half* Bgh = Bh + (size_t)n0 * K;
    const __half* Bgl = (NB == 2) ? (Bl + (size_t)n0 * K) : nullptr;

    float acc[4][4][4];
#pragma unroll
    for (int i = 0; i < 4; i++)
#pragma unroll
        for (int j = 0; j < 4; j++)
#pragma unroll
            for (int r = 0; r < 4; r++) acc[i][j][r] = 0.f;

    const int NC = K >> 5;

#define ISSUE_H(c)                                                             \
    {                                                                          \
        uint32_t s0 = sb + ((c) % 3) * STG;                                    \
        _Pragma("unroll")                                                      \
        for (int it = 0; it < 2; it++) {                                       \
            int i = it * 256 + tid;                                            \
            int row = i >> 2, seg = i & 3;                                     \
            uint32_t so = row * HPITCH + seg * 16;                             \
            size_t go = (size_t)row * K + (size_t)(c) * 32 + seg * 8;          \
            cp16(s0 + O_AH + so, Agh + go);                                    \
            cp16(s0 + O_AL + so, Agl + go);                                    \
            cp16(s0 + O_BH + so, Bgh + go);                                    \
            if (NB == 2) cp16(s0 + O_BL + so, Bgl + go);                       \
        }                                                                      \
        CP_COMMIT();                                                           \
    }

    ISSUE_H(0);
    ISSUE_H(1);

    int r16 = lane & 15, hsel = lane >> 4;
    int bg = lane >> 3;
    int browoff = ((bg & 2) << 2) + (lane & 7);
    int bkoff = (bg & 1) * 8;

    for (int c = 0; c < NC; c++) {
        if (c + 1 < NC) { CP_WAIT1(); } else { CP_WAIT0(); }
        __syncthreads();
        if (c + 2 < NC) ISSUE_H(c + 2);
        uint32_t base = sb + (c % 3) * STG;
#pragma unroll
        for (int kk = 0; kk < 32; kk += 16) {
            uint32_t ah[16], al[16], bh[8], bl[8];
#pragma unroll
            for (int mt = 0; mt < 4; mt++) {
                uint32_t ad = (uint32_t)((wm * 64 + mt * 16 + r16) * HPITCH +
                                         (kk + hsel * 8) * 2);
                ldsm_x4(ah + 4 * mt, base + O_AH + ad);
                ldsm_x4(al + 4 * mt, base + O_AL + ad);
            }
#pragma unroll
            for (int ntp = 0; ntp < 2; ntp++) {
                uint32_t bd = (uint32_t)((wn * 32 + ntp * 16 + browoff) * HPITCH +
                                         (kk + bkoff) * 2);
                ldsm_x4(bh + 4 * ntp, base + O_BH + bd);
                if (NB == 2) ldsm_x4(bl + 4 * ntp, base + O_BL + bd);
            }
#pragma unroll
            for (int mt = 0; mt < 4; mt++)
#pragma unroll
                for (int nt = 0; nt < 4; nt++) {
                    uint32_t* bp = bh + (nt >> 1) * 4 + (nt & 1) * 2;
                    mma_f16(acc[mt][nt], ah + 4 * mt, bp);
                    mma_f16(acc[mt][nt], al + 4 * mt, bp);
                    if (NB == 2) {
                        uint32_t* bp2 = bl + (nt >> 1) * 4 + (nt & 1) * 2;
                        mma_f16(acc[mt][nt], ah + 4 * mt, bp2);
                    }
                }
        }
        __syncthreads();
    }
#undef ISSUE_H

    int gid = lane >> 2, qid = lane & 3;
#pragma unroll
    for (int mt = 0; mt < 4; mt++) {
#pragma unroll
        for (int nt = 0; nt < 4; nt++) {
            int n = n0 + wn * 32 + nt * 8 + 2 * qid;
            float bsum0 = bias ? bias[n] : 0.f;
            float bsum1 = bias ? bias[n + 1] : 0.f;
#pragma unroll
            for (int half = 0; half < 2; half++) {
                int m = m0 + wm * 64 + mt * 16 + gid + half * 8;
                float v0 = acc[mt][nt][half * 2 + 0] + bsum0;
                float v1 = acc[mt][nt][half * 2 + 1] + bsum1;
                if (gelu) {
                    v0 = 0.5f * v0 * (1.f + erff(v0 * 0.70710678118654752f));
                    v1 = 0.5f * v1 * (1.f + erff(v1 * 0.70710678118654752f));
                }
                if (res) {
                    const float* rr = res + (size_t)m * N + n;
                    v0 += rr[0];
                    v1 += rr[1];
                }
                if (Cf) {
                    float2 o;
                    o.x = v0; o.y = v1;
                    *(float2*)(Cf + (size_t)m * N + n) = o;
                }
                if (Ch) {
                    __half2 oh, ol;
                    oh.x = __float2half(v0);
                    oh.y = __float2half(v1);
                    ol.x = __float2half(v0 - __half2float(oh.x));
                    ol.y = __float2half(v1 - __half2float(oh.y));
                    *(__half2*)(Ch + (size_t)m * N + n) = oh;
                    *(__half2*)(Cl + (size_t)m * N + n) = ol;
                }
            }
        }
    }
}

// ---------------------------------------------------------------------------
// MMA flash attention (R5-validated structure, fp16 types)
// ---------------------------------------------------------------------------
#define APITCH  144
#define AT_TILE 9216
#define AT_Q    0
#define AT_KV0  (2 * AT_TILE)
#define AT_KVS  (4 * AT_TILE)
#define AT_SMEM (AT_KV0 + 2 * AT_KVS)

__global__ __launch_bounds__(128)
void attn_mma(const __half* __restrict__ qkvh,
              const __half* __restrict__ qkvl,
              __half* __restrict__ oh,
              __half* __restrict__ ol) {
    extern __shared__ __align__(128) char smem[];
    uint32_t sb = smem_u32(smem);
    int tid = threadIdx.x, w = tid >> 5, lane = tid & 31;
    int qi = (int)gridDim.x - 1 - (int)blockIdx.x;
    int bh = blockIdx.y;
    int b = bh >> 4, h = bh & 15;
    const int RS = 3 * Cz;
    const size_t tokbase = (size_t)(b * Tz) * RS + h * Dz;

    int gid = lane >> 2, qid = lane & 3;
    int r16 = lane & 15, hsel = lane >> 4;
    int bg = lane >> 3;
    int browoff = ((bg & 2) << 2) + (lane & 7);
    int bkoff = (bg & 1) * 8;
    int t_row = (bg & 1) * 8 + (lane & 7);
    int t_col = (bg >> 1) * 8;

#define ISSUE_KV(kt)                                                           \
    {                                                                          \
        uint32_t s0 = sb + AT_KV0 + ((kt) & 1) * AT_KVS;                       \
        const __half* srcs[4] = {                                              \
            qkvh + tokbase + Cz, qkvl + tokbase + Cz,                          \
            qkvh + tokbase + 2 * Cz, qkvl + tokbase + 2 * Cz };                \
        _Pragma("unroll")                                                      \
        for (int t = 0; t < 4; t++) {                                          \
            _Pragma("unroll")                                                  \
            for (int it = 0; it < 4; it++) {                                   \
                int i = it * 128 + tid;                                        \
                int r = i >> 3, s = i & 7;                                     \
                cp16(s0 + t * AT_TILE + r * APITCH + s * 16,                   \
                     srcs[t] + (size_t)((kt) * 64 + r) * RS + s * 8);          \
            }                                                                  \
        }                                                                      \
        CP_COMMIT();                                                           \
    }

    {
#pragma unroll
        for (int t = 0; t < 2; t++) {
            const __half* src = (t ? qkvl : qkvh) + tokbase;
            uint32_t dst = sb + AT_Q + t * AT_TILE;
#pragma unroll
            for (int it = 0; it < 4; it++) {
                int i = it * 128 + tid;
                int r = i >> 3, s = i & 7;
                cp16(dst + r * APITCH + s * 16,
                     src + (size_t)(qi * 64 + r) * RS + s * 8);
            }
        }
        uint32_t s0 = sb + AT_KV0;
        const __half* srcs[4] = {
            qkvh + tokbase + Cz, qkvl + tokbase + Cz,
            qkvh + tokbase + 2 * Cz, qkvl + tokbase + 2 * Cz };
#pragma unroll
        for (int t = 0; t < 4; t++) {
#pragma unroll
            for (int it = 0; it < 4; it++) {
                int i = it * 128 + tid;
                int r = i >> 3, s = i & 7;
                cp16(s0 + t * AT_TILE + r * APITCH + s * 16,
                     srcs[t] + (size_t)r * RS + s * 8);
            }
        }
        CP_COMMIT();
    }
    if (qi >= 1) ISSUE_KV(1);

    if (qi >= 1) { CP_WAIT1(); } else { CP_WAIT0(); }
    __syncthreads();

    uint32_t qfh[4][4], qfl[4][4];
#pragma unroll
    for (int kk = 0; kk < 4; kk++) {
        uint32_t ad = sb + AT_Q + (uint32_t)((w * 16 + r16) * APITCH +
                                             (kk * 16 + hsel * 8) * 2);
        ldsm_x4(qfh[kk], ad);
        ldsm_x4(qfl[kk], ad + AT_TILE);
    }

    float oacc[8][4];
#pragma unroll
    for (int i = 0; i < 8; i++)
#pragma unroll
        for (int j = 0; j < 4; j++) oacc[i][j] = 0.f;
    float mrow[2] = {-1e30f, -1e30f};
    float lrow[2] = {0.f, 0.f};

    for (int kt = 0; kt <= qi; kt++) {
        if (kt > 0) {
            if (kt < qi) { CP_WAIT1(); } else { CP_WAIT0(); }
            __syncthreads();
        }
        uint32_t kb = sb + AT_KV0 + (kt & 1) * AT_KVS;

        float s[8][4];
#pragma unroll
        for (int i = 0; i < 8; i++)
#pragma unroll
            for (int j = 0; j < 4; j++) s[i][j] = 0.f;
#pragma unroll
        for (int kk = 0; kk < 4; kk++) {
            uint32_t kh[16], kl[16];
#pragma unroll
            for (int np = 0; np < 4; np++) {
                uint32_t ad = kb + (uint32_t)((np * 16 + browoff) * APITCH +
                                              (kk * 16 + bkoff) * 2);
                ldsm_x4(kh + 4 * np, ad);
                ldsm_x4(kl + 4 * np, ad + AT_TILE);
            }
#pragma unroll
            for (int nt = 0; nt < 8; nt++) {
                uint32_t* bp = kh + (nt >> 1) * 4 + (nt & 1) * 2;
                uint32_t* bl2 = kl + (nt >> 1) * 4 + (nt & 1) * 2;
                mma_f16(s[nt], qfh[kk], bp);
                mma_f16(s[nt], qfh[kk], bl2);
                mma_f16(s[nt], qfl[kk], bp);
            }
        }
#pragma unroll
        for (int nt = 0; nt < 8; nt++)
#pragma unroll
            for (int j = 0; j < 4; j++) s[nt][j] *= 0.125f;
        if (kt == qi) {
#pragma unroll
            for (int nt = 0; nt < 8; nt++)
#pragma unroll
                for (int j = 0; j < 4; j++) {
                    int kc = 8 * nt + 2 * qid + (j & 1);
                    int qr = w * 16 + gid + (j >> 1) * 8;
                    if (kc > qr) s[nt][j] = -1e30f;
                }
        }
        float mt0 = -1e30f, mt1 = -1e30f;
#pragma unroll
        for (int nt = 0; nt < 8; nt++) {
            mt0 = fmaxf(mt0, fmaxf(s[nt][0], s[nt][1]));
            mt1 = fmaxf(mt1, fmaxf(s[nt][2], s[nt][3]));
        }
        mt0 = fmaxf(mt0, __shfl_xor_sync(0xffffffffu, mt0, 1));
        mt0 = fmaxf(mt0, __shfl_xor_sync(0xffffffffu, mt0, 2));
        mt1 = fmaxf(mt1, __shfl_xor_sync(0xffffffffu, mt1, 1));
        mt1 = fmaxf(mt1, __shfl_xor_sync(0xffffffffu, mt1, 2));
        float mn0 = fmaxf(mrow[0], mt0), mn1 = fmaxf(mrow[1], mt1);
        float c0 = __expf(mrow[0] - mn0), c1 = __expf(mrow[1] - mn1);
        mrow[0] = mn0; mrow[1] = mn1;
        float rs0 = 0.f, rs1 = 0.f;
#pragma unroll
        for (int nt = 0; nt < 8; nt++) {
            s[nt][0] = __expf(s[nt][0] - mn0);
            s[nt][1] = __expf(s[nt][1] - mn0);
            s[nt][2] = __expf(s[nt][2] - mn1);
            s[nt][3] = __expf(s[nt][3] - mn1);
            rs0 += s[nt][0] + s[nt][1];
            rs1 += s[nt][2] + s[nt][3];
        }
        rs0 += __shfl_xor_sync(0xffffffffu, rs0, 1);
        rs0 += __shfl_xor_sync(0xffffffffu, rs0, 2);
        rs1 += __shfl_xor_sync(0xffffffffu, rs1, 1);
        rs1 += __shfl_xor_sync(0xffffffffu, rs1, 2);
        lrow[0] = lrow[0] * c0 + rs0;
        lrow[1] = lrow[1] * c1 + rs1;
#pragma unroll
        for (int nt = 0; nt < 8; nt++) {
            oacc[nt][0] *= c0; oacc[nt][1] *= c0;
            oacc[nt][2] *= c1; oacc[nt][3] *= c1;
        }
#pragma unroll
        for (int k2 = 0; k2 < 4; k2++) {
            uint32_t pah[4], pal[4];
            {
                float p00 = s[2 * k2][0],     p01 = s[2 * k2][1];
                float p10 = s[2 * k2][2],     p11 = s[2 * k2][3];
                float p20 = s[2 * k2 + 1][0], p21 = s[2 * k2 + 1][1];
                float p30 = s[2 * k2 + 1][2], p31 = s[2 * k2 + 1][3];
                pah[0] = packh(p00, p01);
                pah[1] = packh(p10, p11);
                pah[2] = packh(p20, p21);
                pah[3] = packh(p30, p31);
                __half2* hp;
                hp = (__half2*)&pah[0];
                pal[0] = packh(p00 - __half2float(hp->x), p01 - __half2float(hp->y));
                hp = (__half2*)&pah[1];
                pal[1] = packh(p10 - __half2float(hp->x), p11 - __half2float(hp->y));
                hp = (__half2*)&pah[2];
                pal[2] = packh(p20 - __half2float(hp->x), p21 - __half2float(hp->y));
                hp = (__half2*)&pah[3];
                pal[3] = packh(p30 - __half2float(hp->x), p31 - __half2float(hp->y));
            }
            uint32_t vh[16], vl[16];
#pragma unroll
            for (int np = 0; np < 4; np++) {
                uint32_t ad = kb + 2 * AT_TILE +
                              (uint32_t)((k2 * 16 + t_row) * APITCH +
                                         (np * 16 + t_col) * 2);
                ldsm_x4t(vh + 4 * np, ad);
                ldsm_x4t(vl + 4 * np, ad + AT_TILE);
            }
#pragma unroll
            for (int nt = 0; nt < 8; nt++) {
                uint32_t* bp = vh + (nt >> 1) * 4 + (nt & 1) * 2;
                uint32_t* bl2 = vl + (nt >> 1) * 4 + (nt & 1) * 2;
                mma_f16(oacc[nt], pah, bp);
                mma_f16(oacc[nt], pah, bl2);
                mma_f16(oacc[nt], pal, bp);
            }
        }
        __syncthreads();
        if (kt + 2 <= qi) ISSUE_KV(kt + 2);
    }
#undef ISSUE_KV

    float inv0 = 1.f / lrow[0], inv1 = 1.f / lrow[1];
    int tok0 = b * Tz + qi * 64 + w * 16 + gid;
#pragma unroll
    for (int nt = 0; nt < 8; nt++) {
        int col = h * Dz + 8 * nt + 2 * qid;
        float v0 = oacc[nt][0] * inv0, v1 = oacc[nt][1] * inv0;
        float v2 = oacc[nt][2] * inv1, v3 = oacc[nt][3] * inv1;
        __half2 ph, pl;
        ph.x = __float2half(v0); ph.y = __float2half(v1);
        pl.x = __float2half(v0 - __half2float(ph.x));
        pl.y = __float2half(v1 - __half2float(ph.y));
        *(__half2*)(oh + (size_t)tok0 * Cz + col) = ph;
        *(__half2*)(ol + (size_t)tok0 * Cz + col) = pl;
        ph.x = __float2half(v2); ph.y = __float2half(v3);
        pl.x = __float2half(v2 - __half2float(ph.x));
        pl.y = __float2half(v3 - __half2float(ph.y));
        *(__half2*)(oh + (size_t)(tok0 + 8) * Cz + col) = ph;
        *(__half2*)(ol + (size_t)(tok0 + 8) * Cz + col) = pl;
    }
}

// ---------------------------------------------------------------------------
// Embedding
// ---------------------------------------------------------------------------
__global__ void embed_kernel(const int* __restrict__ idx,
                             const float* __restrict__ tok,
                             const float* __restrict__ pos,
                             float* __restrict__ x) {
    int row = blockIdx.x;
    int t   = row & (Tz - 1);
    int tokid = idx[row];
    const float* te = tok + (size_t)tokid * Cz;
    const float* pe = pos + (size_t)t * Cz;
    float* xr = x + (size_t)row * Cz;
    for (int i = threadIdx.x; i < Cz; i += blockDim.x)
        xr[i] = te[i] + pe[i];
}

// ---------------------------------------------------------------------------
// LayerNorm per row, writes fp16 hi/lo pair
// ---------------------------------------------------------------------------
__global__ void ln_kernel(const float* __restrict__ x,
                          __half* __restrict__ yh, __half* __restrict__ yl,
                          const float* __restrict__ g, const float* __restrict__ b) {
    int row = blockIdx.x;
    const float* xr = x + (size_t)row * Cz;
    float s = 0.f, s2 = 0.f;
    for (int i = threadIdx.x; i < Cz; i += blockDim.x) {
        float v = xr[i];
        s += v; s2 += v * v;
    }
    __shared__ float sh_s[8], sh_s2[8];
    for (int off = 16; off > 0; off >>= 1) {
        s  += __shfl_down_sync(0xffffffffu, s,  off);
        s2 += __shfl_down_sync(0xffffffffu, s2, off);
    }
    int lane = threadIdx.x & 31, wid = threadIdx.x >> 5;
    if (lane == 0) { sh_s[wid] = s; sh_s2[wid] = s2; }
    __syncthreads();
    if (wid == 0) {
        s  = (lane < 8) ? sh_s[lane]  : 0.f;
        s2 = (lane < 8) ? sh_s2[lane] : 0.f;
        for (int off = 4; off > 0; off >>= 1) {
            s  += __shfl_down_sync(0xffffffffu, s,  off);
            s2 += __shfl_down_sync(0xffffffffu, s2, off);
        }
        if (lane == 0) { sh_s[0] = s; sh_s2[0] = s2; }
    }
    __syncthreads();
    float mean = sh_s[0] * (1.f / Cz);
    float var  = sh_s2[0] * (1.f / Cz) - mean * mean;
    float rstd = rsqrtf(var + EPSz);
    __half* yhr = yh + (size_t)row * Cz;
    __half* ylr = yl + (size_t)row * Cz;
    for (int i = threadIdx.x; i < Cz; i += blockDim.x) {
        float v = (xr[i] - mean) * rstd * g[i] + b[i];
        __half h = __float2half(v);
        yhr[i] = h;
        ylr[i] = __float2half(v - __half2float(h));
    }
}

// ---------------------------------------------------------------------------
// Launch
// ---------------------------------------------------------------------------
extern "C" void kernel_launch(void* const* d_in, const int* in_sizes, int n_in,
                              void* d_out, int out_size) {
    const int*   idx     = (const int*)  d_in[0];
    const float* tok_emb = (const float*)d_in[1];
    const float* pos_emb = (const float*)d_in[2];
    const float* qkv_w   = (const float*)d_in[3];
    const float* proj_w  = (const float*)d_in[4];
    const float* proj_b  = (const float*)d_in[5];
    const float* ln1_g   = (const float*)d_in[6];
    const float* ln1_b   = (const float*)d_in[7];
    const float* ln2_g   = (const float*)d_in[8];
    const float* ln2_b   = (const float*)d_in[9];
    const float* fc1_w   = (const float*)d_in[10];
    const float* fc1_b   = (const float*)d_in[11];
    const float* fc2_w   = (const float*)d_in[12];
    const float* fc2_b   = (const float*)d_in[13];
    const float* lnf_g   = (const float*)d_in[14];
    const float* lnf_b   = (const float*)d_in[15];
    float* out = (float*)d_out;

    float* x;
    cudaGetSymbolAddress((void**)&x, g_x);
    __half *hh, *hl, *qkvh, *qkvl, *atth, *attl, *ffnh, *ffnl;
    cudaGetSymbolAddress((void**)&hh,   g_hh);
    cudaGetSymbolAddress((void**)&hl,   g_hl);
    cudaGetSymbolAddress((void**)&qkvh, g_qkvh);
    cudaGetSymbolAddress((void**)&qkvl, g_qkvl);
    cudaGetSymbolAddress((void**)&atth, g_atth);
    cudaGetSymbolAddress((void**)&attl, g_attl);
    cudaGetSymbolAddress((void**)&ffnh, g_ffnh);
    cudaGetSymbolAddress((void**)&ffnl, g_ffnl);
    __half *qkvTh, *qkvTl, *projT, *fc1T, *fc2T, *tokT;
    cudaGetSymbolAddress((void**)&qkvTh, g_qkvT_h);
    cudaGetSymbolAddress((void**)&qkvTl, g_qkvT_l);
    cudaGetSymbolAddress((void**)&projT, g_projT);
    cudaGetSymbolAddress((void**)&fc1T,  g_fc1T);
    cudaGetSymbolAddress((void**)&fc2T,  g_fc2T);
    cudaGetSymbolAddress((void**)&tokT,  g_tokT);

    const int GS2 = 3 * 30720;   // 2-pass stage set
    const int GS3 = 3 * 40960;   // 3-pass stage set
    cudaFuncSetAttribute(gemm_h<1>, cudaFuncAttributeMaxDynamicSharedMemorySize, GS2);
    cudaFuncSetAttribute(gemm_h<2>, cudaFuncAttributeMaxDynamicSharedMemorySize, GS3);
    cudaFuncSetAttribute(attn_mma, cudaFuncAttributeMaxDynamicSharedMemorySize, AT_SMEM);

    // ---- weight prep ----
    dim3 tb(32, 8);
    wtrans_pair<<<dim3(3 * Cz / 32, Cz / 32, Lz), tb>>>(qkv_w, qkvTh, qkvTl, Cz, 3 * Cz);
    wtrans_one<<<dim3(Cz / 32, Cz / 32, Lz), tb>>>(proj_w, projT, Cz, Cz);
    wtrans_one<<<dim3(HIDz / 32, Cz / 32, Lz), tb>>>(fc1_w, fc1T, Cz, HIDz);
    wtrans_one<<<dim3(Cz / 32, HIDz / 32, Lz), tb>>>(fc2_w, fc2T, HIDz, Cz);
    wsplit_one<<<(Vz * Cz + 255) / 256, 256>>>(tok_emb, tokT, Vz * Cz);

    embed_kernel<<<NTOK, 256>>>(idx, tok_emb, pos_emb, x);

    for (int l = 0; l < Lz; l++) {
        const __half* qwh = qkvTh + (size_t)l * 3 * Cz * Cz;
        const __half* qwl = qkvTl + (size_t)l * 3 * Cz * Cz;
        const __half* pw  = projT + (size_t)l * Cz * Cz;
        const __half* w1  = fc1T  + (size_t)l * Cz * HIDz;
        const __half* w2  = fc2T  + (size_t)l * Cz * HIDz;
        const float* pb = proj_b + (size_t)l * Cz;
        const float* b1 = fc1_b  + (size_t)l * HIDz;
        const float* b2 = fc2_b  + (size_t)l * Cz;

        ln_kernel<<<NTOK, 256>>>(x, hh, hl, ln1_g + l * Cz, ln1_b + l * Cz);
        gemm_h<2><<<dim3(3 * Cz / 128, NTOK / 128), 256, GS3>>>(
            hh, hl, qwh, qwl, nullptr, qkvh, qkvl,
            NTOK, 3 * Cz, Cz, nullptr, nullptr, 0);
        attn_mma<<<dim3(Tz / 64, Bz * Hz), 128, AT_SMEM>>>(qkvh, qkvl, atth, attl);
        gemm_h<1><<<dim3(Cz / 128, NTOK / 128), 256, GS2>>>(
            atth, attl, pw, nullptr, x, nullptr, nullptr,
            NTOK, Cz, Cz, pb, x, 0);
        ln_kernel<<<NTOK, 256>>>(x, hh, hl, ln2_g + l * Cz, ln2_b + l * Cz);
        gemm_h<1><<<dim3(HIDz / 128, NTOK / 128), 256, GS2>>>(
            hh, hl, w1, nullptr, nullptr, ffnh, ffnl,
            NTOK, HIDz, Cz, b1, nullptr, 1);
        gemm_h<1><<<dim3(Cz / 128, NTOK / 128), 256, GS2>>>(
            ffnh, ffnl, w2, nullptr, x, nullptr, nullptr,
            NTOK, Cz, HIDz, b2, x, 0);
    }

    ln_kernel<<<NTOK, 256>>>(x, hh, hl, lnf_g, lnf_b);
    gemm_h<1><<<dim3(Vz / 128, NTOK / 128), 256, GS2>>>(
        hh, hl, tokT, nullptr, out, nullptr, nullptr,
        NTOK, Vz, Cz, nullptr, nullptr, 0);
}

// round 10
// speedup vs baseline: 3.5060x; 1.1835x over previous
#include <cuda_runtime.h>
#include <cuda_fp16.h>
#include <cstdint>
#include <math.h>

// Problem constants
#define Bz   2
#define Tz   1024
#define Cz   1024
#define Hz   16
#define Lz   8
#define Dz   64
#define HIDz 4096
#define Vz   32000
#define NTOK (Bz * Tz)          // 2048
#define EPSz 1e-5f

// ---------------------------------------------------------------------------
// PTX helpers (base ISA only)
// ---------------------------------------------------------------------------
__device__ __forceinline__ uint32_t smem_u32(const void* p) {
    uint32_t a;
    asm("{ .reg .u64 t; cvta.to.shared.u64 t, %1; cvt.u32.u64 %0, t; }"
        : "=r"(a) : "l"(p));
    return a;
}
__device__ __forceinline__ void ldsm_x4(uint32_t* r, uint32_t addr) {
    asm volatile("ldmatrix.sync.aligned.m8n8.x4.shared.b16 {%0,%1,%2,%3}, [%4];"
        : "=r"(r[0]), "=r"(r[1]), "=r"(r[2]), "=r"(r[3]) : "r"(addr));
}
__device__ __forceinline__ void ldsm_x4t(uint32_t* r, uint32_t addr) {
    asm volatile("ldmatrix.sync.aligned.m8n8.x4.trans.shared.b16 {%0,%1,%2,%3}, [%4];"
        : "=r"(r[0]), "=r"(r[1]), "=r"(r[2]), "=r"(r[3]) : "r"(addr));
}
__device__ __forceinline__ void mma_f16(float* d, const uint32_t* a, const uint32_t* b) {
    asm volatile("mma.sync.aligned.m16n8k16.row.col.f32.f16.f16.f32 "
        "{%0,%1,%2,%3}, {%4,%5,%6,%7}, {%8,%9}, {%0,%1,%2,%3};"
        : "+f"(d[0]), "+f"(d[1]), "+f"(d[2]), "+f"(d[3])
        : "r"(a[0]), "r"(a[1]), "r"(a[2]), "r"(a[3]), "r"(b[0]), "r"(b[1]));
}
__device__ __forceinline__ void cp16(uint32_t saddr, const void* gaddr) {
    asm volatile("cp.async.ca.shared.global [%0], [%1], 16;"
                 :: "r"(saddr), "l"(gaddr) : "memory");
}
#define CP_COMMIT() asm volatile("cp.async.commit_group;" ::: "memory")
#define CP_WAIT1()  asm volatile("cp.async.wait_group 1;" ::: "memory")
#define CP_WAIT0()  asm volatile("cp.async.wait_group 0;" ::: "memory")

__device__ __forceinline__ uint32_t packh(float x, float y) {
    __half2 t;
    t.x = __float2half(x);
    t.y = __float2half(y);
    return *(uint32_t*)&t;
}

// ---------------------------------------------------------------------------
// Scratch (device globals)
// ---------------------------------------------------------------------------
__device__ float g_x[NTOK * Cz];                 // residual stream
__device__ __half g_hh  [NTOK * Cz];
__device__ __half g_hl  [NTOK * Cz];
__device__ __half g_qkvh[NTOK * 3 * Cz];
__device__ __half g_qkvl[NTOK * 3 * Cz];
__device__ __half g_atth[NTOK * Cz];
__device__ __half g_attl[NTOK * Cz];
__device__ __half g_ffnh[NTOK * HIDz];
__device__ __half g_ffnl[NTOK * HIDz];

// Weights, transposed to [N,K]. qkv = fp16 pair (3-pass); rest = single fp16.
__device__ __half g_qkvT_h[Lz * 3 * Cz * Cz];
__device__ __half g_qkvT_l[Lz * 3 * Cz * Cz];
__device__ __half g_projT[Lz * Cz * Cz];
__device__ __half g_fc1T [Lz * HIDz * Cz];
__device__ __half g_fc2T [Lz * Cz * HIDz];
__device__ __half g_tokT [Vz * Cz];

// ---------------------------------------------------------------------------
// Weight prep
// ---------------------------------------------------------------------------
__global__ void wtrans_pair(const float* __restrict__ W,
                            __half* __restrict__ Th, __half* __restrict__ Tl,
                            int K, int N) {
    __shared__ float t[32][33];
    const float* Wl = W + (size_t)blockIdx.z * K * N;
    __half* Thl = Th + (size_t)blockIdx.z * K * N;
    __half* Tll = Tl + (size_t)blockIdx.z * K * N;
    int n0 = blockIdx.x * 32, k0 = blockIdx.y * 32;
    int tx = threadIdx.x, ty = threadIdx.y;
#pragma unroll
    for (int j = 0; j < 32; j += 8)
        t[ty + j][tx] = Wl[(size_t)(k0 + ty + j) * N + n0 + tx];
    __syncthreads();
#pragma unroll
    for (int j = 0; j < 32; j += 8) {
        float v = t[tx][ty + j];
        __half h = __float2half(v);
        size_t o = (size_t)(n0 + ty + j) * K + k0 + tx;
        Thl[o] = h;
        Tll[o] = __float2half(v - __half2float(h));
    }
}

__global__ void wtrans_one(const float* __restrict__ W,
                           __half* __restrict__ T, int K, int N) {
    __shared__ float t[32][33];
    const float* Wl = W + (size_t)blockIdx.z * K * N;
    __half* Tl2 = T + (size_t)blockIdx.z * K * N;
    int n0 = blockIdx.x * 32, k0 = blockIdx.y * 32;
    int tx = threadIdx.x, ty = threadIdx.y;
#pragma unroll
    for (int j = 0; j < 32; j += 8)
        t[ty + j][tx] = Wl[(size_t)(k0 + ty + j) * N + n0 + tx];
    __syncthreads();
#pragma unroll
    for (int j = 0; j < 32; j += 8)
        Tl2[(size_t)(n0 + ty + j) * K + k0 + tx] = __float2half(t[tx][ty + j]);
}

__global__ void wsplit_one(const float* __restrict__ W, __half* __restrict__ T, int n) {
    int i = blockIdx.x * blockDim.x + threadIdx.x;
    if (i < n) T[i] = __float2half(W[i]);
}

// ---------------------------------------------------------------------------
// gemm_h<NA,NB>: fp16 mma GEMM. A = NA tiles, B = NB tiles.
// (1,1): Ah*Bh. (2,1): + Al*Bh. (2,2): + Ah*Bl (3-pass).
// Block 128x128, 8 warps (64x32), BK=32, NSTG=3 cp.async pipeline.
// ---------------------------------------------------------------------------
#define HPITCH 80

template <int NA, int NB>
__global__ __launch_bounds__(256)
void gemm_h(const __half* __restrict__ Ah, const __half* __restrict__ Al,
            const __half* __restrict__ Bh, const __half* __restrict__ Bl,
            float* __restrict__ Cf,
            __half* __restrict__ Ch, __half* __restrict__ Cl,
            int M, int N, int K,
            const float* __restrict__ bias, const float* __restrict__ res,
            int gelu) {
    constexpr int STG = (NA + NB) * 10240;
    constexpr int O_AH = 0;
    constexpr int O_AL = 10240;                 // valid only if NA==2
    constexpr int O_BH = NA * 10240;
    constexpr int O_BL = O_BH + 10240;          // valid only if NB==2
    extern __shared__ __align__(128) char smem[];
    uint32_t sb = smem_u32(smem);
    int tid = threadIdx.x, wid = tid >> 5, lane = tid & 31;
    int m0 = blockIdx.y * 128, n0 = blockIdx.x * 128;
    int wm = wid & 1, wn = wid >> 1;

    const __half* Agh = Ah + (size_t)m0 * K;
    const __half* Agl = (NA == 2) ? (Al + (size_t)m0 * K) : nullptr;
    const __half* Bgh = Bh + (size_t)n0 * K;
    const __half* Bgl = (NB == 2) ? (Bl + (size_t)n0 * K) : nullptr;

    float acc[4][4][4];
#pragma unroll
    for (int i = 0; i < 4; i++)
#pragma unroll
        for (int j = 0; j < 4; j++)
#pragma unroll
            for (int r = 0; r < 4; r++) acc[i][j][r] = 0.f;

    const int NC = K >> 5;

#define ISSUE_H(c)                                                             \
    {                                                                          \
        uint32_t s0 = sb + ((c) % 3) * STG;                                    \
        _Pragma("unroll")                                                      \
        for (int it = 0; it < 2; it++) {                                       \
            int i = it * 256 + tid;                                            \
            int row = i >> 2, seg = i & 3;                                     \
            uint32_t so = row * HPITCH + seg * 16;                             \
            size_t go = (size_t)row * K + (size_t)(c) * 32 + seg * 8;          \
            cp16(s0 + O_AH + so, Agh + go);                                    \
            if (NA == 2) cp16(s0 + O_AL + so, Agl + go);                       \
            cp16(s0 + O_BH + so, Bgh + go);                                    \
            if (NB == 2) cp16(s0 + O_BL + so, Bgl + go);                       \
        }                                                                      \
        CP_COMMIT();                                                           \
    }

    ISSUE_H(0);
    ISSUE_H(1);

    int r16 = lane & 15, hsel = lane >> 4;
    int bg = lane >> 3;
    int browoff = ((bg & 2) << 2) + (lane & 7);
    int bkoff = (bg & 1) * 8;

    for (int c = 0; c < NC; c++) {
        if (c + 1 < NC) { CP_WAIT1(); } else { CP_WAIT0(); }
        __syncthreads();
        if (c + 2 < NC) ISSUE_H(c + 2);
        uint32_t base = sb + (c % 3) * STG;
#pragma unroll
        for (int kk = 0; kk < 32; kk += 16) {
            uint32_t ah[16], al[16], bh[8], bl[8];
#pragma unroll
            for (int mt = 0; mt < 4; mt++) {
                uint32_t ad = (uint32_t)((wm * 64 + mt * 16 + r16) * HPITCH +
                                         (kk + hsel * 8) * 2);
                ldsm_x4(ah + 4 * mt, base + O_AH + ad);
                if (NA == 2) ldsm_x4(al + 4 * mt, base + O_AL + ad);
            }
#pragma unroll
            for (int ntp = 0; ntp < 2; ntp++) {
                uint32_t bd = (uint32_t)((wn * 32 + ntp * 16 + browoff) * HPITCH +
                                         (kk + bkoff) * 2);
                ldsm_x4(bh + 4 * ntp, base + O_BH + bd);
                if (NB == 2) ldsm_x4(bl + 4 * ntp, base + O_BL + bd);
            }
#pragma unroll
            for (int mt = 0; mt < 4; mt++)
#pragma unroll
                for (int nt = 0; nt < 4; nt++) {
                    uint32_t* bp = bh + (nt >> 1) * 4 + (nt & 1) * 2;
                    mma_f16(acc[mt][nt], ah + 4 * mt, bp);
                    if (NA == 2) mma_f16(acc[mt][nt], al + 4 * mt, bp);
                    if (NB == 2) {
                        uint32_t* bp2 = bl + (nt >> 1) * 4 + (nt & 1) * 2;
                        mma_f16(acc[mt][nt], ah + 4 * mt, bp2);
                    }
                }
        }
        __syncthreads();
    }
#undef ISSUE_H

    int gid = lane >> 2, qid = lane & 3;
#pragma unroll
    for (int mt = 0; mt < 4; mt++) {
#pragma unroll
        for (int nt = 0; nt < 4; nt++) {
            int n = n0 + wn * 32 + nt * 8 + 2 * qid;
            float bsum0 = bias ? bias[n] : 0.f;
            float bsum1 = bias ? bias[n + 1] : 0.f;
#pragma unroll
            for (int half = 0; half < 2; half++) {
                int m = m0 + wm * 64 + mt * 16 + gid + half * 8;
                float v0 = acc[mt][nt][half * 2 + 0] + bsum0;
                float v1 = acc[mt][nt][half * 2 + 1] + bsum1;
                if (gelu) {
                    v0 = 0.5f * v0 * (1.f + erff(v0 * 0.70710678118654752f));
                    v1 = 0.5f * v1 * (1.f + erff(v1 * 0.70710678118654752f));
                }
                if (res) {
                    const float* rr = res + (size_t)m * N + n;
                    v0 += rr[0];
                    v1 += rr[1];
                }
                if (Cf) {
                    float2 o;
                    o.x = v0; o.y = v1;
                    *(float2*)(Cf + (size_t)m * N + n) = o;
                }
                if (Ch) {
                    __half2 oh, ol;
                    oh.x = __float2half(v0);
                    oh.y = __float2half(v1);
                    ol.x = __float2half(v0 - __half2float(oh.x));
                    ol.y = __float2half(v1 - __half2float(oh.y));
                    *(__half2*)(Ch + (size_t)m * N + n) = oh;
                    *(__half2*)(Cl + (size_t)m * N + n) = ol;
                }
            }
        }
    }
}

// ---------------------------------------------------------------------------
// MMA flash attention (R5-validated structure, fp16 types)
// ---------------------------------------------------------------------------
#define APITCH  144
#define AT_TILE 9216
#define AT_Q    0
#define AT_KV0  (2 * AT_TILE)
#define AT_KVS  (4 * AT_TILE)
#define AT_SMEM (AT_KV0 + 2 * AT_KVS)

__global__ __launch_bounds__(128)
void attn_mma(const __half* __restrict__ qkvh,
              const __half* __restrict__ qkvl,
              __half* __restrict__ oh,
              __half* __restrict__ ol) {
    extern __shared__ __align__(128) char smem[];
    uint32_t sb = smem_u32(smem);
    int tid = threadIdx.x, w = tid >> 5, lane = tid & 31;
    int qi = (int)gridDim.x - 1 - (int)blockIdx.x;
    int bh = blockIdx.y;
    int b = bh >> 4, h = bh & 15;
    const int RS = 3 * Cz;
    const size_t tokbase = (size_t)(b * Tz) * RS + h * Dz;

    int gid = lane >> 2, qid = lane & 3;
    int r16 = lane & 15, hsel = lane >> 4;
    int bg = lane >> 3;
    int browoff = ((bg & 2) << 2) + (lane & 7);
    int bkoff = (bg & 1) * 8;
    int t_row = (bg & 1) * 8 + (lane & 7);
    int t_col = (bg >> 1) * 8;

#define ISSUE_KV(kt)                                                           \
    {                                                                          \
        uint32_t s0 = sb + AT_KV0 + ((kt) & 1) * AT_KVS;                       \
        const __half* srcs[4] = {                                              \
            qkvh + tokbase + Cz, qkvl + tokbase + Cz,                          \
            qkvh + tokbase + 2 * Cz, qkvl + tokbase + 2 * Cz };                \
        _Pragma("unroll")                                                      \
        for (int t = 0; t < 4; t++) {                                          \
            _Pragma("unroll")                                                  \
            for (int it = 0; it < 4; it++) {                                   \
                int i = it * 128 + tid;                                        \
                int r = i >> 3, s = i & 7;                                     \
                cp16(s0 + t * AT_TILE + r * APITCH + s * 16,                   \
                     srcs[t] + (size_t)((kt) * 64 + r) * RS + s * 8);          \
            }                                                                  \
        }                                                                      \
        CP_COMMIT();                                                           \
    }

    {
#pragma unroll
        for (int t = 0; t < 2; t++) {
            const __half* src = (t ? qkvl : qkvh) + tokbase;
            uint32_t dst = sb + AT_Q + t * AT_TILE;
#pragma unroll
            for (int it = 0; it < 4; it++) {
                int i = it * 128 + tid;
                int r = i >> 3, s = i & 7;
                cp16(dst + r * APITCH + s * 16,
                     src + (size_t)(qi * 64 + r) * RS + s * 8);
            }
        }
        uint32_t s0 = sb + AT_KV0;
        const __half* srcs[4] = {
            qkvh + tokbase + Cz, qkvl + tokbase + Cz,
            qkvh + tokbase + 2 * Cz, qkvl + tokbase + 2 * Cz };
#pragma unroll
        for (int t = 0; t < 4; t++) {
#pragma unroll
            for (int it = 0; it < 4; it++) {
                int i = it * 128 + tid;
                int r = i >> 3, s = i & 7;
                cp16(s0 + t * AT_TILE + r * APITCH + s * 16,
                     srcs[t] + (size_t)r * RS + s * 8);
            }
        }
        CP_COMMIT();
    }
    if (qi >= 1) ISSUE_KV(1);

    if (qi >= 1) { CP_WAIT1(); } else { CP_WAIT0(); }
    __syncthreads();

    uint32_t qfh[4][4], qfl[4][4];
#pragma unroll
    for (int kk = 0; kk < 4; kk++) {
        uint32_t ad = sb + AT_Q + (uint32_t)((w * 16 + r16) * APITCH +
                                             (kk * 16 + hsel * 8) * 2);
        ldsm_x4(qfh[kk], ad);
        ldsm_x4(qfl[kk], ad + AT_TILE);
    }

    float oacc[8][4];
#pragma unroll
    for (int i = 0; i < 8; i++)
#pragma unroll
        for (int j = 0; j < 4; j++) oacc[i][j] = 0.f;
    float mrow[2] = {-1e30f, -1e30f};
    float lrow[2] = {0.f, 0.f};

    for (int kt = 0; kt <= qi; kt++) {
        if (kt > 0) {
            if (kt < qi) { CP_WAIT1(); } else { CP_WAIT0(); }
            __syncthreads();
        }
        uint32_t kb = sb + AT_KV0 + (kt & 1) * AT_KVS;

        float s[8][4];
#pragma unroll
        for (int i = 0; i < 8; i++)
#pragma unroll
            for (int j = 0; j < 4; j++) s[i][j] = 0.f;
#pragma unroll
        for (int kk = 0; kk < 4; kk++) {
            uint32_t kh[16], kl[16];
#pragma unroll
            for (int np = 0; np < 4; np++) {
                uint32_t ad = kb + (uint32_t)((np * 16 + browoff) * APITCH +
                                              (kk * 16 + bkoff) * 2);
                ldsm_x4(kh + 4 * np, ad);
                ldsm_x4(kl + 4 * np, ad + AT_TILE);
            }
#pragma unroll
            for (int nt = 0; nt < 8; nt++) {
                uint32_t* bp = kh + (nt >> 1) * 4 + (nt & 1) * 2;
                uint32_t* bl2 = kl + (nt >> 1) * 4 + (nt & 1) * 2;
                mma_f16(s[nt], qfh[kk], bp);
                mma_f16(s[nt], qfh[kk], bl2);
                mma_f16(s[nt], qfl[kk], bp);
            }
        }
#pragma unroll
        for (int nt = 0; nt < 8; nt++)
#pragma unroll
            for (int j = 0; j < 4; j++) s[nt][j] *= 0.125f;
        if (kt == qi) {
#pragma unroll
            for (int nt = 0; nt < 8; nt++)
#pragma unroll
                for (int j = 0; j < 4; j++) {
                    int kc = 8 * nt + 2 * qid + (j & 1);
                    int qr = w * 16 + gid + (j >> 1) * 8;
                    if (kc > qr) s[nt][j] = -1e30f;
                }
        }
        float mt0 = -1e30f, mt1 = -1e30f;
#pragma unroll
        for (int nt = 0; nt < 8; nt++) {
            mt0 = fmaxf(mt0, fmaxf(s[nt][0], s[nt][1]));
            mt1 = fmaxf(mt1, fmaxf(s[nt][2], s[nt][3]));
        }
        mt0 = fmaxf(mt0, __shfl_xor_sync(0xffffffffu, mt0, 1));
        mt0 = fmaxf(mt0, __shfl_xor_sync(0xffffffffu, mt0, 2));
        mt1 = fmaxf(mt1, __shfl_xor_sync(0xffffffffu, mt1, 1));
        mt1 = fmaxf(mt1, __shfl_xor_sync(0xffffffffu, mt1, 2));
        float mn0 = fmaxf(mrow[0], mt0), mn1 = fmaxf(mrow[1], mt1);
        float c0 = __expf(mrow[0] - mn0), c1 = __expf(mrow[1] - mn1);
        mrow[0] = mn0; mrow[1] = mn1;
        float rs0 = 0.f, rs1 = 0.f;
#pragma unroll
        for (int nt = 0; nt < 8; nt++) {
            s[nt][0] = __expf(s[nt][0] - mn0);
            s[nt][1] = __expf(s[nt][1] - mn0);
            s[nt][2] = __expf(s[nt][2] - mn1);
            s[nt][3] = __expf(s[nt][3] - mn1);
            rs0 += s[nt][0] + s[nt][1];
            rs1 += s[nt][2] + s[nt][3];
        }
        rs0 += __shfl_xor_sync(0xffffffffu, rs0, 1);
        rs0 += __shfl_xor_sync(0xffffffffu, rs0, 2);
        rs1 += __shfl_xor_sync(0xffffffffu, rs1, 1);
        rs1 += __shfl_xor_sync(0xffffffffu, rs1, 2);
        lrow[0] = lrow[0] * c0 + rs0;
        lrow[1] = lrow[1] * c1 + rs1;
#pragma unroll
        for (int nt = 0; nt < 8; nt++) {
            oacc[nt][0] *= c0; oacc[nt][1] *= c0;
            oacc[nt][2] *= c1; oacc[nt][3] *= c1;
        }
#pragma unroll
        for (int k2 = 0; k2 < 4; k2++) {
            uint32_t pah[4], pal[4];
            {
                float p00 = s[2 * k2][0],     p01 = s[2 * k2][1];
                float p10 = s[2 * k2][2],     p11 = s[2 * k2][3];
                float p20 = s[2 * k2 + 1][0], p21 = s[2 * k2 + 1][1];
                float p30 = s[2 * k2 + 1][2], p31 = s[2 * k2 + 1][3];
                pah[0] = packh(p00, p01);
                pah[1] = packh(p10, p11);
                pah[2] = packh(p20, p21);
                pah[3] = packh(p30, p31);
                __half2* hp;
                hp = (__half2*)&pah[0];
                pal[0] = packh(p00 - __half2float(hp->x), p01 - __half2float(hp->y));
                hp = (__half2*)&pah[1];
                pal[1] = packh(p10 - __half2float(hp->x), p11 - __half2float(hp->y));
                hp = (__half2*)&pah[2];
                pal[2] = packh(p20 - __half2float(hp->x), p21 - __half2float(hp->y));
                hp = (__half2*)&pah[3];
                pal[3] = packh(p30 - __half2float(hp->x), p31 - __half2float(hp->y));
            }
            uint32_t vh[16], vl[16];
#pragma unroll
            for (int np = 0; np < 4; np++) {
                uint32_t ad = kb + 2 * AT_TILE +
                              (uint32_t)((k2 * 16 + t_row) * APITCH +
                                         (np * 16 + t_col) * 2);
                ldsm_x4t(vh + 4 * np, ad);
                ldsm_x4t(vl + 4 * np, ad + AT_TILE);
            }
#pragma unroll
            for (int nt = 0; nt < 8; nt++) {
                uint32_t* bp = vh + (nt >> 1) * 4 + (nt & 1) * 2;
                uint32_t* bl2 = vl + (nt >> 1) * 4 + (nt & 1) * 2;
                mma_f16(oacc[nt], pah, bp);
                mma_f16(oacc[nt], pah, bl2);
                mma_f16(oacc[nt], pal, bp);
            }
        }
        __syncthreads();
        if (kt + 2 <= qi) ISSUE_KV(kt + 2);
    }
#undef ISSUE_KV

    float inv0 = 1.f / lrow[0], inv1 = 1.f / lrow[1];
    int tok0 = b * Tz + qi * 64 + w * 16 + gid;
#pragma unroll
    for (int nt = 0; nt < 8; nt++) {
        int col = h * Dz + 8 * nt + 2 * qid;
        float v0 = oacc[nt][0] * inv0, v1 = oacc[nt][1] * inv0;
        float v2 = oacc[nt][2] * inv1, v3 = oacc[nt][3] * inv1;
        __half2 ph, pl;
        ph.x = __float2half(v0); ph.y = __float2half(v1);
        pl.x = __float2half(v0 - __half2float(ph.x));
        pl.y = __float2half(v1 - __half2float(ph.y));
        *(__half2*)(oh + (size_t)tok0 * Cz + col) = ph;
        *(__half2*)(ol + (size_t)tok0 * Cz + col) = pl;
        ph.x = __float2half(v2); ph.y = __float2half(v3);
        pl.x = __float2half(v2 - __half2float(ph.x));
        pl.y = __float2half(v3 - __half2float(ph.y));
        *(__half2*)(oh + (size_t)(tok0 + 8) * Cz + col) = ph;
        *(__half2*)(ol + (size_t)(tok0 + 8) * Cz + col) = pl;
    }
}

// ---------------------------------------------------------------------------
// Embedding
// ---------------------------------------------------------------------------
__global__ void embed_kernel(const int* __restrict__ idx,
                             const float* __restrict__ tok,
                             const float* __restrict__ pos,
                             float* __restrict__ x) {
    int row = blockIdx.x;
    int t   = row & (Tz - 1);
    int tokid = idx[row];
    const float* te = tok + (size_t)tokid * Cz;
    const float* pe = pos + (size_t)t * Cz;
    float* xr = x + (size_t)row * Cz;
    for (int i = threadIdx.x; i < Cz; i += blockDim.x)
        xr[i] = te[i] + pe[i];
}

// ---------------------------------------------------------------------------
// LayerNorm per row, writes fp16 hi/lo pair
// ---------------------------------------------------------------------------
__global__ void ln_kernel(const float* __restrict__ x,
                          __half* __restrict__ yh, __half* __restrict__ yl,
                          const float* __restrict__ g, const float* __restrict__ b) {
    int row = blockIdx.x;
    const float* xr = x + (size_t)row * Cz;
    float s = 0.f, s2 = 0.f;
    for (int i = threadIdx.x; i < Cz; i += blockDim.x) {
        float v = xr[i];
        s += v; s2 += v * v;
    }
    __shared__ float sh_s[8], sh_s2[8];
    for (int off = 16; off > 0; off >>= 1) {
        s  += __shfl_down_sync(0xffffffffu, s,  off);
        s2 += __shfl_down_sync(0xffffffffu, s2, off);
    }
    int lane = threadIdx.x & 31, wid = threadIdx.x >> 5;
    if (lane == 0) { sh_s[wid] = s; sh_s2[wid] = s2; }
    __syncthreads();
    if (wid == 0) {
        s  = (lane < 8) ? sh_s[lane]  : 0.f;
        s2 = (lane < 8) ? sh_s2[lane] : 0.f;
        for (int off = 4; off > 0; off >>= 1) {
            s  += __shfl_down_sync(0xffffffffu, s,  off);
            s2 += __shfl_down_sync(0xffffffffu, s2, off);
        }
        if (lane == 0) { sh_s[0] = s; sh_s2[0] = s2; }
    }
    __syncthreads();
    float mean = sh_s[0] * (1.f / Cz);
    float var  = sh_s2[0] * (1.f / Cz) - mean * mean;
    float rstd = rsqrtf(var + EPSz);
    __half* yhr = yh + (size_t)row * Cz;
    __half* ylr = yl + (size_t)row * Cz;
    for (int i = threadIdx.x; i < Cz; i += blockDim.x) {
        float v = (xr[i] - mean) * rstd * g[i] + b[i];
        __half h = __float2half(v);
        yhr[i] = h;
        ylr[i] = __float2half(v - __half2float(h));
    }
}

// ---------------------------------------------------------------------------
// Launch
// ---------------------------------------------------------------------------
extern "C" void kernel_launch(void* const* d_in, const int* in_sizes, int n_in,
                              void* d_out, int out_size) {
    const int*   idx     = (const int*)  d_in[0];
    const float* tok_emb = (const float*)d_in[1];
    const float* pos_emb = (const float*)d_in[2];
    const float* qkv_w   = (const float*)d_in[3];
    const float* proj_w  = (const float*)d_in[4];
    const float* proj_b  = (const float*)d_in[5];
    const float* ln1_g   = (const float*)d_in[6];
    const float* ln1_b   = (const float*)d_in[7];
    const float* ln2_g   = (const float*)d_in[8];
    const float* ln2_b   = (const float*)d_in[9];
    const float* fc1_w   = (const float*)d_in[10];
    const float* fc1_b   = (const float*)d_in[11];
    const float* fc2_w   = (const float*)d_in[12];
    const float* fc2_b   = (const float*)d_in[13];
    const float* lnf_g   = (const float*)d_in[14];
    const float* lnf_b   = (const float*)d_in[15];
    float* out = (float*)d_out;

    float* x;
    cudaGetSymbolAddress((void**)&x, g_x);
    __half *hh, *hl, *qkvh, *qkvl, *atth, *attl, *ffnh, *ffnl;
    cudaGetSymbolAddress((void**)&hh,   g_hh);
    cudaGetSymbolAddress((void**)&hl,   g_hl);
    cudaGetSymbolAddress((void**)&qkvh, g_qkvh);
    cudaGetSymbolAddress((void**)&qkvl, g_qkvl);
    cudaGetSymbolAddress((void**)&atth, g_atth);
    cudaGetSymbolAddress((void**)&attl, g_attl);
    cudaGetSymbolAddress((void**)&ffnh, g_ffnh);
    cudaGetSymbolAddress((void**)&ffnl, g_ffnl);
    __half *qkvTh, *qkvTl, *projT, *fc1T, *fc2T, *tokT;
    cudaGetSymbolAddress((void**)&qkvTh, g_qkvT_h);
    cudaGetSymbolAddress((void**)&qkvTl, g_qkvT_l);
    cudaGetSymbolAddress((void**)&projT, g_projT);
    cudaGetSymbolAddress((void**)&fc1T,  g_fc1T);
    cudaGetSymbolAddress((void**)&fc2T,  g_fc2T);
    cudaGetSymbolAddress((void**)&tokT,  g_tokT);

    const int GS11 = 3 * 20480;
    const int GS21 = 3 * 30720;
    const int GS22 = 3 * 40960;
    cudaFuncSetAttribute(gemm_h<1, 1>, cudaFuncAttributeMaxDynamicSharedMemorySize, GS11);
    cudaFuncSetAttribute(gemm_h<2, 1>, cudaFuncAttributeMaxDynamicSharedMemorySize, GS21);
    cudaFuncSetAttribute(gemm_h<2, 2>, cudaFuncAttributeMaxDynamicSharedMemorySize, GS22);
    cudaFuncSetAttribute(attn_mma, cudaFuncAttributeMaxDynamicSharedMemorySize, AT_SMEM);

    // ---- weight prep ----
    dim3 tb(32, 8);
    wtrans_pair<<<dim3(3 * Cz / 32, Cz / 32, Lz), tb>>>(qkv_w, qkvTh, qkvTl, Cz, 3 * Cz);
    wtrans_one<<<dim3(Cz / 32, Cz / 32, Lz), tb>>>(proj_w, projT, Cz, Cz);
    wtrans_one<<<dim3(HIDz / 32, Cz / 32, Lz), tb>>>(fc1_w, fc1T, Cz, HIDz);
    wtrans_one<<<dim3(Cz / 32, HIDz / 32, Lz), tb>>>(fc2_w, fc2T, HIDz, Cz);
    wsplit_one<<<(Vz * Cz + 255) / 256, 256>>>(tok_emb, tokT, Vz * Cz);

    embed_kernel<<<NTOK, 256>>>(idx, tok_emb, pos_emb, x);

    for (int l = 0; l < Lz; l++) {
        const __half* qwh = qkvTh + (size_t)l * 3 * Cz * Cz;
        const __half* qwl = qkvTl + (size_t)l * 3 * Cz * Cz;
        const __half* pw  = projT + (size_t)l * Cz * Cz;
        const __half* w1  = fc1T  + (size_t)l * Cz * HIDz;
        const __half* w2  = fc2T  + (size_t)l * Cz * HIDz;
        const float* pb = proj_b + (size_t)l * Cz;
        const float* b1 = fc1_b  + (size_t)l * HIDz;
        const float* b2 = fc2_b  + (size_t)l * Cz;

        ln_kernel<<<NTOK, 256>>>(x, hh, hl, ln1_g + l * Cz, ln1_b + l * Cz);
        gemm_h<2, 2><<<dim3(3 * Cz / 128, NTOK / 128), 256, GS22>>>(
            hh, hl, qwh, qwl, nullptr, qkvh, qkvl,
            NTOK, 3 * Cz, Cz, nullptr, nullptr, 0);
        attn_mma<<<dim3(Tz / 64, Bz * Hz), 128, AT_SMEM>>>(qkvh, qkvl, atth, attl);
        gemm_h<2, 1><<<dim3(Cz / 128, NTOK / 128), 256, GS21>>>(
            atth, attl, pw, nullptr, x, nullptr, nullptr,
            NTOK, Cz, Cz, pb, x, 0);
        ln_kernel<<<NTOK, 256>>>(x, hh, hl, ln2_g + l * Cz, ln2_b + l * Cz);
        gemm_h<2, 1><<<dim3(HIDz / 128, NTOK / 128), 256, GS21>>>(
            hh, hl, w1, nullptr, nullptr, ffnh, ffnl,
            NTOK, HIDz, Cz, b1, nullptr, 1);
        gemm_h<1, 1><<<dim3(Cz / 128, NTOK / 128), 256, GS11>>>(
            ffnh, nullptr, w2, nullptr, x, nullptr, nullptr,
            NTOK, Cz, HIDz, b2, x, 0);
    }

    ln_kernel<<<NTOK, 256>>>(x, hh, hl, lnf_g, lnf_b);
    gemm_h<1, 1><<<dim3(Vz / 128, NTOK / 128), 256, GS11>>>(
        hh, nullptr, tokT, nullptr, out, nullptr, nullptr,
        NTOK, Vz, Cz, nullptr, nullptr, 0);
}

// round 11
// speedup vs baseline: 3.8898x; 1.1094x over previous
#include <cuda_runtime.h>
#include <cuda_fp16.h>
#include <cstdint>
#include <math.h>

// Problem constants
#define Bz   2
#define Tz   1024
#define Cz   1024
#define Hz   16
#define Lz   8
#define Dz   64
#define HIDz 4096
#define Vz   32000
#define NTOK (Bz * Tz)          // 2048
#define EPSz 1e-5f

// ---------------------------------------------------------------------------
// PTX helpers (base ISA only)
// ---------------------------------------------------------------------------
__device__ __forceinline__ uint32_t smem_u32(const void* p) {
    uint32_t a;
    asm("{ .reg .u64 t; cvta.to.shared.u64 t, %1; cvt.u32.u64 %0, t; }"
        : "=r"(a) : "l"(p));
    return a;
}
__device__ __forceinline__ void ldsm_x4(uint32_t* r, uint32_t addr) {
    asm volatile("ldmatrix.sync.aligned.m8n8.x4.shared.b16 {%0,%1,%2,%3}, [%4];"
        : "=r"(r[0]), "=r"(r[1]), "=r"(r[2]), "=r"(r[3]) : "r"(addr));
}
__device__ __forceinline__ void ldsm_x4t(uint32_t* r, uint32_t addr) {
    asm volatile("ldmatrix.sync.aligned.m8n8.x4.trans.shared.b16 {%0,%1,%2,%3}, [%4];"
        : "=r"(r[0]), "=r"(r[1]), "=r"(r[2]), "=r"(r[3]) : "r"(addr));
}
__device__ __forceinline__ void mma_f16(float* d, const uint32_t* a, const uint32_t* b) {
    asm volatile("mma.sync.aligned.m16n8k16.row.col.f32.f16.f16.f32 "
        "{%0,%1,%2,%3}, {%4,%5,%6,%7}, {%8,%9}, {%0,%1,%2,%3};"
        : "+f"(d[0]), "+f"(d[1]), "+f"(d[2]), "+f"(d[3])
        : "r"(a[0]), "r"(a[1]), "r"(a[2]), "r"(a[3]), "r"(b[0]), "r"(b[1]));
}
__device__ __forceinline__ void cp16(uint32_t saddr, const void* gaddr) {
    asm volatile("cp.async.ca.shared.global [%0], [%1], 16;"
                 :: "r"(saddr), "l"(gaddr) : "memory");
}
#define CP_COMMIT() asm volatile("cp.async.commit_group;" ::: "memory")
#define CP_WAIT1()  asm volatile("cp.async.wait_group 1;" ::: "memory")
#define CP_WAIT0()  asm volatile("cp.async.wait_group 0;" ::: "memory")

__device__ __forceinline__ uint32_t packh(float x, float y) {
    __half2 t;
    t.x = __float2half(x);
    t.y = __float2half(y);
    return *(uint32_t*)&t;
}

// ---------------------------------------------------------------------------
// Scratch (device globals)
// ---------------------------------------------------------------------------
__device__ float g_x[NTOK * Cz];                 // residual stream
__device__ __half g_hh  [NTOK * Cz];
__device__ __half g_hl  [NTOK * Cz];
__device__ __half g_qkvh[NTOK * 3 * Cz];
__device__ __half g_qkvl[NTOK * 3 * Cz];
__device__ __half g_atth[NTOK * Cz];
__device__ __half g_attl[NTOK * Cz];
__device__ __half g_ffnh[NTOK * HIDz];

// Weights, transposed to [N,K]. qkv = fp16 pair (3-pass); rest = single fp16.
__device__ __half g_qkvT_h[Lz * 3 * Cz * Cz];
__device__ __half g_qkvT_l[Lz * 3 * Cz * Cz];
__device__ __half g_projT[Lz * Cz * Cz];
__device__ __half g_fc1T [Lz * HIDz * Cz];
__device__ __half g_fc2T [Lz * Cz * HIDz];
__device__ __half g_tokT [Vz * Cz];

// ---------------------------------------------------------------------------
// Weight prep
// ---------------------------------------------------------------------------
__global__ void wtrans_pair(const float* __restrict__ W,
                            __half* __restrict__ Th, __half* __restrict__ Tl,
                            int K, int N) {
    __shared__ float t[32][33];
    const float* Wl = W + (size_t)blockIdx.z * K * N;
    __half* Thl = Th + (size_t)blockIdx.z * K * N;
    __half* Tll = Tl + (size_t)blockIdx.z * K * N;
    int n0 = blockIdx.x * 32, k0 = blockIdx.y * 32;
    int tx = threadIdx.x, ty = threadIdx.y;
#pragma unroll
    for (int j = 0; j < 32; j += 8)
        t[ty + j][tx] = Wl[(size_t)(k0 + ty + j) * N + n0 + tx];
    __syncthreads();
#pragma unroll
    for (int j = 0; j < 32; j += 8) {
        float v = t[tx][ty + j];
        __half h = __float2half(v);
        size_t o = (size_t)(n0 + ty + j) * K + k0 + tx;
        Thl[o] = h;
        Tll[o] = __float2half(v - __half2float(h));
    }
}

__global__ void wtrans_one(const float* __restrict__ W,
                           __half* __restrict__ T, int K, int N) {
    __shared__ float t[32][33];
    const float* Wl = W + (size_t)blockIdx.z * K * N;
    __half* Tl2 = T + (size_t)blockIdx.z * K * N;
    int n0 = blockIdx.x * 32, k0 = blockIdx.y * 32;
    int tx = threadIdx.x, ty = threadIdx.y;
#pragma unroll
    for (int j = 0; j < 32; j += 8)
        t[ty + j][tx] = Wl[(size_t)(k0 + ty + j) * N + n0 + tx];
    __syncthreads();
#pragma unroll
    for (int j = 0; j < 32; j += 8)
        Tl2[(size_t)(n0 + ty + j) * K + k0 + tx] = __float2half(t[tx][ty + j]);
}

__global__ void wsplit_one(const float* __restrict__ W, __half* __restrict__ T, int n) {
    int i = blockIdx.x * blockDim.x + threadIdx.x;
    if (i < n) T[i] = __float2half(W[i]);
}

// ---------------------------------------------------------------------------
// gemm_h<NA,NB>: fp16 mma GEMM. A = NA tiles, B = NB tiles.
// (1,1): Ah*Bh. (2,1): + Al*Bh. (2,2): + Ah*Bl (3-pass).
// Block 128x128, 8 warps (64x32), BK=32, NSTG=3 cp.async pipeline.
// ---------------------------------------------------------------------------
#define HPITCH 80

template <int NA, int NB>
__global__ __launch_bounds__(256)
void gemm_h(const __half* __restrict__ Ah, const __half* __restrict__ Al,
            const __half* __restrict__ Bh, const __half* __restrict__ Bl,
            float* __restrict__ Cf,
            __half* __restrict__ Ch, __half* __restrict__ Cl,
            int M, int N, int K,
            const float* __restrict__ bias, const float* __restrict__ res,
            int gelu) {
    constexpr int STG = (NA + NB) * 10240;
    constexpr int O_AH = 0;
    constexpr int O_AL = 10240;                 // valid only if NA==2
    constexpr int O_BH = NA * 10240;
    constexpr int O_BL = O_BH + 10240;          // valid only if NB==2
    extern __shared__ __align__(128) char smem[];
    uint32_t sb = smem_u32(smem);
    int tid = threadIdx.x, wid = tid >> 5, lane = tid & 31;
    int m0 = blockIdx.y * 128, n0 = blockIdx.x * 128;
    int wm = wid & 1, wn = wid >> 1;

    const __half* Agh = Ah + (size_t)m0 * K;
    const __half* Agl = (NA == 2) ? (Al + (size_t)m0 * K) : nullptr;
    const __half* Bgh = Bh + (size_t)n0 * K;
    const __half* Bgl = (NB == 2) ? (Bl + (size_t)n0 * K) : nullptr;

    float acc[4][4][4];
#pragma unroll
    for (int i = 0; i < 4; i++)
#pragma unroll
        for (int j = 0; j < 4; j++)
#pragma unroll
            for (int r = 0; r < 4; r++) acc[i][j][r] = 0.f;

    const int NC = K >> 5;

#define ISSUE_H(c)                                                             \
    {                                                                          \
        uint32_t s0 = sb + ((c) % 3) * STG;                                    \
        _Pragma("unroll")                                                      \
        for (int it = 0; it < 2; it++) {                                       \
            int i = it * 256 + tid;                                            \
            int row = i >> 2, seg = i & 3;                                     \
            uint32_t so = row * HPITCH + seg * 16;                             \
            size_t go = (size_t)row * K + (size_t)(c) * 32 + seg * 8;          \
            cp16(s0 + O_AH + so, Agh + go);                                    \
            if (NA == 2) cp16(s0 + O_AL + so, Agl + go);                       \
            cp16(s0 + O_BH + so, Bgh + go);                                    \
            if (NB == 2) cp16(s0 + O_BL + so, Bgl + go);                       \
        }                                                                      \
        CP_COMMIT();                                                           \
    }

    ISSUE_H(0);
    ISSUE_H(1);

    int r16 = lane & 15, hsel = lane >> 4;
    int bg = lane >> 3;
    int browoff = ((bg & 2) << 2) + (lane & 7);
    int bkoff = (bg & 1) * 8;

    for (int c = 0; c < NC; c++) {
        if (c + 1 < NC) { CP_WAIT1(); } else { CP_WAIT0(); }
        __syncthreads();
        if (c + 2 < NC) ISSUE_H(c + 2);
        uint32_t base = sb + (c % 3) * STG;
#pragma unroll
        for (int kk = 0; kk < 32; kk += 16) {
            uint32_t ah[16], al[16], bh[8], bl[8];
#pragma unroll
            for (int mt = 0; mt < 4; mt++) {
                uint32_t ad = (uint32_t)((wm * 64 + mt * 16 + r16) * HPITCH +
                                         (kk + hsel * 8) * 2);
                ldsm_x4(ah + 4 * mt, base + O_AH + ad);
                if (NA == 2) ldsm_x4(al + 4 * mt, base + O_AL + ad);
            }
#pragma unroll
            for (int ntp = 0; ntp < 2; ntp++) {
                uint32_t bd = (uint32_t)((wn * 32 + ntp * 16 + browoff) * HPITCH +
                                         (kk + bkoff) * 2);
                ldsm_x4(bh + 4 * ntp, base + O_BH + bd);
                if (NB == 2) ldsm_x4(bl + 4 * ntp, base + O_BL + bd);
            }
#pragma unroll
            for (int mt = 0; mt < 4; mt++)
#pragma unroll
                for (int nt = 0; nt < 4; nt++) {
                    uint32_t* bp = bh + (nt >> 1) * 4 + (nt & 1) * 2;
                    mma_f16(acc[mt][nt], ah + 4 * mt, bp);
                    if (NA == 2) mma_f16(acc[mt][nt], al + 4 * mt, bp);
                    if (NB == 2) {
                        uint32_t* bp2 = bl + (nt >> 1) * 4 + (nt & 1) * 2;
                        mma_f16(acc[mt][nt], ah + 4 * mt, bp2);
                    }
                }
        }
        __syncthreads();
    }
#undef ISSUE_H

    int gid = lane >> 2, qid = lane & 3;
#pragma unroll
    for (int mt = 0; mt < 4; mt++) {
#pragma unroll
        for (int nt = 0; nt < 4; nt++) {
            int n = n0 + wn * 32 + nt * 8 + 2 * qid;
            float bsum0 = bias ? bias[n] : 0.f;
            float bsum1 = bias ? bias[n + 1] : 0.f;
#pragma unroll
            for (int half = 0; half < 2; half++) {
                int m = m0 + wm * 64 + mt * 16 + gid + half * 8;
                float v0 = acc[mt][nt][half * 2 + 0] + bsum0;
                float v1 = acc[mt][nt][half * 2 + 1] + bsum1;
                if (gelu) {
                    v0 = 0.5f * v0 * (1.f + erff(v0 * 0.70710678118654752f));
                    v1 = 0.5f * v1 * (1.f + erff(v1 * 0.70710678118654752f));
                }
                if (res) {
                    const float* rr = res + (size_t)m * N + n;
                    v0 += rr[0];
                    v1 += rr[1];
                }
                if (Cf) {
                    float2 o;
                    o.x = v0; o.y = v1;
                    *(float2*)(Cf + (size_t)m * N + n) = o;
                }
                if (Ch) {
                    __half2 oh;
                    oh.x = __float2half(v0);
                    oh.y = __float2half(v1);
                    *(__half2*)(Ch + (size_t)m * N + n) = oh;
                    if (Cl) {
                        __half2 ol;
                        ol.x = __float2half(v0 - __half2float(oh.x));
                        ol.y = __float2half(v1 - __half2float(oh.y));
                        *(__half2*)(Cl + (size_t)m * N + n) = ol;
                    }
                }
            }
        }
    }
}

// ---------------------------------------------------------------------------
// MMA flash attention (R5-validated structure, fp16 types)
// ---------------------------------------------------------------------------
#define APITCH  144
#define AT_TILE 9216
#define AT_Q    0
#define AT_KV0  (2 * AT_TILE)
#define AT_KVS  (4 * AT_TILE)
#define AT_SMEM (AT_KV0 + 2 * AT_KVS)

__global__ __launch_bounds__(128)
void attn_mma(const __half* __restrict__ qkvh,
              const __half* __restrict__ qkvl,
              __half* __restrict__ oh,
              __half* __restrict__ ol) {
    extern __shared__ __align__(128) char smem[];
    uint32_t sb = smem_u32(smem);
    int tid = threadIdx.x, w = tid >> 5, lane = tid & 31;
    int qi = (int)gridDim.x - 1 - (int)blockIdx.x;
    int bh = blockIdx.y;
    int b = bh >> 4, h = bh & 15;
    const int RS = 3 * Cz;
    const size_t tokbase = (size_t)(b * Tz) * RS + h * Dz;

    int gid = lane >> 2, qid = lane & 3;
    int r16 = lane & 15, hsel = lane >> 4;
    int bg = lane >> 3;
    int browoff = ((bg & 2) << 2) + (lane & 7);
    int bkoff = (bg & 1) * 8;
    int t_row = (bg & 1) * 8 + (lane & 7);
    int t_col = (bg >> 1) * 8;

#define ISSUE_KV(kt)                                                           \
    {                                                                          \
        uint32_t s0 = sb + AT_KV0 + ((kt) & 1) * AT_KVS;                       \
        const __half* srcs[4] = {                                              \
            qkvh + tokbase + Cz, qkvl + tokbase + Cz,                          \
            qkvh + tokbase + 2 * Cz, qkvl + tokbase + 2 * Cz };                \
        _Pragma("unroll")                                                      \
        for (int t = 0; t < 4; t++) {                                          \
            _Pragma("unroll")                                                  \
            for (int it = 0; it < 4; it++) {                                   \
                int i = it * 128 + tid;                                        \
                int r = i >> 3, s = i & 7;                                     \
                cp16(s0 + t * AT_TILE + r * APITCH + s * 16,                   \
                     srcs[t] + (size_t)((kt) * 64 + r) * RS + s * 8);          \
            }                                                                  \
        }                                                                      \
        CP_COMMIT();                                                           \
    }

    {
#pragma unroll
        for (int t = 0; t < 2; t++) {
            const __half* src = (t ? qkvl : qkvh) + tokbase;
            uint32_t dst = sb + AT_Q + t * AT_TILE;
#pragma unroll
            for (int it = 0; it < 4; it++) {
                int i = it * 128 + tid;
                int r = i >> 3, s = i & 7;
                cp16(dst + r * APITCH + s * 16,
                     src + (size_t)(qi * 64 + r) * RS + s * 8);
            }
        }
        uint32_t s0 = sb + AT_KV0;
        const __half* srcs[4] = {
            qkvh + tokbase + Cz, qkvl + tokbase + Cz,
            qkvh + tokbase + 2 * Cz, qkvl + tokbase + 2 * Cz };
#pragma unroll
        for (int t = 0; t < 4; t++) {
#pragma unroll
            for (int it = 0; it < 4; it++) {
                int i = it * 128 + tid;
                int r = i >> 3, s = i & 7;
                cp16(s0 + t * AT_TILE + r * APITCH + s * 16,
                     srcs[t] + (size_t)r * RS + s * 8);
            }
        }
        CP_COMMIT();
    }
    if (qi >= 1) ISSUE_KV(1);

    if (qi >= 1) { CP_WAIT1(); } else { CP_WAIT0(); }
    __syncthreads();

    uint32_t qfh[4][4], qfl[4][4];
#pragma unroll
    for (int kk = 0; kk < 4; kk++) {
        uint32_t ad = sb + AT_Q + (uint32_t)((w * 16 + r16) * APITCH +
                                             (kk * 16 + hsel * 8) * 2);
        ldsm_x4(qfh[kk], ad);
        ldsm_x4(qfl[kk], ad + AT_TILE);
    }

    float oacc[8][4];
#pragma unroll
    for (int i = 0; i < 8; i++)
#pragma unroll
        for (int j = 0; j < 4; j++) oacc[i][j] = 0.f;
    float mrow[2] = {-1e30f, -1e30f};
    float lrow[2] = {0.f, 0.f};

    for (int kt = 0; kt <= qi; kt++) {
        if (kt > 0) {
            if (kt < qi) { CP_WAIT1(); } else { CP_WAIT0(); }
            __syncthreads();
        }
        uint32_t kb = sb + AT_KV0 + (kt & 1) * AT_KVS;

        float s[8][4];
#pragma unroll
        for (int i = 0; i < 8; i++)
#pragma unroll
            for (int j = 0; j < 4; j++) s[i][j] = 0.f;
#pragma unroll
        for (int kk = 0; kk < 4; kk++) {
            uint32_t kh[16], kl[16];
#pragma unroll
            for (int np = 0; np < 4; np++) {
                uint32_t ad = kb + (uint32_t)((np * 16 + browoff) * APITCH +
                                              (kk * 16 + bkoff) * 2);
                ldsm_x4(kh + 4 * np, ad);
                ldsm_x4(kl + 4 * np, ad + AT_TILE);
            }
#pragma unroll
            for (int nt = 0; nt < 8; nt++) {
                uint32_t* bp = kh + (nt >> 1) * 4 + (nt & 1) * 2;
                uint32_t* bl2 = kl + (nt >> 1) * 4 + (nt & 1) * 2;
                mma_f16(s[nt], qfh[kk], bp);
                mma_f16(s[nt], qfh[kk], bl2);
                mma_f16(s[nt], qfl[kk], bp);
            }
        }
#pragma unroll
        for (int nt = 0; nt < 8; nt++)
#pragma unroll
            for (int j = 0; j < 4; j++) s[nt][j] *= 0.125f;
        if (kt == qi) {
#pragma unroll
            for (int nt = 0; nt < 8; nt++)
#pragma unroll
                for (int j = 0; j < 4; j++) {
                    int kc = 8 * nt + 2 * qid + (j & 1);
                    int qr = w * 16 + gid + (j >> 1) * 8;
                    if (kc > qr) s[nt][j] = -1e30f;
                }
        }
        float mt0 = -1e30f, mt1 = -1e30f;
#pragma unroll
        for (int nt = 0; nt < 8; nt++) {
            mt0 = fmaxf(mt0, fmaxf(s[nt][0], s[nt][1]));
            mt1 = fmaxf(mt1, fmaxf(s[nt][2], s[nt][3]));
        }
        mt0 = fmaxf(mt0, __shfl_xor_sync(0xffffffffu, mt0, 1));
        mt0 = fmaxf(mt0, __shfl_xor_sync(0xffffffffu, mt0, 2));
        mt1 = fmaxf(mt1, __shfl_xor_sync(0xffffffffu, mt1, 1));
        mt1 = fmaxf(mt1, __shfl_xor_sync(0xffffffffu, mt1, 2));
        float mn0 = fmaxf(mrow[0], mt0), mn1 = fmaxf(mrow[1], mt1);
        float c0 = __expf(mrow[0] - mn0), c1 = __expf(mrow[1] - mn1);
        mrow[0] = mn0; mrow[1] = mn1;
        float rs0 = 0.f, rs1 = 0.f;
#pragma unroll
        for (int nt = 0; nt < 8; nt++) {
            s[nt][0] = __expf(s[nt][0] - mn0);
            s[nt][1] = __expf(s[nt][1] - mn0);
            s[nt][2] = __expf(s[nt][2] - mn1);
            s[nt][3] = __expf(s[nt][3] - mn1);
            rs0 += s[nt][0] + s[nt][1];
            rs1 += s[nt][2] + s[nt][3];
        }
        rs0 += __shfl_xor_sync(0xffffffffu, rs0, 1);
        rs0 += __shfl_xor_sync(0xffffffffu, rs0, 2);
        rs1 += __shfl_xor_sync(0xffffffffu, rs1, 1);
        rs1 += __shfl_xor_sync(0xffffffffu, rs1, 2);
        lrow[0] = lrow[0] * c0 + rs0;
        lrow[1] = lrow[1] * c1 + rs1;
#pragma unroll
        for (int nt = 0; nt < 8; nt++) {
            oacc[nt][0] *= c0; oacc[nt][1] *= c0;
            oacc[nt][2] *= c1; oacc[nt][3] *= c1;
        }
#pragma unroll
        for (int k2 = 0; k2 < 4; k2++) {
            uint32_t pah[4], pal[4];
            {
                float p00 = s[2 * k2][0],     p01 = s[2 * k2][1];
                float p10 = s[2 * k2][2],     p11 = s[2 * k2][3];
                float p20 = s[2 * k2 + 1][0], p21 = s[2 * k2 + 1][1];
                float p30 = s[2 * k2 + 1][2], p31 = s[2 * k2 + 1][3];
                pah[0] = packh(p00, p01);
                pah[1] = packh(p10, p11);
                pah[2] = packh(p20, p21);
                pah[3] = packh(p30, p31);
                __half2* hp;
                hp = (__half2*)&pah[0];
                pal[0] = packh(p00 - __half2float(hp->x), p01 - __half2float(hp->y));
                hp = (__half2*)&pah[1];
                pal[1] = packh(p10 - __half2float(hp->x), p11 - __half2float(hp->y));
                hp = (__half2*)&pah[2];
                pal[2] = packh(p20 - __half2float(hp->x), p21 - __half2float(hp->y));
                hp = (__half2*)&pah[3];
                pal[3] = packh(p30 - __half2float(hp->x), p31 - __half2float(hp->y));
            }
            uint32_t vh[16], vl[16];
#pragma unroll
            for (int np = 0; np < 4; np++) {
                uint32_t ad = kb + 2 * AT_TILE +
                              (uint32_t)((k2 * 16 + t_row) * APITCH +
                                         (np * 16 + t_col) * 2);
                ldsm_x4t(vh + 4 * np, ad);
                ldsm_x4t(vl + 4 * np, ad + AT_TILE);
            }
#pragma unroll
            for (int nt = 0; nt < 8; nt++) {
                uint32_t* bp = vh + (nt >> 1) * 4 + (nt & 1) * 2;
                uint32_t* bl2 = vl + (nt >> 1) * 4 + (nt & 1) * 2;
                mma_f16(oacc[nt], pah, bp);
                mma_f16(oacc[nt], pah, bl2);
                mma_f16(oacc[nt], pal, bp);
            }
        }
        __syncthreads();
        if (kt + 2 <= qi) ISSUE_KV(kt + 2);
    }
#undef ISSUE_KV

    float inv0 = 1.f / lrow[0], inv1 = 1.f / lrow[1];
    int tok0 = b * Tz + qi * 64 + w * 16 + gid;
#pragma unroll
    for (int nt = 0; nt < 8; nt++) {
        int col = h * Dz + 8 * nt + 2 * qid;
        float v0 = oacc[nt][0] * inv0, v1 = oacc[nt][1] * inv0;
        float v2 = oacc[nt][2] * inv1, v3 = oacc[nt][3] * inv1;
        __half2 ph, pl;
        ph.x = __float2half(v0); ph.y = __float2half(v1);
        pl.x = __float2half(v0 - __half2float(ph.x));
        pl.y = __float2half(v1 - __half2float(ph.y));
        *(__half2*)(oh + (size_t)tok0 * Cz + col) = ph;
        *(__half2*)(ol + (size_t)tok0 * Cz + col) = pl;
        ph.x = __float2half(v2); ph.y = __float2half(v3);
        pl.x = __float2half(v2 - __half2float(ph.x));
        pl.y = __float2half(v3 - __half2float(ph.y));
        *(__half2*)(oh + (size_t)(tok0 + 8) * Cz + col) = ph;
        *(__half2*)(ol + (size_t)(tok0 + 8) * Cz + col) = pl;
    }
}

// ---------------------------------------------------------------------------
// Embedding
// ---------------------------------------------------------------------------
__global__ void embed_kernel(const int* __restrict__ idx,
                             const float* __restrict__ tok,
                             const float* __restrict__ pos,
                             float* __restrict__ x) {
    int row = blockIdx.x;
    int t   = row & (Tz - 1);
    int tokid = idx[row];
    const float* te = tok + (size_t)tokid * Cz;
    const float* pe = pos + (size_t)t * Cz;
    float* xr = x + (size_t)row * Cz;
    for (int i = threadIdx.x; i < Cz; i += blockDim.x)
        xr[i] = te[i] + pe[i];
}

// ---------------------------------------------------------------------------
// LayerNorm per row, writes fp16 hi/lo pair (lo optional)
// ---------------------------------------------------------------------------
__global__ void ln_kernel(const float* __restrict__ x,
                          __half* __restrict__ yh, __half* __restrict__ yl,
                          const float* __restrict__ g, const float* __restrict__ b) {
    int row = blockIdx.x;
    const float* xr = x + (size_t)row * Cz;
    float s = 0.f, s2 = 0.f;
    for (int i = threadIdx.x; i < Cz; i += blockDim.x) {
        float v = xr[i];
        s += v; s2 += v * v;
    }
    __shared__ float sh_s[8], sh_s2[8];
    for (int off = 16; off > 0; off >>= 1) {
        s  += __shfl_down_sync(0xffffffffu, s,  off);
        s2 += __shfl_down_sync(0xffffffffu, s2, off);
    }
    int lane = threadIdx.x & 31, wid = threadIdx.x >> 5;
    if (lane == 0) { sh_s[wid] = s; sh_s2[wid] = s2; }
    __syncthreads();
    if (wid == 0) {
        s  = (lane < 8) ? sh_s[lane]  : 0.f;
        s2 = (lane < 8) ? sh_s2[lane] : 0.f;
        for (int off = 4; off > 0; off >>= 1) {
            s  += __shfl_down_sync(0xffffffffu, s,  off);
            s2 += __shfl_down_sync(0xffffffffu, s2, off);
        }
        if (lane == 0) { sh_s[0] = s; sh_s2[0] = s2; }
    }
    __syncthreads();
    float mean = sh_s[0] * (1.f / Cz);
    float var  = sh_s2[0] * (1.f / Cz) - mean * mean;
    float rstd = rsqrtf(var + EPSz);
    __half* yhr = yh + (size_t)row * Cz;
    __half* ylr = yl ? (yl + (size_t)row * Cz) : nullptr;
    for (int i = threadIdx.x; i < Cz; i += blockDim.x) {
        float v = (xr[i] - mean) * rstd * g[i] + b[i];
        __half h = __float2half(v);
        yhr[i] = h;
        if (ylr) ylr[i] = __float2half(v - __half2float(h));
    }
}

// ---------------------------------------------------------------------------
// Launch
// ---------------------------------------------------------------------------
extern "C" void kernel_launch(void* const* d_in, const int* in_sizes, int n_in,
                              void* d_out, int out_size) {
    const int*   idx     = (const int*)  d_in[0];
    const float* tok_emb = (const float*)d_in[1];
    const float* pos_emb = (const float*)d_in[2];
    const float* qkv_w   = (const float*)d_in[3];
    const float* proj_w  = (const float*)d_in[4];
    const float* proj_b  = (const float*)d_in[5];
    const float* ln1_g   = (const float*)d_in[6];
    const float* ln1_b   = (const float*)d_in[7];
    const float* ln2_g   = (const float*)d_in[8];
    const float* ln2_b   = (const float*)d_in[9];
    const float* fc1_w   = (const float*)d_in[10];
    const float* fc1_b   = (const float*)d_in[11];
    const float* fc2_w   = (const float*)d_in[12];
    const float* fc2_b   = (const float*)d_in[13];
    const float* lnf_g   = (const float*)d_in[14];
    const float* lnf_b   = (const float*)d_in[15];
    float* out = (float*)d_out;

    float* x;
    cudaGetSymbolAddress((void**)&x, g_x);
    __half *hh, *hl, *qkvh, *qkvl, *atth, *attl, *ffnh;
    cudaGetSymbolAddress((void**)&hh,   g_hh);
    cudaGetSymbolAddress((void**)&hl,   g_hl);
    cudaGetSymbolAddress((void**)&qkvh, g_qkvh);
    cudaGetSymbolAddress((void**)&qkvl, g_qkvl);
    cudaGetSymbolAddress((void**)&atth, g_atth);
    cudaGetSymbolAddress((void**)&attl, g_attl);
    cudaGetSymbolAddress((void**)&ffnh, g_ffnh);
    __half *qkvTh, *qkvTl, *projT, *fc1T, *fc2T, *tokT;
    cudaGetSymbolAddress((void**)&qkvTh, g_qkvT_h);
    cudaGetSymbolAddress((void**)&qkvTl, g_qkvT_l);
    cudaGetSymbolAddress((void**)&projT, g_projT);
    cudaGetSymbolAddress((void**)&fc1T,  g_fc1T);
    cudaGetSymbolAddress((void**)&fc2T,  g_fc2T);
    cudaGetSymbolAddress((void**)&tokT,  g_tokT);

    const int GS11 = 3 * 20480;
    const int GS21 = 3 * 30720;
    const int GS22 = 3 * 40960;
    cudaFuncSetAttribute(gemm_h<1, 1>, cudaFuncAttributeMaxDynamicSharedMemorySize, GS11);
    cudaFuncSetAttribute(gemm_h<2, 1>, cudaFuncAttributeMaxDynamicSharedMemorySize, GS21);
    cudaFuncSetAttribute(gemm_h<2, 2>, cudaFuncAttributeMaxDynamicSharedMemorySize, GS22);
    cudaFuncSetAttribute(attn_mma, cudaFuncAttributeMaxDynamicSharedMemorySize, AT_SMEM);

    // ---- weight prep ----
    dim3 tb(32, 8);
    wtrans_pair<<<dim3(3 * Cz / 32, Cz / 32, Lz), tb>>>(qkv_w, qkvTh, qkvTl, Cz, 3 * Cz);
    wtrans_one<<<dim3(Cz / 32, Cz / 32, Lz), tb>>>(proj_w, projT, Cz, Cz);
    wtrans_one<<<dim3(HIDz / 32, Cz / 32, Lz), tb>>>(fc1_w, fc1T, Cz, HIDz);
    wtrans_one<<<dim3(Cz / 32, HIDz / 32, Lz), tb>>>(fc2_w, fc2T, HIDz, Cz);
    wsplit_one<<<(Vz * Cz + 255) / 256, 256>>>(tok_emb, tokT, Vz * Cz);

    embed_kernel<<<NTOK, 256>>>(idx, tok_emb, pos_emb, x);

    for (int l = 0; l < Lz; l++) {
        const __half* qwh = qkvTh + (size_t)l * 3 * Cz * Cz;
        const __half* qwl = qkvTl + (size_t)l * 3 * Cz * Cz;
        const __half* pw  = projT + (size_t)l * Cz * Cz;
        const __half* w1  = fc1T  + (size_t)l * Cz * HIDz;
        const __half* w2  = fc2T  + (size_t)l * Cz * HIDz;
        const float* pb = proj_b + (size_t)l * Cz;
        const float* b1 = fc1_b  + (size_t)l * HIDz;
        const float* b2 = fc2_b  + (size_t)l * Cz;

        ln_kernel<<<NTOK, 256>>>(x, hh, hl, ln1_g + l * Cz, ln1_b + l * Cz);
        gemm_h<2, 2><<<dim3(3 * Cz / 128, NTOK / 128), 256, GS22>>>(
            hh, hl, qwh, qwl, nullptr, qkvh, qkvl,
            NTOK, 3 * Cz, Cz, nullptr, nullptr, 0);
        attn_mma<<<dim3(Tz / 64, Bz * Hz), 128, AT_SMEM>>>(qkvh, qkvl, atth, attl);
        gemm_h<2, 1><<<dim3(Cz / 128, NTOK / 128), 256, GS21>>>(
            atth, attl, pw, nullptr, x, nullptr, nullptr,
            NTOK, Cz, Cz, pb, x, 0);
        ln_kernel<<<NTOK, 256>>>(x, hh, nullptr, ln2_g + l * Cz, ln2_b + l * Cz);
        gemm_h<1, 1><<<dim3(HIDz / 128, NTOK / 128), 256, GS11>>>(
            hh, nullptr, w1, nullptr, nullptr, ffnh, nullptr,
            NTOK, HIDz, Cz, b1, nullptr, 1);
        gemm_h<1, 1><<<dim3(Cz / 128, NTOK / 128), 256, GS11>>>(
            ffnh, nullptr, w2, nullptr, x, nullptr, nullptr,
            NTOK, Cz, HIDz, b2, x, 0);
    }

    ln_kernel<<<NTOK, 256>>>(x, hh, nullptr, lnf_g, lnf_b);
    gemm_h<1, 1><<<dim3(Vz / 128, NTOK / 128), 256, GS11>>>(
        hh, nullptr, tokT, nullptr, out, nullptr, nullptr,
        NTOK, Vz, Cz, nullptr, nullptr, 0);
}

// round 12
// speedup vs baseline: 3.9837x; 1.0242x over previous
#include <cuda_runtime.h>
#include <cuda_fp16.h>
#include <cstdint>
#include <math.h>

// Problem constants
#define Bz   2
#define Tz   1024
#define Cz   1024
#define Hz   16
#define Lz   8
#define Dz   64
#define HIDz 4096
#define Vz   32000
#define NTOK (Bz * Tz)          // 2048
#define EPSz 1e-5f

// ---------------------------------------------------------------------------
// PTX helpers (base ISA only)
// ---------------------------------------------------------------------------
__device__ __forceinline__ uint32_t smem_u32(const void* p) {
    uint32_t a;
    asm("{ .reg .u64 t; cvta.to.shared.u64 t, %1; cvt.u32.u64 %0, t; }"
        : "=r"(a) : "l"(p));
    return a;
}
__device__ __forceinline__ void ldsm_x4(uint32_t* r, uint32_t addr) {
    asm volatile("ldmatrix.sync.aligned.m8n8.x4.shared.b16 {%0,%1,%2,%3}, [%4];"
        : "=r"(r[0]), "=r"(r[1]), "=r"(r[2]), "=r"(r[3]) : "r"(addr));
}
__device__ __forceinline__ void ldsm_x4t(uint32_t* r, uint32_t addr) {
    asm volatile("ldmatrix.sync.aligned.m8n8.x4.trans.shared.b16 {%0,%1,%2,%3}, [%4];"
        : "=r"(r[0]), "=r"(r[1]), "=r"(r[2]), "=r"(r[3]) : "r"(addr));
}
__device__ __forceinline__ void mma_f16(float* d, const uint32_t* a, const uint32_t* b) {
    asm volatile("mma.sync.aligned.m16n8k16.row.col.f32.f16.f16.f32 "
        "{%0,%1,%2,%3}, {%4,%5,%6,%7}, {%8,%9}, {%0,%1,%2,%3};"
        : "+f"(d[0]), "+f"(d[1]), "+f"(d[2]), "+f"(d[3])
        : "r"(a[0]), "r"(a[1]), "r"(a[2]), "r"(a[3]), "r"(b[0]), "r"(b[1]));
}
__device__ __forceinline__ void cp16(uint32_t saddr, const void* gaddr) {
    asm volatile("cp.async.ca.shared.global [%0], [%1], 16;"
                 :: "r"(saddr), "l"(gaddr) : "memory");
}
#define CP_COMMIT() asm volatile("cp.async.commit_group;" ::: "memory")
#define CP_WAIT1()  asm volatile("cp.async.wait_group 1;" ::: "memory")
#define CP_WAIT0()  asm volatile("cp.async.wait_group 0;" ::: "memory")

__device__ __forceinline__ uint32_t packh(float x, float y) {
    __half2 t;
    t.x = __float2half(x);
    t.y = __float2half(y);
    return *(uint32_t*)&t;
}

// ---------------------------------------------------------------------------
// Scratch (device globals)
// ---------------------------------------------------------------------------
__device__ float g_x[NTOK * Cz];                 // residual stream
__device__ __half g_hh  [NTOK * Cz];
__device__ __half g_hl  [NTOK * Cz];
__device__ __half g_qkvh[NTOK * 3 * Cz];
__device__ __half g_qkvl[NTOK * 3 * Cz];
__device__ __half g_atth[NTOK * Cz];
__device__ __half g_attl[NTOK * Cz];
__device__ __half g_ffnh[NTOK * HIDz];

// Weights, transposed to [N,K]. qkv = fp16 pair; rest = single fp16.
__device__ __half g_qkvT_h[Lz * 3 * Cz * Cz];
__device__ __half g_qkvT_l[Lz * 3 * Cz * Cz];
__device__ __half g_projT[Lz * Cz * Cz];
__device__ __half g_fc1T [Lz * HIDz * Cz];
__device__ __half g_fc2T [Lz * Cz * HIDz];
__device__ __half g_tokT [Vz * Cz];

// ---------------------------------------------------------------------------
// Weight prep
// ---------------------------------------------------------------------------
__global__ void wtrans_pair(const float* __restrict__ W,
                            __half* __restrict__ Th, __half* __restrict__ Tl,
                            int K, int N) {
    __shared__ float t[32][33];
    const float* Wl = W + (size_t)blockIdx.z * K * N;
    __half* Thl = Th + (size_t)blockIdx.z * K * N;
    __half* Tll = Tl + (size_t)blockIdx.z * K * N;
    int n0 = blockIdx.x * 32, k0 = blockIdx.y * 32;
    int tx = threadIdx.x, ty = threadIdx.y;
#pragma unroll
    for (int j = 0; j < 32; j += 8)
        t[ty + j][tx] = Wl[(size_t)(k0 + ty + j) * N + n0 + tx];
    __syncthreads();
#pragma unroll
    for (int j = 0; j < 32; j += 8) {
        float v = t[tx][ty + j];
        __half h = __float2half(v);
        size_t o = (size_t)(n0 + ty + j) * K + k0 + tx;
        Thl[o] = h;
        Tll[o] = __float2half(v - __half2float(h));
    }
}

// Improved transpose: tile 32n x 64k, half2 writes (128B per warp transaction)
__global__ void wtrans_one(const float* __restrict__ W,
                           __half* __restrict__ T, int K, int N) {
    __shared__ float t[64][33];
    const float* Wl = W + (size_t)blockIdx.z * K * N;
    __half* Tg = T + (size_t)blockIdx.z * K * N;
    int n0 = blockIdx.x * 32, k0 = blockIdx.y * 64;
    int tx = threadIdx.x, ty = threadIdx.y;
#pragma unroll
    for (int j = 0; j < 64; j += 8)
        t[ty + j][tx] = Wl[(size_t)(k0 + ty + j) * N + n0 + tx];
    __syncthreads();
#pragma unroll
    for (int p = 0; p < 4; p++) {
        int nloc = p * 8 + ty;
        __half2 h2;
        h2.x = __float2half(t[2 * tx][nloc]);
        h2.y = __float2half(t[2 * tx + 1][nloc]);
        *(__half2*)(Tg + (size_t)(n0 + nloc) * K + k0 + 2 * tx) = h2;
    }
}

__global__ void wsplit_one(const float* __restrict__ W, __half* __restrict__ T, int n) {
    int i = blockIdx.x * blockDim.x + threadIdx.x;
    if (i < n) T[i] = __float2half(W[i]);
}

// ---------------------------------------------------------------------------
// gemm_h<NA,NB>: fp16 mma GEMM. A = NA tiles, B = NB tiles.
// (1,1): Ah*Bh. (2,1): + Al*Bh. (2,2): + Ah*Bl (3-pass).
// ldc = output row stride (allows writing a column slice of a wider matrix).
// Block 128x128, 8 warps (64x32), BK=32, NSTG=3 cp.async pipeline.
// ---------------------------------------------------------------------------
#define HPITCH 80

template <int NA, int NB>
__global__ __launch_bounds__(256)
void gemm_h(const __half* __restrict__ Ah, const __half* __restrict__ Al,
            const __half* __restrict__ Bh, const __half* __restrict__ Bl,
            float* __restrict__ Cf,
            __half* __restrict__ Ch, __half* __restrict__ Cl,
            int M, int N, int K, int ldc,
            const float* __restrict__ bias, const float* __restrict__ res,
            int gelu) {
    constexpr int STG = (NA + NB) * 10240;
    constexpr int O_AH = 0;
    constexpr int O_AL = 10240;                 // valid only if NA==2
    constexpr int O_BH = NA * 10240;
    constexpr int O_BL = O_BH + 10240;          // valid only if NB==2
    extern __shared__ __align__(128) char smem[];
    uint32_t sb = smem_u32(smem);
    int tid = threadIdx.x, wid = tid >> 5, lane = tid & 31;
    int m0 = blockIdx.y * 128, n0 = blockIdx.x * 128;
    int wm = wid & 1, wn = wid >> 1;

    const __half* Agh = Ah + (size_t)m0 * K;
    const __half* Agl = (NA == 2) ? (Al + (size_t)m0 * K) : nullptr;
    const __half* Bgh = Bh + (size_t)n0 * K;
    const __half* Bgl = (NB == 2) ? (Bl + (size_t)n0 * K) : nullptr;

    float acc[4][4][4];
#pragma unroll
    for (int i = 0; i < 4; i++)
#pragma unroll
        for (int j = 0; j < 4; j++)
#pragma unroll
            for (int r = 0; r < 4; r++) acc[i][j][r] = 0.f;

    const int NC = K >> 5;

#define ISSUE_H(c)                                                             \
    {                                                                          \
        uint32_t s0 = sb + ((c) % 3) * STG;                                    \
        _Pragma("unroll")                                                      \
        for (int it = 0; it < 2; it++) {                                       \
            int i = it * 256 + tid;                                            \
            int row = i >> 2, seg = i & 3;                                     \
            uint32_t so = row * HPITCH + seg * 16;                             \
            size_t go = (size_t)row * K + (size_t)(c) * 32 + seg * 8;          \
            cp16(s0 + O_AH + so, Agh + go);                                    \
            if (NA == 2) cp16(s0 + O_AL + so, Agl + go);                       \
            cp16(s0 + O_BH + so, Bgh + go);                                    \
            if (NB == 2) cp16(s0 + O_BL + so, Bgl + go);                       \
        }                                                                      \
        CP_COMMIT();                                                           \
    }

    ISSUE_H(0);
    ISSUE_H(1);

    int r16 = lane & 15, hsel = lane >> 4;
    int bg = lane >> 3;
    int browoff = ((bg & 2) << 2) + (lane & 7);
    int bkoff = (bg & 1) * 8;

    for (int c = 0; c < NC; c++) {
        if (c + 1 < NC) { CP_WAIT1(); } else { CP_WAIT0(); }
        __syncthreads();
        if (c + 2 < NC) ISSUE_H(c + 2);
        uint32_t base = sb + (c % 3) * STG;
#pragma unroll
        for (int kk = 0; kk < 32; kk += 16) {
            uint32_t ah[16], al[16], bh[8], bl[8];
#pragma unroll
            for (int mt = 0; mt < 4; mt++) {
                uint32_t ad = (uint32_t)((wm * 64 + mt * 16 + r16) * HPITCH +
                                         (kk + hsel * 8) * 2);
                ldsm_x4(ah + 4 * mt, base + O_AH + ad);
                if (NA == 2) ldsm_x4(al + 4 * mt, base + O_AL + ad);
            }
#pragma unroll
            for (int ntp = 0; ntp < 2; ntp++) {
                uint32_t bd = (uint32_t)((wn * 32 + ntp * 16 + browoff) * HPITCH +
                                         (kk + bkoff) * 2);
                ldsm_x4(bh + 4 * ntp, base + O_BH + bd);
                if (NB == 2) ldsm_x4(bl + 4 * ntp, base + O_BL + bd);
            }
#pragma unroll
            for (int mt = 0; mt < 4; mt++)
#pragma unroll
                for (int nt = 0; nt < 4; nt++) {
                    uint32_t* bp = bh + (nt >> 1) * 4 + (nt & 1) * 2;
                    mma_f16(acc[mt][nt], ah + 4 * mt, bp);
                    if (NA == 2) mma_f16(acc[mt][nt], al + 4 * mt, bp);
                    if (NB == 2) {
                        uint32_t* bp2 = bl + (nt >> 1) * 4 + (nt & 1) * 2;
                        mma_f16(acc[mt][nt], ah + 4 * mt, bp2);
                    }
                }
        }
        __syncthreads();
    }
#undef ISSUE_H

    int gid = lane >> 2, qid = lane & 3;
#pragma unroll
    for (int mt = 0; mt < 4; mt++) {
#pragma unroll
        for (int nt = 0; nt < 4; nt++) {
            int n = n0 + wn * 32 + nt * 8 + 2 * qid;
            float bsum0 = bias ? bias[n] : 0.f;
            float bsum1 = bias ? bias[n + 1] : 0.f;
#pragma unroll
            for (int half = 0; half < 2; half++) {
                int m = m0 + wm * 64 + mt * 16 + gid + half * 8;
                float v0 = acc[mt][nt][half * 2 + 0] + bsum0;
                float v1 = acc[mt][nt][half * 2 + 1] + bsum1;
                if (gelu) {
                    v0 = 0.5f * v0 * (1.f + erff(v0 * 0.70710678118654752f));
                    v1 = 0.5f * v1 * (1.f + erff(v1 * 0.70710678118654752f));
                }
                if (res) {
                    const float* rr = res + (size_t)m * ldc + n;
                    v0 += rr[0];
                    v1 += rr[1];
                }
                if (Cf) {
                    float2 o;
                    o.x = v0; o.y = v1;
                    *(float2*)(Cf + (size_t)m * ldc + n) = o;
                }
                if (Ch) {
                    __half2 oh;
                    oh.x = __float2half(v0);
                    oh.y = __float2half(v1);
                    *(__half2*)(Ch + (size_t)m * ldc + n) = oh;
                    if (Cl) {
                        __half2 ol;
                        ol.x = __float2half(v0 - __half2float(oh.x));
                        ol.y = __float2half(v1 - __half2float(oh.y));
                        *(__half2*)(Cl + (size_t)m * ldc + n) = ol;
                    }
                }
            }
        }
    }
}

// ---------------------------------------------------------------------------
// MMA flash attention (R5-validated structure, fp16 types)
// ---------------------------------------------------------------------------
#define APITCH  144
#define AT_TILE 9216
#define AT_Q    0
#define AT_KV0  (2 * AT_TILE)
#define AT_KVS  (4 * AT_TILE)
#define AT_SMEM (AT_KV0 + 2 * AT_KVS)

__global__ __launch_bounds__(128)
void attn_mma(const __half* __restrict__ qkvh,
              const __half* __restrict__ qkvl,
              __half* __restrict__ oh,
              __half* __restrict__ ol) {
    extern __shared__ __align__(128) char smem[];
    uint32_t sb = smem_u32(smem);
    int tid = threadIdx.x, w = tid >> 5, lane = tid & 31;
    int qi = (int)gridDim.x - 1 - (int)blockIdx.x;
    int bh = blockIdx.y;
    int b = bh >> 4, h = bh & 15;
    const int RS = 3 * Cz;
    const size_t tokbase = (size_t)(b * Tz) * RS + h * Dz;

    int gid = lane >> 2, qid = lane & 3;
    int r16 = lane & 15, hsel = lane >> 4;
    int bg = lane >> 3;
    int browoff = ((bg & 2) << 2) + (lane & 7);
    int bkoff = (bg & 1) * 8;
    int t_row = (bg & 1) * 8 + (lane & 7);
    int t_col = (bg >> 1) * 8;

#define ISSUE_KV(kt)                                                           \
    {                                                                          \
        uint32_t s0 = sb + AT_KV0 + ((kt) & 1) * AT_KVS;                       \
        const __half* srcs[4] = {                                              \
            qkvh + tokbase + Cz, qkvl + tokbase + Cz,                          \
            qkvh + tokbase + 2 * Cz, qkvl + tokbase + 2 * Cz };                \
        _Pragma("unroll")                                                      \
        for (int t = 0; t < 4; t++) {                                          \
            _Pragma("unroll")                                                  \
            for (int it = 0; it < 4; it++) {                                   \
                int i = it * 128 + tid;                                        \
                int r = i >> 3, s = i & 7;                                     \
                cp16(s0 + t * AT_TILE + r * APITCH + s * 16,                   \
                     srcs[t] + (size_t)((kt) * 64 + r) * RS + s * 8);          \
            }                                                                  \
        }                                                                      \
        CP_COMMIT();                                                           \
    }

    {
#pragma unroll
        for (int t = 0; t < 2; t++) {
            const __half* src = (t ? qkvl : qkvh) + tokbase;
            uint32_t dst = sb + AT_Q + t * AT_TILE;
#pragma unroll
            for (int it = 0; it < 4; it++) {
                int i = it * 128 + tid;
                int r = i >> 3, s = i & 7;
                cp16(dst + r * APITCH + s * 16,
                     src + (size_t)(qi * 64 + r) * RS + s * 8);
            }
        }
        uint32_t s0 = sb + AT_KV0;
        const __half* srcs[4] = {
            qkvh + tokbase + Cz, qkvl + tokbase + Cz,
            qkvh + tokbase + 2 * Cz, qkvl + tokbase + 2 * Cz };
#pragma unroll
        for (int t = 0; t < 4; t++) {
#pragma unroll
            for (int it = 0; it < 4; it++) {
                int i = it * 128 + tid;
                int r = i >> 3, s = i & 7;
                cp16(s0 + t * AT_TILE + r * APITCH + s * 16,
                     srcs[t] + (size_t)r * RS + s * 8);
            }
        }
        CP_COMMIT();
    }
    if (qi >= 1) ISSUE_KV(1);

    if (qi >= 1) { CP_WAIT1(); } else { CP_WAIT0(); }
    __syncthreads();

    uint32_t qfh[4][4], qfl[4][4];
#pragma unroll
    for (int kk = 0; kk < 4; kk++) {
        uint32_t ad = sb + AT_Q + (uint32_t)((w * 16 + r16) * APITCH +
                                             (kk * 16 + hsel * 8) * 2);
        ldsm_x4(qfh[kk], ad);
        ldsm_x4(qfl[kk], ad + AT_TILE);
    }

    float oacc[8][4];
#pragma unroll
    for (int i = 0; i < 8; i++)
#pragma unroll
        for (int j = 0; j < 4; j++) oacc[i][j] = 0.f;
    float mrow[2] = {-1e30f, -1e30f};
    float lrow[2] = {0.f, 0.f};

    for (int kt = 0; kt <= qi; kt++) {
        if (kt > 0) {
            if (kt < qi) { CP_WAIT1(); } else { CP_WAIT0(); }
            __syncthreads();
        }
        uint32_t kb = sb + AT_KV0 + (kt & 1) * AT_KVS;

        float s[8][4];
#pragma unroll
        for (int i = 0; i < 8; i++)
#pragma unroll
            for (int j = 0; j < 4; j++) s[i][j] = 0.f;
#pragma unroll
        for (int kk = 0; kk < 4; kk++) {
            uint32_t kh[16], kl[16];
#pragma unroll
            for (int np = 0; np < 4; np++) {
                uint32_t ad = kb + (uint32_t)((np * 16 + browoff) * APITCH +
                                              (kk * 16 + bkoff) * 2);
                ldsm_x4(kh + 4 * np, ad);
                ldsm_x4(kl + 4 * np, ad + AT_TILE);
            }
#pragma unroll
            for (int nt = 0; nt < 8; nt++) {
                uint32_t* bp = kh + (nt >> 1) * 4 + (nt & 1) * 2;
                uint32_t* bl2 = kl + (nt >> 1) * 4 + (nt & 1) * 2;
                mma_f16(s[nt], qfh[kk], bp);
                mma_f16(s[nt], qfh[kk], bl2);
                mma_f16(s[nt], qfl[kk], bp);
            }
        }
#pragma unroll
        for (int nt = 0; nt < 8; nt++)
#pragma unroll
            for (int j = 0; j < 4; j++) s[nt][j] *= 0.125f;
        if (kt == qi) {
#pragma unroll
            for (int nt = 0; nt < 8; nt++)
#pragma unroll
                for (int j = 0; j < 4; j++) {
                    int kc = 8 * nt + 2 * qid + (j & 1);
                    int qr = w * 16 + gid + (j >> 1) * 8;
                    if (kc > qr) s[nt][j] = -1e30f;
                }
        }
        float mt0 = -1e30f, mt1 = -1e30f;
#pragma unroll
        for (int nt = 0; nt < 8; nt++) {
            mt0 = fmaxf(mt0, fmaxf(s[nt][0], s[nt][1]));
            mt1 = fmaxf(mt1, fmaxf(s[nt][2], s[nt][3]));
        }
        mt0 = fmaxf(mt0, __shfl_xor_sync(0xffffffffu, mt0, 1));
        mt0 = fmaxf(mt0, __shfl_xor_sync(0xffffffffu, mt0, 2));
        mt1 = fmaxf(mt1, __shfl_xor_sync(0xffffffffu, mt1, 1));
        mt1 = fmaxf(mt1, __shfl_xor_sync(0xffffffffu, mt1, 2));
        float mn0 = fmaxf(mrow[0], mt0), mn1 = fmaxf(mrow[1], mt1);
        float c0 = __expf(mrow[0] - mn0), c1 = __expf(mrow[1] - mn1);
        mrow[0] = mn0; mrow[1] = mn1;
        float rs0 = 0.f, rs1 = 0.f;
#pragma unroll
        for (int nt = 0; nt < 8; nt++) {
            s[nt][0] = __expf(s[nt][0] - mn0);
            s[nt][1] = __expf(s[nt][1] - mn0);
            s[nt][2] = __expf(s[nt][2] - mn1);
            s[nt][3] = __expf(s[nt][3] - mn1);
            rs0 += s[nt][0] + s[nt][1];
            rs1 += s[nt][2] + s[nt][3];
        }
        rs0 += __shfl_xor_sync(0xffffffffu, rs0, 1);
        rs0 += __shfl_xor_sync(0xffffffffu, rs0, 2);
        rs1 += __shfl_xor_sync(0xffffffffu, rs1, 1);
        rs1 += __shfl_xor_sync(0xffffffffu, rs1, 2);
        lrow[0] = lrow[0] * c0 + rs0;
        lrow[1] = lrow[1] * c1 + rs1;
#pragma unroll
        for (int nt = 0; nt < 8; nt++) {
            oacc[nt][0] *= c0; oacc[nt][1] *= c0;
            oacc[nt][2] *= c1; oacc[nt][3] *= c1;
        }
#pragma unroll
        for (int k2 = 0; k2 < 4; k2++) {
            uint32_t pah[4], pal[4];
            {
                float p00 = s[2 * k2][0],     p01 = s[2 * k2][1];
                float p10 = s[2 * k2][2],     p11 = s[2 * k2][3];
                float p20 = s[2 * k2 + 1][0], p21 = s[2 * k2 + 1][1];
                float p30 = s[2 * k2 + 1][2], p31 = s[2 * k2 + 1][3];
                pah[0] = packh(p00, p01);
                pah[1] = packh(p10, p11);
                pah[2] = packh(p20, p21);
                pah[3] = packh(p30, p31);
                __half2* hp;
                hp = (__half2*)&pah[0];
                pal[0] = packh(p00 - __half2float(hp->x), p01 - __half2float(hp->y));
                hp = (__half2*)&pah[1];
                pal[1] = packh(p10 - __half2float(hp->x), p11 - __half2float(hp->y));
                hp = (__half2*)&pah[2];
                pal[2] = packh(p20 - __half2float(hp->x), p21 - __half2float(hp->y));
                hp = (__half2*)&pah[3];
                pal[3] = packh(p30 - __half2float(hp->x), p31 - __half2float(hp->y));
            }
            uint32_t vh[16], vl[16];
#pragma unroll
            for (int np = 0; np < 4; np++) {
                uint32_t ad = kb + 2 * AT_TILE +
                              (uint32_t)((k2 * 16 + t_row) * APITCH +
                                         (np * 16 + t_col) * 2);
                ldsm_x4t(vh + 4 * np, ad);
                ldsm_x4t(vl + 4 * np, ad + AT_TILE);
            }
#pragma unroll
            for (int nt = 0; nt < 8; nt++) {
                uint32_t* bp = vh + (nt >> 1) * 4 + (nt & 1) * 2;
                uint32_t* bl2 = vl + (nt >> 1) * 4 + (nt & 1) * 2;
                mma_f16(oacc[nt], pah, bp);
                mma_f16(oacc[nt], pah, bl2);
                mma_f16(oacc[nt], pal, bp);
            }
        }
        __syncthreads();
        if (kt + 2 <= qi) ISSUE_KV(kt + 2);
    }
#undef ISSUE_KV

    float inv0 = 1.f / lrow[0], inv1 = 1.f / lrow[1];
    int tok0 = b * Tz + qi * 64 + w * 16 + gid;
#pragma unroll
    for (int nt = 0; nt < 8; nt++) {
        int col = h * Dz + 8 * nt + 2 * qid;
        float v0 = oacc[nt][0] * inv0, v1 = oacc[nt][1] * inv0;
        float v2 = oacc[nt][2] * inv1, v3 = oacc[nt][3] * inv1;
        __half2 ph, pl;
        ph.x = __float2half(v0); ph.y = __float2half(v1);
        pl.x = __float2half(v0 - __half2float(ph.x));
        pl.y = __float2half(v1 - __half2float(ph.y));
        *(__half2*)(oh + (size_t)tok0 * Cz + col) = ph;
        *(__half2*)(ol + (size_t)tok0 * Cz + col) = pl;
        ph.x = __float2half(v2); ph.y = __float2half(v3);
        pl.x = __float2half(v2 - __half2float(ph.x));
        pl.y = __float2half(v3 - __half2float(ph.y));
        *(__half2*)(oh + (size_t)(tok0 + 8) * Cz + col) = ph;
        *(__half2*)(ol + (size_t)(tok0 + 8) * Cz + col) = pl;
    }
}

// ---------------------------------------------------------------------------
// Embedding
// ---------------------------------------------------------------------------
__global__ void embed_kernel(const int* __restrict__ idx,
                             const float* __restrict__ tok,
                             const float* __restrict__ pos,
                             float* __restrict__ x) {
    int row = blockIdx.x;
    int t   = row & (Tz - 1);
    int tokid = idx[row];
    const float* te = tok + (size_t)tokid * Cz;
    const float* pe = pos + (size_t)t * Cz;
    float* xr = x + (size_t)row * Cz;
    for (int i = threadIdx.x; i < Cz; i += blockDim.x)
        xr[i] = te[i] + pe[i];
}

// ---------------------------------------------------------------------------
// LayerNorm per row, writes fp16 hi/lo pair (lo optional)
// ---------------------------------------------------------------------------
__global__ void ln_kernel(const float* __restrict__ x,
                          __half* __restrict__ yh, __half* __restrict__ yl,
                          const float* __restrict__ g, const float* __restrict__ b) {
    int row = blockIdx.x;
    const float* xr = x + (size_t)row * Cz;
    float s = 0.f, s2 = 0.f;
    for (int i = threadIdx.x; i < Cz; i += blockDim.x) {
        float v = xr[i];
        s += v; s2 += v * v;
    }
    __shared__ float sh_s[8], sh_s2[8];
    for (int off = 16; off > 0; off >>= 1) {
        s  += __shfl_down_sync(0xffffffffu, s,  off);
        s2 += __shfl_down_sync(0xffffffffu, s2, off);
    }
    int lane = threadIdx.x & 31, wid = threadIdx.x >> 5;
    if (lane == 0) { sh_s[wid] = s; sh_s2[wid] = s2; }
    __syncthreads();
    if (wid == 0) {
        s  = (lane < 8) ? sh_s[lane]  : 0.f;
        s2 = (lane < 8) ? sh_s2[lane] : 0.f;
        for (int off = 4; off > 0; off >>= 1) {
            s  += __shfl_down_sync(0xffffffffu, s,  off);
            s2 += __shfl_down_sync(0xffffffffu, s2, off);
        }
        if (lane == 0) { sh_s[0] = s; sh_s2[0] = s2; }
    }
    __syncthreads();
    float mean = sh_s[0] * (1.f / Cz);
    float var  = sh_s2[0] * (1.f / Cz) - mean * mean;
    float rstd = rsqrtf(var + EPSz);
    __half* yhr = yh + (size_t)row * Cz;
    __half* ylr = yl ? (yl + (size_t)row * Cz) : nullptr;
    for (int i = threadIdx.x; i < Cz; i += blockDim.x) {
        float v = (xr[i] - mean) * rstd * g[i] + b[i];
        __half h = __float2half(v);
        yhr[i] = h;
        if (ylr) ylr[i] = __float2half(v - __half2float(h));
    }
}

// ---------------------------------------------------------------------------
// Launch
// ---------------------------------------------------------------------------
extern "C" void kernel_launch(void* const* d_in, const int* in_sizes, int n_in,
                              void* d_out, int out_size) {
    const int*   idx     = (const int*)  d_in[0];
    const float* tok_emb = (const float*)d_in[1];
    const float* pos_emb = (const float*)d_in[2];
    const float* qkv_w   = (const float*)d_in[3];
    const float* proj_w  = (const float*)d_in[4];
    const float* proj_b  = (const float*)d_in[5];
    const float* ln1_g   = (const float*)d_in[6];
    const float* ln1_b   = (const float*)d_in[7];
    const float* ln2_g   = (const float*)d_in[8];
    const float* ln2_b   = (const float*)d_in[9];
    const float* fc1_w   = (const float*)d_in[10];
    const float* fc1_b   = (const float*)d_in[11];
    const float* fc2_w   = (const float*)d_in[12];
    const float* fc2_b   = (const float*)d_in[13];
    const float* lnf_g   = (const float*)d_in[14];
    const float* lnf_b   = (const float*)d_in[15];
    float* out = (float*)d_out;

    float* x;
    cudaGetSymbolAddress((void**)&x, g_x);
    __half *hh, *hl, *qkvh, *qkvl, *atth, *attl, *ffnh;
    cudaGetSymbolAddress((void**)&hh,   g_hh);
    cudaGetSymbolAddress((void**)&hl,   g_hl);
    cudaGetSymbolAddress((void**)&qkvh, g_qkvh);
    cudaGetSymbolAddress((void**)&qkvl, g_qkvl);
    cudaGetSymbolAddress((void**)&atth, g_atth);
    cudaGetSymbolAddress((void**)&attl, g_attl);
    cudaGetSymbolAddress((void**)&ffnh, g_ffnh);
    __half *qkvTh, *qkvTl, *projT, *fc1T, *fc2T, *tokT;
    cudaGetSymbolAddress((void**)&qkvTh, g_qkvT_h);
    cudaGetSymbolAddress((void**)&qkvTl, g_qkvT_l);
    cudaGetSymbolAddress((void**)&projT, g_projT);
    cudaGetSymbolAddress((void**)&fc1T,  g_fc1T);
    cudaGetSymbolAddress((void**)&fc2T,  g_fc2T);
    cudaGetSymbolAddress((void**)&tokT,  g_tokT);

    const int GS11 = 3 * 20480;
    const int GS21 = 3 * 30720;
    const int GS22 = 3 * 40960;
    cudaFuncSetAttribute(gemm_h<1, 1>, cudaFuncAttributeMaxDynamicSharedMemorySize, GS11);
    cudaFuncSetAttribute(gemm_h<2, 1>, cudaFuncAttributeMaxDynamicSharedMemorySize, GS21);
    cudaFuncSetAttribute(gemm_h<2, 2>, cudaFuncAttributeMaxDynamicSharedMemorySize, GS22);
    cudaFuncSetAttribute(attn_mma, cudaFuncAttributeMaxDynamicSharedMemorySize, AT_SMEM);

    // ---- weight prep ----
    dim3 tb(32, 8);
    wtrans_pair<<<dim3(3 * Cz / 32, Cz / 32, Lz), tb>>>(qkv_w, qkvTh, qkvTl, Cz, 3 * Cz);
    wtrans_one<<<dim3(Cz / 32, Cz / 64, Lz), tb>>>(proj_w, projT, Cz, Cz);
    wtrans_one<<<dim3(HIDz / 32, Cz / 64, Lz), tb>>>(fc1_w, fc1T, Cz, HIDz);
    wtrans_one<<<dim3(Cz / 32, HIDz / 64, Lz), tb>>>(fc2_w, fc2T, HIDz, Cz);
    wsplit_one<<<(Vz * Cz + 255) / 256, 256>>>(tok_emb, tokT, Vz * Cz);

    embed_kernel<<<NTOK, 256>>>(idx, tok_emb, pos_emb, x);

    for (int l = 0; l < Lz; l++) {
        const __half* qwh = qkvTh + (size_t)l * 3 * Cz * Cz;
        const __half* qwl = qkvTl + (size_t)l * 3 * Cz * Cz;
        const __half* vwh = qwh + (size_t)2 * Cz * Cz;     // v rows [2048,3072)
        const __half* pw  = projT + (size_t)l * Cz * Cz;
        const __half* w1  = fc1T  + (size_t)l * Cz * HIDz;
        const __half* w2  = fc2T  + (size_t)l * Cz * HIDz;
        const float* pb = proj_b + (size_t)l * Cz;
        const float* b1 = fc1_b  + (size_t)l * HIDz;
        const float* b2 = fc2_b  + (size_t)l * Cz;

        ln_kernel<<<NTOK, 256>>>(x, hh, hl, ln1_g + l * Cz, ln1_b + l * Cz);
        // q,k: 3-pass (softmax-sensitive), columns [0, 2048)
        gemm_h<2, 2><<<dim3(2 * Cz / 128, NTOK / 128), 256, GS22>>>(
            hh, hl, qwh, qwl, nullptr, qkvh, qkvl,
            NTOK, 2 * Cz, Cz, 3 * Cz, nullptr, nullptr, 0);
        // v: 2-pass (linear path), columns [2048, 3072)
        gemm_h<2, 1><<<dim3(Cz / 128, NTOK / 128), 256, GS21>>>(
            hh, hl, vwh, nullptr, nullptr, qkvh + 2 * Cz, qkvl + 2 * Cz,
            NTOK, Cz, Cz, 3 * Cz, nullptr, nullptr, 0);
        attn_mma<<<dim3(Tz / 64, Bz * Hz), 128, AT_SMEM>>>(qkvh, qkvl, atth, attl);
        gemm_h<2, 1><<<dim3(Cz / 128, NTOK / 128), 256, GS21>>>(
            atth, attl, pw, nullptr, x, nullptr, nullptr,
            NTOK, Cz, Cz, Cz, pb, x, 0);
        ln_kernel<<<NTOK, 256>>>(x, hh, nullptr, ln2_g + l * Cz, ln2_b + l * Cz);
        gemm_h<1, 1><<<dim3(HIDz / 128, NTOK / 128), 256, GS11>>>(
            hh, nullptr, w1, nullptr, nullptr, ffnh, nullptr,
            NTOK, HIDz, Cz, HIDz, b1, nullptr, 1);
        gemm_h<1, 1><<<dim3(Cz / 128, NTOK / 128), 256, GS11>>>(
            ffnh, nullptr, w2, nullptr, x, nullptr, nullptr,
            NTOK, Cz, HIDz, Cz, b2, x, 0);
    }

    ln_kernel<<<NTOK, 256>>>(x, hh, nullptr, lnf_g, lnf_b);
    gemm_h<1, 1><<<dim3(Vz / 128, NTOK / 128), 256, GS11>>>(
        hh, nullptr, tokT, nullptr, out, nullptr, nullptr,
        NTOK, Vz, Cz, Vz, nullptr, nullptr, 0);
}

// round 13
// speedup vs baseline: 4.0335x; 1.0125x over previous
#include <cuda_runtime.h>
#include <cuda_fp16.h>
#include <cstdint>
#include <math.h>

// Problem constants
#define Bz   2
#define Tz   1024
#define Cz   1024
#define Hz   16
#define Lz   8
#define Dz   64
#define HIDz 4096
#define Vz   32000
#define NTOK (Bz * Tz)          // 2048
#define EPSz 1e-5f

// ---------------------------------------------------------------------------
// PTX helpers (base ISA only)
// ---------------------------------------------------------------------------
__device__ __forceinline__ uint32_t smem_u32(const void* p) {
    uint32_t a;
    asm("{ .reg .u64 t; cvta.to.shared.u64 t, %1; cvt.u32.u64 %0, t; }"
        : "=r"(a) : "l"(p));
    return a;
}
__device__ __forceinline__ void ldsm_x4(uint32_t* r, uint32_t addr) {
    asm volatile("ldmatrix.sync.aligned.m8n8.x4.shared.b16 {%0,%1,%2,%3}, [%4];"
        : "=r"(r[0]), "=r"(r[1]), "=r"(r[2]), "=r"(r[3]) : "r"(addr));
}
__device__ __forceinline__ void ldsm_x4t(uint32_t* r, uint32_t addr) {
    asm volatile("ldmatrix.sync.aligned.m8n8.x4.trans.shared.b16 {%0,%1,%2,%3}, [%4];"
        : "=r"(r[0]), "=r"(r[1]), "=r"(r[2]), "=r"(r[3]) : "r"(addr));
}
__device__ __forceinline__ void mma_f16(float* d, const uint32_t* a, const uint32_t* b) {
    asm volatile("mma.sync.aligned.m16n8k16.row.col.f32.f16.f16.f32 "
        "{%0,%1,%2,%3}, {%4,%5,%6,%7}, {%8,%9}, {%0,%1,%2,%3};"
        : "+f"(d[0]), "+f"(d[1]), "+f"(d[2]), "+f"(d[3])
        : "r"(a[0]), "r"(a[1]), "r"(a[2]), "r"(a[3]), "r"(b[0]), "r"(b[1]));
}
__device__ __forceinline__ void cp16(uint32_t saddr, const void* gaddr) {
    asm volatile("cp.async.ca.shared.global [%0], [%1], 16;"
                 :: "r"(saddr), "l"(gaddr) : "memory");
}
#define CP_COMMIT() asm volatile("cp.async.commit_group;" ::: "memory")
#define CP_WAIT1()  asm volatile("cp.async.wait_group 1;" ::: "memory")
#define CP_WAIT0()  asm volatile("cp.async.wait_group 0;" ::: "memory")

__device__ __forceinline__ uint32_t packh(float x, float y) {
    __half2 t;
    t.x = __float2half(x);
    t.y = __float2half(y);
    return *(uint32_t*)&t;
}

// ---------------------------------------------------------------------------
// Scratch (device globals)
// ---------------------------------------------------------------------------
__device__ float g_x[NTOK * Cz];                 // residual stream
__device__ __half g_hh  [NTOK * Cz];
__device__ __half g_hl  [NTOK * Cz];
__device__ __half g_qkvh[NTOK * 3 * Cz];
__device__ __half g_qkvl[NTOK * 3 * Cz];
__device__ __half g_atth[NTOK * Cz];
__device__ __half g_attl[NTOK * Cz];
__device__ __half g_ffnh[NTOK * HIDz];

// Weights, transposed to [N,K]. qkv = fp16 pair; rest = single fp16.
__device__ __half g_qkvT_h[Lz * 3 * Cz * Cz];
__device__ __half g_qkvT_l[Lz * 3 * Cz * Cz];
__device__ __half g_projT[Lz * Cz * Cz];
__device__ __half g_fc1T [Lz * HIDz * Cz];
__device__ __half g_fc2T [Lz * Cz * HIDz];
__device__ __half g_tokT [Vz * Cz];

// ---------------------------------------------------------------------------
// Weight prep (coalesced transpose, half2 writes)
// ---------------------------------------------------------------------------
__global__ void wtrans_pair(const float* __restrict__ W,
                            __half* __restrict__ Th, __half* __restrict__ Tl,
                            int K, int N) {
    __shared__ float t[64][33];
    const float* Wl = W + (size_t)blockIdx.z * K * N;
    __half* Thg = Th + (size_t)blockIdx.z * K * N;
    __half* Tlg = Tl + (size_t)blockIdx.z * K * N;
    int n0 = blockIdx.x * 32, k0 = blockIdx.y * 64;
    int tx = threadIdx.x, ty = threadIdx.y;
#pragma unroll
    for (int j = 0; j < 64; j += 8)
        t[ty + j][tx] = Wl[(size_t)(k0 + ty + j) * N + n0 + tx];
    __syncthreads();
#pragma unroll
    for (int p = 0; p < 4; p++) {
        int nloc = p * 8 + ty;
        float v0 = t[2 * tx][nloc], v1 = t[2 * tx + 1][nloc];
        __half2 h2, l2;
        h2.x = __float2half(v0);
        h2.y = __float2half(v1);
        l2.x = __float2half(v0 - __half2float(h2.x));
        l2.y = __float2half(v1 - __half2float(h2.y));
        size_t o = (size_t)(n0 + nloc) * K + k0 + 2 * tx;
        *(__half2*)(Thg + o) = h2;
        *(__half2*)(Tlg + o) = l2;
    }
}

__global__ void wtrans_one(const float* __restrict__ W,
                           __half* __restrict__ T, int K, int N) {
    __shared__ float t[64][33];
    const float* Wl = W + (size_t)blockIdx.z * K * N;
    __half* Tg = T + (size_t)blockIdx.z * K * N;
    int n0 = blockIdx.x * 32, k0 = blockIdx.y * 64;
    int tx = threadIdx.x, ty = threadIdx.y;
#pragma unroll
    for (int j = 0; j < 64; j += 8)
        t[ty + j][tx] = Wl[(size_t)(k0 + ty + j) * N + n0 + tx];
    __syncthreads();
#pragma unroll
    for (int p = 0; p < 4; p++) {
        int nloc = p * 8 + ty;
        __half2 h2;
        h2.x = __float2half(t[2 * tx][nloc]);
        h2.y = __float2half(t[2 * tx + 1][nloc]);
        *(__half2*)(Tg + (size_t)(n0 + nloc) * K + k0 + 2 * tx) = h2;
    }
}

__global__ void wsplit_one(const float* __restrict__ W, __half* __restrict__ T, int n) {
    int i = blockIdx.x * blockDim.x + threadIdx.x;
    if (i < n) T[i] = __float2half(W[i]);
}

// ---------------------------------------------------------------------------
// gemm_body<NA,NB>: fp16 mma GEMM core (device function).
// Block 128x128, 8 warps (64x32), BK=32, NSTG=3 cp.async pipeline.
// ---------------------------------------------------------------------------
#define HPITCH 80

template <int NA, int NB>
__device__ __forceinline__ void gemm_body(
    const __half* __restrict__ Ah, const __half* __restrict__ Al,
    const __half* __restrict__ Bh, const __half* __restrict__ Bl,
    float* __restrict__ Cf, __half* __restrict__ Ch, __half* __restrict__ Cl,
    int N, int K, int ldc,
    const float* __restrict__ bias, const float* __restrict__ res,
    int gelu, int m0, int n0, char* smem) {
    constexpr int STG = (NA + NB) * 10240;
    constexpr int O_AH = 0;
    constexpr int O_AL = 10240;
    constexpr int O_BH = NA * 10240;
    constexpr int O_BL = O_BH + 10240;
    uint32_t sb = smem_u32(smem);
    int tid = threadIdx.x, wid = tid >> 5, lane = tid & 31;
    int wm = wid & 1, wn = wid >> 1;

    const __half* Agh = Ah + (size_t)m0 * K;
    const __half* Agl = (NA == 2) ? (Al + (size_t)m0 * K) : nullptr;
    const __half* Bgh = Bh + (size_t)n0 * K;
    const __half* Bgl = (NB == 2) ? (Bl + (size_t)n0 * K) : nullptr;

    float acc[4][4][4];
#pragma unroll
    for (int i = 0; i < 4; i++)
#pragma unroll
        for (int j = 0; j < 4; j++)
#pragma unroll
            for (int r = 0; r < 4; r++) acc[i][j][r] = 0.f;

    const int NC = K >> 5;

#define ISSUE_H(c)                                                             \
    {                                                                          \
        uint32_t s0 = sb + ((c) % 3) * STG;                                    \
        _Pragma("unroll")                                                      \
        for (int it = 0; it < 2; it++) {                                       \
            int i = it * 256 + tid;                                            \
            int row = i >> 2, seg = i & 3;                                     \
            uint32_t so = row * HPITCH + seg * 16;                             \
            size_t go = (size_t)row * K + (size_t)(c) * 32 + seg * 8;          \
            cp16(s0 + O_AH + so, Agh + go);                                    \
            if (NA == 2) cp16(s0 + O_AL + so, Agl + go);                       \
            cp16(s0 + O_BH + so, Bgh + go);                                    \
            if (NB == 2) cp16(s0 + O_BL + so, Bgl + go);                       \
        }                                                                      \
        CP_COMMIT();                                                           \
    }

    ISSUE_H(0);
    ISSUE_H(1);

    int r16 = lane & 15, hsel = lane >> 4;
    int bg = lane >> 3;
    int browoff = ((bg & 2) << 2) + (lane & 7);
    int bkoff = (bg & 1) * 8;

    for (int c = 0; c < NC; c++) {
        if (c + 1 < NC) { CP_WAIT1(); } else { CP_WAIT0(); }
        __syncthreads();
        if (c + 2 < NC) ISSUE_H(c + 2);
        uint32_t base = sb + (c % 3) * STG;
#pragma unroll
        for (int kk = 0; kk < 32; kk += 16) {
            uint32_t ah[16], al[16], bh[8], bl[8];
#pragma unroll
            for (int mt = 0; mt < 4; mt++) {
                uint32_t ad = (uint32_t)((wm * 64 + mt * 16 + r16) * HPITCH +
                                         (kk + hsel * 8) * 2);
                ldsm_x4(ah + 4 * mt, base + O_AH + ad);
                if (NA == 2) ldsm_x4(al + 4 * mt, base + O_AL + ad);
            }
#pragma unroll
            for (int ntp = 0; ntp < 2; ntp++) {
                uint32_t bd = (uint32_t)((wn * 32 + ntp * 16 + browoff) * HPITCH +
                                         (kk + bkoff) * 2);
                ldsm_x4(bh + 4 * ntp, base + O_BH + bd);
                if (NB == 2) ldsm_x4(bl + 4 * ntp, base + O_BL + bd);
            }
#pragma unroll
            for (int mt = 0; mt < 4; mt++)
#pragma unroll
                for (int nt = 0; nt < 4; nt++) {
                    uint32_t* bp = bh + (nt >> 1) * 4 + (nt & 1) * 2;
                    mma_f16(acc[mt][nt], ah + 4 * mt, bp);
                    if (NA == 2) mma_f16(acc[mt][nt], al + 4 * mt, bp);
                    if (NB == 2) {
                        uint32_t* bp2 = bl + (nt >> 1) * 4 + (nt & 1) * 2;
                        mma_f16(acc[mt][nt], ah + 4 * mt, bp2);
                    }
                }
        }
        __syncthreads();
    }
#undef ISSUE_H

    int gid = lane >> 2, qid = lane & 3;
#pragma unroll
    for (int mt = 0; mt < 4; mt++) {
#pragma unroll
        for (int nt = 0; nt < 4; nt++) {
            int n = n0 + wn * 32 + nt * 8 + 2 * qid;
            float bsum0 = bias ? bias[n] : 0.f;
            float bsum1 = bias ? bias[n + 1] : 0.f;
#pragma unroll
            for (int half = 0; half < 2; half++) {
                int m = m0 + wm * 64 + mt * 16 + gid + half * 8;
                float v0 = acc[mt][nt][half * 2 + 0] + bsum0;
                float v1 = acc[mt][nt][half * 2 + 1] + bsum1;
                if (gelu) {
                    v0 = 0.5f * v0 * (1.f + erff(v0 * 0.70710678118654752f));
                    v1 = 0.5f * v1 * (1.f + erff(v1 * 0.70710678118654752f));
                }
                if (res) {
                    const float* rr = res + (size_t)m * ldc + n;
                    v0 += rr[0];
                    v1 += rr[1];
                }
                if (Cf) {
                    float2 o;
                    o.x = v0; o.y = v1;
                    *(float2*)(Cf + (size_t)m * ldc + n) = o;
                }
                if (Ch) {
                    __half2 oh;
                    oh.x = __float2half(v0);
                    oh.y = __float2half(v1);
                    *(__half2*)(Ch + (size_t)m * ldc + n) = oh;
                    if (Cl) {
                        __half2 ol;
                        ol.x = __float2half(v0 - __half2float(oh.x));
                        ol.y = __float2half(v1 - __half2float(oh.y));
                        *(__half2*)(Cl + (size_t)m * ldc + n) = ol;
                    }
                }
            }
        }
    }
}

// Generic standalone GEMM
template <int NA, int NB>
__global__ __launch_bounds__(256)
void gemm_h(const __half* __restrict__ Ah, const __half* __restrict__ Al,
            const __half* __restrict__ Bh, const __half* __restrict__ Bl,
            float* __restrict__ Cf,
            __half* __restrict__ Ch, __half* __restrict__ Cl,
            int N, int K, int ldc,
            const float* __restrict__ bias, const float* __restrict__ res,
            int gelu) {
    extern __shared__ __align__(128) char smem[];
    gemm_body<NA, NB>(Ah, Al, Bh, Bl, Cf, Ch, Cl, N, K, ldc, bias, res, gelu,
                      blockIdx.y * 128, blockIdx.x * 128, smem);
}

// Fused qkv: blockIdx.x < 16 -> q,k (3-pass); else -> v (2-pass).
// Output is the interleaved qkv buffer with row stride 3*Cz.
__global__ __launch_bounds__(256)
void gemm_qkv(const __half* __restrict__ hh, const __half* __restrict__ hl,
              const __half* __restrict__ qkwh, const __half* __restrict__ qkwl,
              const __half* __restrict__ vwh,
              __half* __restrict__ qkvh, __half* __restrict__ qkvl) {
    extern __shared__ __align__(128) char smem[];
    int m0 = blockIdx.y * 128;
    if (blockIdx.x < 16) {
        gemm_body<2, 2>(hh, hl, qkwh, qkwl, nullptr, qkvh, qkvl,
                        2 * Cz, Cz, 3 * Cz, nullptr, nullptr, 0,
                        m0, blockIdx.x * 128, smem);
    } else {
        gemm_body<2, 1>(hh, hl, vwh, nullptr, nullptr,
                        qkvh + 2 * Cz, qkvl + 2 * Cz,
                        Cz, Cz, 3 * Cz, nullptr, nullptr, 0,
                        m0, (blockIdx.x - 16) * 128, smem);
    }
}

// ---------------------------------------------------------------------------
// MMA flash attention (R5-validated structure, fp16 types)
// ---------------------------------------------------------------------------
#define APITCH  144
#define AT_TILE 9216
#define AT_Q    0
#define AT_KV0  (2 * AT_TILE)
#define AT_KVS  (4 * AT_TILE)
#define AT_SMEM (AT_KV0 + 2 * AT_KVS)

__global__ __launch_bounds__(128)
void attn_mma(const __half* __restrict__ qkvh,
              const __half* __restrict__ qkvl,
              __half* __restrict__ oh,
              __half* __restrict__ ol) {
    extern __shared__ __align__(128) char smem[];
    uint32_t sb = smem_u32(smem);
    int tid = threadIdx.x, w = tid >> 5, lane = tid & 31;
    int qi = (int)gridDim.x - 1 - (int)blockIdx.x;
    int bh = blockIdx.y;
    int b = bh >> 4, h = bh & 15;
    const int RS = 3 * Cz;
    const size_t tokbase = (size_t)(b * Tz) * RS + h * Dz;

    int gid = lane >> 2, qid = lane & 3;
    int r16 = lane & 15, hsel = lane >> 4;
    int bg = lane >> 3;
    int browoff = ((bg & 2) << 2) + (lane & 7);
    int bkoff = (bg & 1) * 8;
    int t_row = (bg & 1) * 8 + (lane & 7);
    int t_col = (bg >> 1) * 8;

#define ISSUE_KV(kt)                                                           \
    {                                                                          \
        uint32_t s0 = sb + AT_KV0 + ((kt) & 1) * AT_KVS;                       \
        const __half* srcs[4] = {                                              \
            qkvh + tokbase + Cz, qkvl + tokbase + Cz,                          \
            qkvh + tokbase + 2 * Cz, qkvl + tokbase + 2 * Cz };                \
        _Pragma("unroll")                                                      \
        for (int t = 0; t < 4; t++) {                                          \
            _Pragma("unroll")                                                  \
            for (int it = 0; it < 4; it++) {                                   \
                int i = it * 128 + tid;                                        \
                int r = i >> 3, s = i & 7;                                     \
                cp16(s0 + t * AT_TILE + r * APITCH + s * 16,                   \
                     srcs[t] + (size_t)((kt) * 64 + r) * RS + s * 8);          \
            }                                                                  \
        }                                                                      \
        CP_COMMIT();                                                           \
    }

    {
#pragma unroll
        for (int t = 0; t < 2; t++) {
            const __half* src = (t ? qkvl : qkvh) + tokbase;
            uint32_t dst = sb + AT_Q + t * AT_TILE;
#pragma unroll
            for (int it = 0; it < 4; it++) {
                int i = it * 128 + tid;
                int r = i >> 3, s = i & 7;
                cp16(dst + r * APITCH + s * 16,
                     src + (size_t)(qi * 64 + r) * RS + s * 8);
            }
        }
        uint32_t s0 = sb + AT_KV0;
        const __half* srcs[4] = {
            qkvh + tokbase + Cz, qkvl + tokbase + Cz,
            qkvh + tokbase + 2 * Cz, qkvl + tokbase + 2 * Cz };
#pragma unroll
        for (int t = 0; t < 4; t++) {
#pragma unroll
            for (int it = 0; it < 4; it++) {
                int i = it * 128 + tid;
                int r = i >> 3, s = i & 7;
                cp16(s0 + t * AT_TILE + r * APITCH + s * 16,
                     srcs[t] + (size_t)r * RS + s * 8);
            }
        }
        CP_COMMIT();
    }
    if (qi >= 1) ISSUE_KV(1);

    if (qi >= 1) { CP_WAIT1(); } else { CP_WAIT0(); }
    __syncthreads();

    uint32_t qfh[4][4], qfl[4][4];
#pragma unroll
    for (int kk = 0; kk < 4; kk++) {
        uint32_t ad = sb + AT_Q + (uint32_t)((w * 16 + r16) * APITCH +
                                             (kk * 16 + hsel * 8) * 2);
        ldsm_x4(qfh[kk], ad);
        ldsm_x4(qfl[kk], ad + AT_TILE);
    }

    float oacc[8][4];
#pragma unroll
    for (int i = 0; i < 8; i++)
#pragma unroll
        for (int j = 0; j < 4; j++) oacc[i][j] = 0.f;
    float mrow[2] = {-1e30f, -1e30f};
    float lrow[2] = {0.f, 0.f};

    for (int kt = 0; kt <= qi; kt++) {
        if (kt > 0) {
            if (kt < qi) { CP_WAIT1(); } else { CP_WAIT0(); }
            __syncthreads();
        }
        uint32_t kb = sb + AT_KV0 + (kt & 1) * AT_KVS;

        float s[8][4];
#pragma unroll
        for (int i = 0; i < 8; i++)
#pragma unroll
            for (int j = 0; j < 4; j++) s[i][j] = 0.f;
#pragma unroll
        for (int kk = 0; kk < 4; kk++) {
            uint32_t kh[16], kl[16];
#pragma unroll
            for (int np = 0; np < 4; np++) {
                uint32_t ad = kb + (uint32_t)((np * 16 + browoff) * APITCH +
                                              (kk * 16 + bkoff) * 2);
                ldsm_x4(kh + 4 * np, ad);
                ldsm_x4(kl + 4 * np, ad + AT_TILE);
            }
#pragma unroll
            for (int nt = 0; nt < 8; nt++) {
                uint32_t* bp = kh + (nt >> 1) * 4 + (nt & 1) * 2;
                uint32_t* bl2 = kl + (nt >> 1) * 4 + (nt & 1) * 2;
                mma_f16(s[nt], qfh[kk], bp);
                mma_f16(s[nt], qfh[kk], bl2);
                mma_f16(s[nt], qfl[kk], bp);
            }
        }
#pragma unroll
        for (int nt = 0; nt < 8; nt++)
#pragma unroll
            for (int j = 0; j < 4; j++) s[nt][j] *= 0.125f;
        if (kt == qi) {
#pragma unroll
            for (int nt = 0; nt < 8; nt++)
#pragma unroll
                for (int j = 0; j < 4; j++) {
                    int kc = 8 * nt + 2 * qid + (j & 1);
                    int qr = w * 16 + gid + (j >> 1) * 8;
                    if (kc > qr) s[nt][j] = -1e30f;
                }
        }
        float mt0 = -1e30f, mt1 = -1e30f;
#pragma unroll
        for (int nt = 0; nt < 8; nt++) {
            mt0 = fmaxf(mt0, fmaxf(s[nt][0], s[nt][1]));
            mt1 = fmaxf(mt1, fmaxf(s[nt][2], s[nt][3]));
        }
        mt0 = fmaxf(mt0, __shfl_xor_sync(0xffffffffu, mt0, 1));
        mt0 = fmaxf(mt0, __shfl_xor_sync(0xffffffffu, mt0, 2));
        mt1 = fmaxf(mt1, __shfl_xor_sync(0xffffffffu, mt1, 1));
        mt1 = fmaxf(mt1, __shfl_xor_sync(0xffffffffu, mt1, 2));
        float mn0 = fmaxf(mrow[0], mt0), mn1 = fmaxf(mrow[1], mt1);
        float c0 = __expf(mrow[0] - mn0), c1 = __expf(mrow[1] - mn1);
        mrow[0] = mn0; mrow[1] = mn1;
        float rs0 = 0.f, rs1 = 0.f;
#pragma unroll
        for (int nt = 0; nt < 8; nt++) {
            s[nt][0] = __expf(s[nt][0] - mn0);
            s[nt][1] = __expf(s[nt][1] - mn0);
            s[nt][2] = __expf(s[nt][2] - mn1);
            s[nt][3] = __expf(s[nt][3] - mn1);
            rs0 += s[nt][0] + s[nt][1];
            rs1 += s[nt][2] + s[nt][3];
        }
        rs0 += __shfl_xor_sync(0xffffffffu, rs0, 1);
        rs0 += __shfl_xor_sync(0xffffffffu, rs0, 2);
        rs1 += __shfl_xor_sync(0xffffffffu, rs1, 1);
        rs1 += __shfl_xor_sync(0xffffffffu, rs1, 2);
        lrow[0] = lrow[0] * c0 + rs0;
        lrow[1] = lrow[1] * c1 + rs1;
#pragma unroll
        for (int nt = 0; nt < 8; nt++) {
            oacc[nt][0] *= c0; oacc[nt][1] *= c0;
            oacc[nt][2] *= c1; oacc[nt][3] *= c1;
        }
#pragma unroll
        for (int k2 = 0; k2 < 4; k2++) {
            uint32_t pah[4], pal[4];
            {
                float p00 = s[2 * k2][0],     p01 = s[2 * k2][1];
                float p10 = s[2 * k2][2],     p11 = s[2 * k2][3];
                float p20 = s[2 * k2 + 1][0], p21 = s[2 * k2 + 1][1];
                float p30 = s[2 * k2 + 1][2], p31 = s[2 * k2 + 1][3];
                pah[0] = packh(p00, p01);
                pah[1] = packh(p10, p11);
                pah[2] = packh(p20, p21);
                pah[3] = packh(p30, p31);
                __half2* hp;
                hp = (__half2*)&pah[0];
                pal[0] = packh(p00 - __half2float(hp->x), p01 - __half2float(hp->y));
                hp = (__half2*)&pah[1];
                pal[1] = packh(p10 - __half2float(hp->x), p11 - __half2float(hp->y));
                hp = (__half2*)&pah[2];
                pal[2] = packh(p20 - __half2float(hp->x), p21 - __half2float(hp->y));
                hp = (__half2*)&pah[3];
                pal[3] = packh(p30 - __half2float(hp->x), p31 - __half2float(hp->y));
            }
            uint32_t vh[16], vl[16];
#pragma unroll
            for (int np = 0; np < 4; np++) {
                uint32_t ad = kb + 2 * AT_TILE +
                              (uint32_t)((k2 * 16 + t_row) * APITCH +
                                         (np * 16 + t_col) * 2);
                ldsm_x4t(vh + 4 * np, ad);
                ldsm_x4t(vl + 4 * np, ad + AT_TILE);
            }
#pragma unroll
            for (int nt = 0; nt < 8; nt++) {
                uint32_t* bp = vh + (nt >> 1) * 4 + (nt & 1) * 2;
                uint32_t* bl2 = vl + (nt >> 1) * 4 + (nt & 1) * 2;
                mma_f16(oacc[nt], pah, bp);
                mma_f16(oacc[nt], pah, bl2);
                mma_f16(oacc[nt], pal, bp);
            }
        }
        __syncthreads();
        if (kt + 2 <= qi) ISSUE_KV(kt + 2);
    }
#undef ISSUE_KV

    float inv0 = 1.f / lrow[0], inv1 = 1.f / lrow[1];
    int tok0 = b * Tz + qi * 64 + w * 16 + gid;
#pragma unroll
    for (int nt = 0; nt < 8; nt++) {
        int col = h * Dz + 8 * nt + 2 * qid;
        float v0 = oacc[nt][0] * inv0, v1 = oacc[nt][1] * inv0;
        float v2 = oacc[nt][2] * inv1, v3 = oacc[nt][3] * inv1;
        __half2 ph, pl;
        ph.x = __float2half(v0); ph.y = __float2half(v1);
        pl.x = __float2half(v0 - __half2float(ph.x));
        pl.y = __float2half(v1 - __half2float(ph.y));
        *(__half2*)(oh + (size_t)tok0 * Cz + col) = ph;
        *(__half2*)(ol + (size_t)tok0 * Cz + col) = pl;
        ph.x = __float2half(v2); ph.y = __float2half(v3);
        pl.x = __float2half(v2 - __half2float(ph.x));
        pl.y = __float2half(v3 - __half2float(ph.y));
        *(__half2*)(oh + (size_t)(tok0 + 8) * Cz + col) = ph;
        *(__half2*)(ol + (size_t)(tok0 + 8) * Cz + col) = pl;
    }
}

// ---------------------------------------------------------------------------
// Embedding
// ---------------------------------------------------------------------------
__global__ void embed_kernel(const int* __restrict__ idx,
                             const float* __restrict__ tok,
                             const float* __restrict__ pos,
                             float* __restrict__ x) {
    int row = blockIdx.x;
    int t   = row & (Tz - 1);
    int tokid = idx[row];
    const float* te = tok + (size_t)tokid * Cz;
    const float* pe = pos + (size_t)t * Cz;
    float* xr = x + (size_t)row * Cz;
    for (int i = threadIdx.x; i < Cz; i += blockDim.x)
        xr[i] = te[i] + pe[i];
}

// ---------------------------------------------------------------------------
// LayerNorm per row, writes fp16 hi/lo pair (lo optional)
// ---------------------------------------------------------------------------
__global__ void ln_kernel(const float* __restrict__ x,
                          __half* __restrict__ yh, __half* __restrict__ yl,
                          const float* __restrict__ g, const float* __restrict__ b) {
    int row = blockIdx.x;
    const float* xr = x + (size_t)row * Cz;
    float s = 0.f, s2 = 0.f;
    for (int i = threadIdx.x; i < Cz; i += blockDim.x) {
        float v = xr[i];
        s += v; s2 += v * v;
    }
    __shared__ float sh_s[8], sh_s2[8];
    for (int off = 16; off > 0; off >>= 1) {
        s  += __shfl_down_sync(0xffffffffu, s,  off);
        s2 += __shfl_down_sync(0xffffffffu, s2, off);
    }
    int lane = threadIdx.x & 31, wid = threadIdx.x >> 5;
    if (lane == 0) { sh_s[wid] = s; sh_s2[wid] = s2; }
    __syncthreads();
    if (wid == 0) {
        s  = (lane < 8) ? sh_s[lane]  : 0.f;
        s2 = (lane < 8) ? sh_s2[lane] : 0.f;
        for (int off = 4; off > 0; off >>= 1) {
            s  += __shfl_down_sync(0xffffffffu, s,  off);
            s2 += __shfl_down_sync(0xffffffffu, s2, off);
        }
        if (lane == 0) { sh_s[0] = s; sh_s2[0] = s2; }
    }
    __syncthreads();
    float mean = sh_s[0] * (1.f / Cz);
    float var  = sh_s2[0] * (1.f / Cz) - mean * mean;
    float rstd = rsqrtf(var + EPSz);
    __half* yhr = yh + (size_t)row * Cz;
    __half* ylr = yl ? (yl + (size_t)row * Cz) : nullptr;
    for (int i = threadIdx.x; i < Cz; i += blockDim.x) {
        float v = (xr[i] - mean) * rstd * g[i] + b[i];
        __half h = __float2half(v);
        yhr[i] = h;
        if (ylr) ylr[i] = __float2half(v - __half2float(h));
    }
}

// ---------------------------------------------------------------------------
// Launch
// ---------------------------------------------------------------------------
extern "C" void kernel_launch(void* const* d_in, const int* in_sizes, int n_in,
                              void* d_out, int out_size) {
    const int*   idx     = (const int*)  d_in[0];
    const float* tok_emb = (const float*)d_in[1];
    const float* pos_emb = (const float*)d_in[2];
    const float* qkv_w   = (const float*)d_in[3];
    const float* proj_w  = (const float*)d_in[4];
    const float* proj_b  = (const float*)d_in[5];
    const float* ln1_g   = (const float*)d_in[6];
    const float* ln1_b   = (const float*)d_in[7];
    const float* ln2_g   = (const float*)d_in[8];
    const float* ln2_b   = (const float*)d_in[9];
    const float* fc1_w   = (const float*)d_in[10];
    const float* fc1_b   = (const float*)d_in[11];
    const float* fc2_w   = (const float*)d_in[12];
    const float* fc2_b   = (const float*)d_in[13];
    const float* lnf_g   = (const float*)d_in[14];
    const float* lnf_b   = (const float*)d_in[15];
    float* out = (float*)d_out;

    float* x;
    cudaGetSymbolAddress((void**)&x, g_x);
    __half *hh, *hl, *qkvh, *qkvl, *atth, *attl, *ffnh;
    cudaGetSymbolAddress((void**)&hh,   g_hh);
    cudaGetSymbolAddress((void**)&hl,   g_hl);
    cudaGetSymbolAddress((void**)&qkvh, g_qkvh);
    cudaGetSymbolAddress((void**)&qkvl, g_qkvl);
    cudaGetSymbolAddress((void**)&atth, g_atth);
    cudaGetSymbolAddress((void**)&attl, g_attl);
    cudaGetSymbolAddress((void**)&ffnh, g_ffnh);
    __half *qkvTh, *qkvTl, *projT, *fc1T, *fc2T, *tokT;
    cudaGetSymbolAddress((void**)&qkvTh, g_qkvT_h);
    cudaGetSymbolAddress((void**)&qkvTl, g_qkvT_l);
    cudaGetSymbolAddress((void**)&projT, g_projT);
    cudaGetSymbolAddress((void**)&fc1T,  g_fc1T);
    cudaGetSymbolAddress((void**)&fc2T,  g_fc2T);
    cudaGetSymbolAddress((void**)&tokT,  g_tokT);

    const int GS11 = 3 * 20480;
    const int GS21 = 3 * 30720;
    const int GS22 = 3 * 40960;
    cudaFuncSetAttribute(gemm_h<1, 1>, cudaFuncAttributeMaxDynamicSharedMemorySize, GS11);
    cudaFuncSetAttribute(gemm_h<2, 1>, cudaFuncAttributeMaxDynamicSharedMemorySize, GS21);
    cudaFuncSetAttribute(gemm_qkv, cudaFuncAttributeMaxDynamicSharedMemorySize, GS22);
    cudaFuncSetAttribute(attn_mma, cudaFuncAttributeMaxDynamicSharedMemorySize, AT_SMEM);

    // ---- weight prep ----
    dim3 tb(32, 8);
    wtrans_pair<<<dim3(3 * Cz / 32, Cz / 64, Lz), tb>>>(qkv_w, qkvTh, qkvTl, Cz, 3 * Cz);
    wtrans_one<<<dim3(Cz / 32, Cz / 64, Lz), tb>>>(proj_w, projT, Cz, Cz);
    wtrans_one<<<dim3(HIDz / 32, Cz / 64, Lz), tb>>>(fc1_w, fc1T, Cz, HIDz);
    wtrans_one<<<dim3(Cz / 32, HIDz / 64, Lz), tb>>>(fc2_w, fc2T, HIDz, Cz);
    wsplit_one<<<(Vz * Cz + 255) / 256, 256>>>(tok_emb, tokT, Vz * Cz);

    embed_kernel<<<NTOK, 256>>>(idx, tok_emb, pos_emb, x);

    for (int l = 0; l < Lz; l++) {
        const __half* qwh = qkvTh + (size_t)l * 3 * Cz * Cz;
        const __half* qwl = qkvTl + (size_t)l * 3 * Cz * Cz;
        const __half* vwh = qwh + (size_t)2 * Cz * Cz;     // v rows [2048,3072)
        const __half* pw  = projT + (size_t)l * Cz * Cz;
        const __half* w1  = fc1T  + (size_t)l * Cz * HIDz;
        const __half* w2  = fc2T  + (size_t)l * Cz * HIDz;
        const float* pb = proj_b + (size_t)l * Cz;
        const float* b1 = fc1_b  + (size_t)l * HIDz;
        const float* b2 = fc2_b  + (size_t)l * Cz;

        ln_kernel<<<NTOK, 256>>>(x, hh, hl, ln1_g + l * Cz, ln1_b + l * Cz);
        gemm_qkv<<<dim3(24, NTOK / 128), 256, GS22>>>(
            hh, hl, qwh, qwl, vwh, qkvh, qkvl);
        attn_mma<<<dim3(Tz / 64, Bz * Hz), 128, AT_SMEM>>>(qkvh, qkvl, atth, attl);
        gemm_h<2, 1><<<dim3(Cz / 128, NTOK / 128), 256, GS21>>>(
            atth, attl, pw, nullptr, x, nullptr, nullptr,
            Cz, Cz, Cz, pb, x, 0);
        ln_kernel<<<NTOK, 256>>>(x, hh, nullptr, ln2_g + l * Cz, ln2_b + l * Cz);
        gemm_h<1, 1><<<dim3(HIDz / 128, NTOK / 128), 256, GS11>>>(
            hh, nullptr, w1, nullptr, nullptr, ffnh, nullptr,
            HIDz, Cz, HIDz, b1, nullptr, 1);
        gemm_h<1, 1><<<dim3(Cz / 128, NTOK / 128), 256, GS11>>>(
            ffnh, nullptr, w2, nullptr, x, nullptr, nullptr,
            Cz, HIDz, Cz, b2, x, 0);
    }

    ln_kernel<<<NTOK, 256>>>(x, hh, nullptr, lnf_g, lnf_b);
    gemm_h<1, 1><<<dim3(Vz / 128, NTOK / 128), 256, GS11>>>(
        hh, nullptr, tokT, nullptr, out, nullptr, nullptr,
        Vz, Cz, Vz, nullptr, nullptr, 0);
}

// round 14
// speedup vs baseline: 4.1143x; 1.0200x over previous
#include <cuda_runtime.h>
#include <cuda_fp16.h>
#include <cstdint>
#include <math.h>

// Problem constants
#define Bz   2
#define Tz   1024
#define Cz   1024
#define Hz   16
#define Lz   8
#define Dz   64
#define HIDz 4096
#define Vz   32000
#define NTOK (Bz * Tz)          // 2048
#define EPSz 1e-5f

// ---------------------------------------------------------------------------
// PTX helpers (base ISA only)
// ---------------------------------------------------------------------------
__device__ __forceinline__ uint32_t smem_u32(const void* p) {
    uint32_t a;
    asm("{ .reg .u64 t; cvta.to.shared.u64 t, %1; cvt.u32.u64 %0, t; }"
        : "=r"(a) : "l"(p));
    return a;
}
__device__ __forceinline__ void ldsm_x4(uint32_t* r, uint32_t addr) {
    asm volatile("ldmatrix.sync.aligned.m8n8.x4.shared.b16 {%0,%1,%2,%3}, [%4];"
        : "=r"(r[0]), "=r"(r[1]), "=r"(r[2]), "=r"(r[3]) : "r"(addr));
}
__device__ __forceinline__ void ldsm_x4t(uint32_t* r, uint32_t addr) {
    asm volatile("ldmatrix.sync.aligned.m8n8.x4.trans.shared.b16 {%0,%1,%2,%3}, [%4];"
        : "=r"(r[0]), "=r"(r[1]), "=r"(r[2]), "=r"(r[3]) : "r"(addr));
}
__device__ __forceinline__ void mma_f16(float* d, const uint32_t* a, const uint32_t* b) {
    asm volatile("mma.sync.aligned.m16n8k16.row.col.f32.f16.f16.f32 "
        "{%0,%1,%2,%3}, {%4,%5,%6,%7}, {%8,%9}, {%0,%1,%2,%3};"
        : "+f"(d[0]), "+f"(d[1]), "+f"(d[2]), "+f"(d[3])
        : "r"(a[0]), "r"(a[1]), "r"(a[2]), "r"(a[3]), "r"(b[0]), "r"(b[1]));
}
__device__ __forceinline__ void cp16(uint32_t saddr, const void* gaddr) {
    asm volatile("cp.async.ca.shared.global [%0], [%1], 16;"
                 :: "r"(saddr), "l"(gaddr) : "memory");
}
#define CP_COMMIT() asm volatile("cp.async.commit_group;" ::: "memory")
#define CP_WAIT1()  asm volatile("cp.async.wait_group 1;" ::: "memory")
#define CP_WAIT0()  asm volatile("cp.async.wait_group 0;" ::: "memory")

__device__ __forceinline__ uint32_t packh(float x, float y) {
    __half2 t;
    t.x = __float2half(x);
    t.y = __float2half(y);
    return *(uint32_t*)&t;
}

// ---------------------------------------------------------------------------
// Scratch (device globals)
// ---------------------------------------------------------------------------
__device__ float g_x[NTOK * Cz];                 // residual stream
__device__ __half g_hh  [NTOK * Cz];
__device__ __half g_hl  [NTOK * Cz];
__device__ __half g_qkvh[NTOK * 3 * Cz];
__device__ __half g_qkvl[NTOK * 3 * Cz];
__device__ __half g_atth[NTOK * Cz];
__device__ __half g_ffnh[NTOK * HIDz];

// Weights, transposed to [N,K]. qkv = fp16 pair; rest = single fp16.
__device__ __half g_qkvT_h[Lz * 3 * Cz * Cz];
__device__ __half g_qkvT_l[Lz * 3 * Cz * Cz];
__device__ __half g_projT[Lz * Cz * Cz];
__device__ __half g_fc1T [Lz * HIDz * Cz];
__device__ __half g_fc2T [Lz * Cz * HIDz];
__device__ __half g_tokT [Vz * Cz];

// ---------------------------------------------------------------------------
// Weight prep (coalesced transpose, half2 writes)
// ---------------------------------------------------------------------------
__global__ void wtrans_pair(const float* __restrict__ W,
                            __half* __restrict__ Th, __half* __restrict__ Tl,
                            int K, int N) {
    __shared__ float t[64][33];
    const float* Wl = W + (size_t)blockIdx.z * K * N;
    __half* Thg = Th + (size_t)blockIdx.z * K * N;
    __half* Tlg = Tl + (size_t)blockIdx.z * K * N;
    int n0 = blockIdx.x * 32, k0 = blockIdx.y * 64;
    int tx = threadIdx.x, ty = threadIdx.y;
#pragma unroll
    for (int j = 0; j < 64; j += 8)
        t[ty + j][tx] = Wl[(size_t)(k0 + ty + j) * N + n0 + tx];
    __syncthreads();
#pragma unroll
    for (int p = 0; p < 4; p++) {
        int nloc = p * 8 + ty;
        float v0 = t[2 * tx][nloc], v1 = t[2 * tx + 1][nloc];
        __half2 h2, l2;
        h2.x = __float2half(v0);
        h2.y = __float2half(v1);
        l2.x = __float2half(v0 - __half2float(h2.x));
        l2.y = __float2half(v1 - __half2float(h2.y));
        size_t o = (size_t)(n0 + nloc) * K + k0 + 2 * tx;
        *(__half2*)(Thg + o) = h2;
        *(__half2*)(Tlg + o) = l2;
    }
}

__global__ void wtrans_one(const float* __restrict__ W,
                           __half* __restrict__ T, int K, int N) {
    __shared__ float t[64][33];
    const float* Wl = W + (size_t)blockIdx.z * K * N;
    __half* Tg = T + (size_t)blockIdx.z * K * N;
    int n0 = blockIdx.x * 32, k0 = blockIdx.y * 64;
    int tx = threadIdx.x, ty = threadIdx.y;
#pragma unroll
    for (int j = 0; j < 64; j += 8)
        t[ty + j][tx] = Wl[(size_t)(k0 + ty + j) * N + n0 + tx];
    __syncthreads();
#pragma unroll
    for (int p = 0; p < 4; p++) {
        int nloc = p * 8 + ty;
        __half2 h2;
        h2.x = __float2half(t[2 * tx][nloc]);
        h2.y = __float2half(t[2 * tx + 1][nloc]);
        *(__half2*)(Tg + (size_t)(n0 + nloc) * K + k0 + 2 * tx) = h2;
    }
}

__global__ void wsplit_one(const float* __restrict__ W, __half* __restrict__ T, int n) {
    int i = blockIdx.x * blockDim.x + threadIdx.x;
    if (i < n) T[i] = __float2half(W[i]);
}

// ---------------------------------------------------------------------------
// gemm_body<NA,NB>: fp16 mma GEMM core (device function).
// Block 128x128, 8 warps (64x32), BK=32, NSTG=3 cp.async pipeline.
// ---------------------------------------------------------------------------
#define HPITCH 80

template <int NA, int NB>
__device__ __forceinline__ void gemm_body(
    const __half* __restrict__ Ah, const __half* __restrict__ Al,
    const __half* __restrict__ Bh, const __half* __restrict__ Bl,
    float* __restrict__ Cf, __half* __restrict__ Ch, __half* __restrict__ Cl,
    int N, int K, int ldc,
    const float* __restrict__ bias, const float* __restrict__ res,
    int gelu, int m0, int n0, char* smem) {
    constexpr int STG = (NA + NB) * 10240;
    constexpr int O_AH = 0;
    constexpr int O_AL = 10240;
    constexpr int O_BH = NA * 10240;
    constexpr int O_BL = O_BH + 10240;
    uint32_t sb = smem_u32(smem);
    int tid = threadIdx.x, wid = tid >> 5, lane = tid & 31;
    int wm = wid & 1, wn = wid >> 1;

    const __half* Agh = Ah + (size_t)m0 * K;
    const __half* Agl = (NA == 2) ? (Al + (size_t)m0 * K) : nullptr;
    const __half* Bgh = Bh + (size_t)n0 * K;
    const __half* Bgl = (NB == 2) ? (Bl + (size_t)n0 * K) : nullptr;

    float acc[4][4][4];
#pragma unroll
    for (int i = 0; i < 4; i++)
#pragma unroll
        for (int j = 0; j < 4; j++)
#pragma unroll
            for (int r = 0; r < 4; r++) acc[i][j][r] = 0.f;

    const int NC = K >> 5;

#define ISSUE_H(c)                                                             \
    {                                                                          \
        uint32_t s0 = sb + ((c) % 3) * STG;                                    \
        _Pragma("unroll")                                                      \
        for (int it = 0; it < 2; it++) {                                       \
            int i = it * 256 + tid;                                            \
            int row = i >> 2, seg = i & 3;                                     \
            uint32_t so = row * HPITCH + seg * 16;                             \
            size_t go = (size_t)row * K + (size_t)(c) * 32 + seg * 8;          \
            cp16(s0 + O_AH + so, Agh + go);                                    \
            if (NA == 2) cp16(s0 + O_AL + so, Agl + go);                       \
            cp16(s0 + O_BH + so, Bgh + go);                                    \
            if (NB == 2) cp16(s0 + O_BL + so, Bgl + go);                       \
        }                                                                      \
        CP_COMMIT();                                                           \
    }

    ISSUE_H(0);
    ISSUE_H(1);

    int r16 = lane & 15, hsel = lane >> 4;
    int bg = lane >> 3;
    int browoff = ((bg & 2) << 2) + (lane & 7);
    int bkoff = (bg & 1) * 8;

    for (int c = 0; c < NC; c++) {
        if (c + 1 < NC) { CP_WAIT1(); } else { CP_WAIT0(); }
        __syncthreads();
        if (c + 2 < NC) ISSUE_H(c + 2);
        uint32_t base = sb + (c % 3) * STG;
#pragma unroll
        for (int kk = 0; kk < 32; kk += 16) {
            uint32_t ah[16], al[16], bh[8], bl[8];
#pragma unroll
            for (int mt = 0; mt < 4; mt++) {
                uint32_t ad = (uint32_t)((wm * 64 + mt * 16 + r16) * HPITCH +
                                         (kk + hsel * 8) * 2);
                ldsm_x4(ah + 4 * mt, base + O_AH + ad);
                if (NA == 2) ldsm_x4(al + 4 * mt, base + O_AL + ad);
            }
#pragma unroll
            for (int ntp = 0; ntp < 2; ntp++) {
                uint32_t bd = (uint32_t)((wn * 32 + ntp * 16 + browoff) * HPITCH +
                                         (kk + bkoff) * 2);
                ldsm_x4(bh + 4 * ntp, base + O_BH + bd);
                if (NB == 2) ldsm_x4(bl + 4 * ntp, base + O_BL + bd);
            }
#pragma unroll
            for (int mt = 0; mt < 4; mt++)
#pragma unroll
                for (int nt = 0; nt < 4; nt++) {
                    uint32_t* bp = bh + (nt >> 1) * 4 + (nt & 1) * 2;
                    mma_f16(acc[mt][nt], ah + 4 * mt, bp);
                    if (NA == 2) mma_f16(acc[mt][nt], al + 4 * mt, bp);
                    if (NB == 2) {
                        uint32_t* bp2 = bl + (nt >> 1) * 4 + (nt & 1) * 2;
                        mma_f16(acc[mt][nt], ah + 4 * mt, bp2);
                    }
                }
        }
        __syncthreads();
    }
#undef ISSUE_H

    int gid = lane >> 2, qid = lane & 3;
#pragma unroll
    for (int mt = 0; mt < 4; mt++) {
#pragma unroll
        for (int nt = 0; nt < 4; nt++) {
            int n = n0 + wn * 32 + nt * 8 + 2 * qid;
            float bsum0 = bias ? bias[n] : 0.f;
            float bsum1 = bias ? bias[n + 1] : 0.f;
#pragma unroll
            for (int half = 0; half < 2; half++) {
                int m = m0 + wm * 64 + mt * 16 + gid + half * 8;
                float v0 = acc[mt][nt][half * 2 + 0] + bsum0;
                float v1 = acc[mt][nt][half * 2 + 1] + bsum1;
                if (gelu) {
                    v0 = 0.5f * v0 * (1.f + erff(v0 * 0.70710678118654752f));
                    v1 = 0.5f * v1 * (1.f + erff(v1 * 0.70710678118654752f));
                }
                if (res) {
                    const float* rr = res + (size_t)m * ldc + n;
                    v0 += rr[0];
                    v1 += rr[1];
                }
                if (Cf) {
                    float2 o;
                    o.x = v0; o.y = v1;
                    *(float2*)(Cf + (size_t)m * ldc + n) = o;
                }
                if (Ch) {
                    __half2 oh;
                    oh.x = __float2half(v0);
                    oh.y = __float2half(v1);
                    *(__half2*)(Ch + (size_t)m * ldc + n) = oh;
                    if (Cl) {
                        __half2 ol;
                        ol.x = __float2half(v0 - __half2float(oh.x));
                        ol.y = __float2half(v1 - __half2float(oh.y));
                        *(__half2*)(Cl + (size_t)m * ldc + n) = ol;
                    }
                }
            }
        }
    }
}

// Generic standalone GEMM
template <int NA, int NB>
__global__ __launch_bounds__(256)
void gemm_h(const __half* __restrict__ Ah, const __half* __restrict__ Al,
            const __half* __restrict__ Bh, const __half* __restrict__ Bl,
            float* __restrict__ Cf,
            __half* __restrict__ Ch, __half* __restrict__ Cl,
            int N, int K, int ldc,
            const float* __restrict__ bias, const float* __restrict__ res,
            int gelu) {
    extern __shared__ __align__(128) char smem[];
    gemm_body<NA, NB>(Ah, Al, Bh, Bl, Cf, Ch, Cl, N, K, ldc, bias, res, gelu,
                      blockIdx.y * 128, blockIdx.x * 128, smem);
}

// Fused qkv: blockIdx.x < 16 -> q,k (3-pass); else -> v (2-pass).
__global__ __launch_bounds__(256)
void gemm_qkv(const __half* __restrict__ hh, const __half* __restrict__ hl,
              const __half* __restrict__ qkwh, const __half* __restrict__ qkwl,
              const __half* __restrict__ vwh,
              __half* __restrict__ qkvh, __half* __restrict__ qkvl) {
    extern __shared__ __align__(128) char smem[];
    int m0 = blockIdx.y * 128;
    if (blockIdx.x < 16) {
        gemm_body<2, 2>(hh, hl, qkwh, qkwl, nullptr, qkvh, qkvl,
                        2 * Cz, Cz, 3 * Cz, nullptr, nullptr, 0,
                        m0, blockIdx.x * 128, smem);
    } else {
        gemm_body<2, 1>(hh, hl, vwh, nullptr, nullptr,
                        qkvh + 2 * Cz, qkvl + 2 * Cz,
                        Cz, Cz, 3 * Cz, nullptr, nullptr, 0,
                        m0, (blockIdx.x - 16) * 128, smem);
    }
}

// ---------------------------------------------------------------------------
// MMA flash attention (R5-validated structure, fp16 types).
// Output: hi only (proj is now 1-pass on A side).
// ---------------------------------------------------------------------------
#define APITCH  144
#define AT_TILE 9216
#define AT_Q    0
#define AT_KV0  (2 * AT_TILE)
#define AT_KVS  (4 * AT_TILE)
#define AT_SMEM (AT_KV0 + 2 * AT_KVS)

__global__ __launch_bounds__(128)
void attn_mma(const __half* __restrict__ qkvh,
              const __half* __restrict__ qkvl,
              __half* __restrict__ oh) {
    extern __shared__ __align__(128) char smem[];
    uint32_t sb = smem_u32(smem);
    int tid = threadIdx.x, w = tid >> 5, lane = tid & 31;
    int qi = (int)gridDim.x - 1 - (int)blockIdx.x;
    int bh = blockIdx.y;
    int b = bh >> 4, h = bh & 15;
    const int RS = 3 * Cz;
    const size_t tokbase = (size_t)(b * Tz) * RS + h * Dz;

    int gid = lane >> 2, qid = lane & 3;
    int r16 = lane & 15, hsel = lane >> 4;
    int bg = lane >> 3;
    int browoff = ((bg & 2) << 2) + (lane & 7);
    int bkoff = (bg & 1) * 8;
    int t_row = (bg & 1) * 8 + (lane & 7);
    int t_col = (bg >> 1) * 8;

#define ISSUE_KV(kt)                                                           \
    {                                                                          \
        uint32_t s0 = sb + AT_KV0 + ((kt) & 1) * AT_KVS;                       \
        const __half* srcs[4] = {                                              \
            qkvh + tokbase + Cz, qkvl + tokbase + Cz,                          \
            qkvh + tokbase + 2 * Cz, qkvl + tokbase + 2 * Cz };                \
        _Pragma("unroll")                                                      \
        for (int t = 0; t < 4; t++) {                                          \
            _Pragma("unroll")                                                  \
            for (int it = 0; it < 4; it++) {                                   \
                int i = it * 128 + tid;                                        \
                int r = i >> 3, s = i & 7;                                     \
                cp16(s0 + t * AT_TILE + r * APITCH + s * 16,                   \
                     srcs[t] + (size_t)((kt) * 64 + r) * RS + s * 8);          \
            }                                                                  \
        }                                                                      \
        CP_COMMIT();                                                           \
    }

    {
#pragma unroll
        for (int t = 0; t < 2; t++) {
            const __half* src = (t ? qkvl : qkvh) + tokbase;
            uint32_t dst = sb + AT_Q + t * AT_TILE;
#pragma unroll
            for (int it = 0; it < 4; it++) {
                int i = it * 128 + tid;
                int r = i >> 3, s = i & 7;
                cp16(dst + r * APITCH + s * 16,
                     src + (size_t)(qi * 64 + r) * RS + s * 8);
            }
        }
        uint32_t s0 = sb + AT_KV0;
        const __half* srcs[4] = {
            qkvh + tokbase + Cz, qkvl + tokbase + Cz,
            qkvh + tokbase + 2 * Cz, qkvl + tokbase + 2 * Cz };
#pragma unroll
        for (int t = 0; t < 4; t++) {
#pragma unroll
            for (int it = 0; it < 4; it++) {
                int i = it * 128 + tid;
                int r = i >> 3, s = i & 7;
                cp16(s0 + t * AT_TILE + r * APITCH + s * 16,
                     srcs[t] + (size_t)r * RS + s * 8);
            }
        }
        CP_COMMIT();
    }
    if (qi >= 1) ISSUE_KV(1);

    if (qi >= 1) { CP_WAIT1(); } else { CP_WAIT0(); }
    __syncthreads();

    uint32_t qfh[4][4], qfl[4][4];
#pragma unroll
    for (int kk = 0; kk < 4; kk++) {
        uint32_t ad = sb + AT_Q + (uint32_t)((w * 16 + r16) * APITCH +
                                             (kk * 16 + hsel * 8) * 2);
        ldsm_x4(qfh[kk], ad);
        ldsm_x4(qfl[kk], ad + AT_TILE);
    }

    float oacc[8][4];
#pragma unroll
    for (int i = 0; i < 8; i++)
#pragma unroll
        for (int j = 0; j < 4; j++) oacc[i][j] = 0.f;
    float mrow[2] = {-1e30f, -1e30f};
    float lrow[2] = {0.f, 0.f};

    for (int kt = 0; kt <= qi; kt++) {
        if (kt > 0) {
            if (kt < qi) { CP_WAIT1(); } else { CP_WAIT0(); }
            __syncthreads();
        }
        uint32_t kb = sb + AT_KV0 + (kt & 1) * AT_KVS;

        float s[8][4];
#pragma unroll
        for (int i = 0; i < 8; i++)
#pragma unroll
            for (int j = 0; j < 4; j++) s[i][j] = 0.f;
#pragma unroll
        for (int kk = 0; kk < 4; kk++) {
            uint32_t kh[16], kl[16];
#pragma unroll
            for (int np = 0; np < 4; np++) {
                uint32_t ad = kb + (uint32_t)((np * 16 + browoff) * APITCH +
                                              (kk * 16 + bkoff) * 2);
                ldsm_x4(kh + 4 * np, ad);
                ldsm_x4(kl + 4 * np, ad + AT_TILE);
            }
#pragma unroll
            for (int nt = 0; nt < 8; nt++) {
                uint32_t* bp = kh + (nt >> 1) * 4 + (nt & 1) * 2;
                uint32_t* bl2 = kl + (nt >> 1) * 4 + (nt & 1) * 2;
                mma_f16(s[nt], qfh[kk], bp);
                mma_f16(s[nt], qfh[kk], bl2);
                mma_f16(s[nt], qfl[kk], bp);
            }
        }
#pragma unroll
        for (int nt = 0; nt < 8; nt++)
#pragma unroll
            for (int j = 0; j < 4; j++) s[nt][j] *= 0.125f;
        if (kt == qi) {
#pragma unroll
            for (int nt = 0; nt < 8; nt++)
#pragma unroll
                for (int j = 0; j < 4; j++) {
                    int kc = 8 * nt + 2 * qid + (j & 1);
                    int qr = w * 16 + gid + (j >> 1) * 8;
                    if (kc > qr) s[nt][j] = -1e30f;
                }
        }
        float mt0 = -1e30f, mt1 = -1e30f;
#pragma unroll
        for (int nt = 0; nt < 8; nt++) {
            mt0 = fmaxf(mt0, fmaxf(s[nt][0], s[nt][1]));
            mt1 = fmaxf(mt1, fmaxf(s[nt][2], s[nt][3]));
        }
        mt0 = fmaxf(mt0, __shfl_xor_sync(0xffffffffu, mt0, 1));
        mt0 = fmaxf(mt0, __shfl_xor_sync(0xffffffffu, mt0, 2));
        mt1 = fmaxf(mt1, __shfl_xor_sync(0xffffffffu, mt1, 1));
        mt1 = fmaxf(mt1, __shfl_xor_sync(0xffffffffu, mt1, 2));
        float mn0 = fmaxf(mrow[0], mt0), mn1 = fmaxf(mrow[1], mt1);
        float c0 = __expf(mrow[0] - mn0), c1 = __expf(mrow[1] - mn1);
        mrow[0] = mn0; mrow[1] = mn1;
        float rs0 = 0.f, rs1 = 0.f;
#pragma unroll
        for (int nt = 0; nt < 8; nt++) {
            s[nt][0] = __expf(s[nt][0] - mn0);
            s[nt][1] = __expf(s[nt][1] - mn0);
            s[nt][2] = __expf(s[nt][2] - mn1);
            s[nt][3] = __expf(s[nt][3] - mn1);
            rs0 += s[nt][0] + s[nt][1];
            rs1 += s[nt][2] + s[nt][3];
        }
        rs0 += __shfl_xor_sync(0xffffffffu, rs0, 1);
        rs0 += __shfl_xor_sync(0xffffffffu, rs0, 2);
        rs1 += __shfl_xor_sync(0xffffffffu, rs1, 1);
        rs1 += __shfl_xor_sync(0xffffffffu, rs1, 2);
        lrow[0] = lrow[0] * c0 + rs0;
        lrow[1] = lrow[1] * c1 + rs1;
#pragma unroll
        for (int nt = 0; nt < 8; nt++) {
            oacc[nt][0] *= c0; oacc[nt][1] *= c0;
            oacc[nt][2] *= c1; oacc[nt][3] *= c1;
        }
#pragma unroll
        for (int k2 = 0; k2 < 4; k2++) {
            uint32_t pah[4], pal[4];
            {
                float p00 = s[2 * k2][0],     p01 = s[2 * k2][1];
                float p10 = s[2 * k2][2],     p11 = s[2 * k2][3];
                float p20 = s[2 * k2 + 1][0], p21 = s[2 * k2 + 1][1];
                float p30 = s[2 * k2 + 1][2], p31 = s[2 * k2 + 1][3];
                pah[0] = packh(p00, p01);
                pah[1] = packh(p10, p11);
                pah[2] = packh(p20, p21);
                pah[3] = packh(p30, p31);
                __half2* hp;
                hp = (__half2*)&pah[0];
                pal[0] = packh(p00 - __half2float(hp->x), p01 - __half2float(hp->y));
                hp = (__half2*)&pah[1];
                pal[1] = packh(p10 - __half2float(hp->x), p11 - __half2float(hp->y));
                hp = (__half2*)&pah[2];
                pal[2] = packh(p20 - __half2float(hp->x), p21 - __half2float(hp->y));
                hp = (__half2*)&pah[3];
                pal[3] = packh(p30 - __half2float(hp->x), p31 - __half2float(hp->y));
            }
            uint32_t vh[16], vl[16];
#pragma unroll
            for (int np = 0; np < 4; np++) {
                uint32_t ad = kb + 2 * AT_TILE +
                              (uint32_t)((k2 * 16 + t_row) * APITCH +
                                         (np * 16 + t_col) * 2);
                ldsm_x4t(vh + 4 * np, ad);
                ldsm_x4t(vl + 4 * np, ad + AT_TILE);
            }
#pragma unroll
            for (int nt = 0; nt < 8; nt++) {
                uint32_t* bp = vh + (nt >> 1) * 4 + (nt & 1) * 2;
                uint32_t* bl2 = vl + (nt >> 1) * 4 + (nt & 1) * 2;
                mma_f16(oacc[nt], pah, bp);
                mma_f16(oacc[nt], pah, bl2);
                mma_f16(oacc[nt], pal, bp);
            }
        }
        __syncthreads();
        if (kt + 2 <= qi) ISSUE_KV(kt + 2);
    }
#undef ISSUE_KV

    float inv0 = 1.f / lrow[0], inv1 = 1.f / lrow[1];
    int tok0 = b * Tz + qi * 64 + w * 16 + gid;
#pragma unroll
    for (int nt = 0; nt < 8; nt++) {
        int col = h * Dz + 8 * nt + 2 * qid;
        __half2 ph;
        ph.x = __float2half(oacc[nt][0] * inv0);
        ph.y = __float2half(oacc[nt][1] * inv0);
        *(__half2*)(oh + (size_t)tok0 * Cz + col) = ph;
        ph.x = __float2half(oacc[nt][2] * inv1);
        ph.y = __float2half(oacc[nt][3] * inv1);
        *(__half2*)(oh + (size_t)(tok0 + 8) * Cz + col) = ph;
    }
}

// ---------------------------------------------------------------------------
// Embedding
// ---------------------------------------------------------------------------
__global__ void embed_kernel(const int* __restrict__ idx,
                             const float* __restrict__ tok,
                             const float* __restrict__ pos,
                             float* __restrict__ x) {
    int row = blockIdx.x;
    int t   = row & (Tz - 1);
    int tokid = idx[row];
    const float* te = tok + (size_t)tokid * Cz;
    const float* pe = pos + (size_t)t * Cz;
    float* xr = x + (size_t)row * Cz;
    for (int i = threadIdx.x; i < Cz; i += blockDim.x)
        xr[i] = te[i] + pe[i];
}

// ---------------------------------------------------------------------------
// LayerNorm per row, writes fp16 hi/lo pair (lo optional)
// ---------------------------------------------------------------------------
__global__ void ln_kernel(const float* __restrict__ x,
                          __half* __restrict__ yh, __half* __restrict__ yl,
                          const float* __restrict__ g, const float* __restrict__ b) {
    int row = blockIdx.x;
    const float* xr = x + (size_t)row * Cz;
    float s = 0.f, s2 = 0.f;
    for (int i = threadIdx.x; i < Cz; i += blockDim.x) {
        float v = xr[i];
        s += v; s2 += v * v;
    }
    __shared__ float sh_s[8], sh_s2[8];
    for (int off = 16; off > 0; off >>= 1) {
        s  += __shfl_down_sync(0xffffffffu, s,  off);
        s2 += __shfl_down_sync(0xffffffffu, s2, off);
    }
    int lane = threadIdx.x & 31, wid = threadIdx.x >> 5;
    if (lane == 0) { sh_s[wid] = s; sh_s2[wid] = s2; }
    __syncthreads();
    if (wid == 0) {
        s  = (lane < 8) ? sh_s[lane]  : 0.f;
        s2 = (lane < 8) ? sh_s2[lane] : 0.f;
        for (int off = 4; off > 0; off >>= 1) {
            s  += __shfl_down_sync(0xffffffffu, s,  off);
            s2 += __shfl_down_sync(0xffffffffu, s2, off);
        }
        if (lane == 0) { sh_s[0] = s; sh_s2[0] = s2; }
    }
    __syncthreads();
    float mean = sh_s[0] * (1.f / Cz);
    float var  = sh_s2[0] * (1.f / Cz) - mean * mean;
    float rstd = rsqrtf(var + EPSz);
    __half* yhr = yh + (size_t)row * Cz;
    __half* ylr = yl ? (yl + (size_t)row * Cz) : nullptr;
    for (int i = threadIdx.x; i < Cz; i += blockDim.x) {
        float v = (xr[i] - mean) * rstd * g[i] + b[i];
        __half h = __float2half(v);
        yhr[i] = h;
        if (ylr) ylr[i] = __float2half(v - __half2float(h));
    }
}

// ---------------------------------------------------------------------------
// Launch
// ---------------------------------------------------------------------------
extern "C" void kernel_launch(void* const* d_in, const int* in_sizes, int n_in,
                              void* d_out, int out_size) {
    const int*   idx     = (const int*)  d_in[0];
    const float* tok_emb = (const float*)d_in[1];
    const float* pos_emb = (const float*)d_in[2];
    const float* qkv_w   = (const float*)d_in[3];
    const float* proj_w  = (const float*)d_in[4];
    const float* proj_b  = (const float*)d_in[5];
    const float* ln1_g   = (const float*)d_in[6];
    const float* ln1_b   = (const float*)d_in[7];
    const float* ln2_g   = (const float*)d_in[8];
    const float* ln2_b   = (const float*)d_in[9];
    const float* fc1_w   = (const float*)d_in[10];
    const float* fc1_b   = (const float*)d_in[11];
    const float* fc2_w   = (const float*)d_in[12];
    const float* fc2_b   = (const float*)d_in[13];
    const float* lnf_g   = (const float*)d_in[14];
    const float* lnf_b   = (const float*)d_in[15];
    float* out = (float*)d_out;

    float* x;
    cudaGetSymbolAddress((void**)&x, g_x);
    __half *hh, *hl, *qkvh, *qkvl, *atth, *ffnh;
    cudaGetSymbolAddress((void**)&hh,   g_hh);
    cudaGetSymbolAddress((void**)&hl,   g_hl);
    cudaGetSymbolAddress((void**)&qkvh, g_qkvh);
    cudaGetSymbolAddress((void**)&qkvl, g_qkvl);
    cudaGetSymbolAddress((void**)&atth, g_atth);
    cudaGetSymbolAddress((void**)&ffnh, g_ffnh);
    __half *qkvTh, *qkvTl, *projT, *fc1T, *fc2T, *tokT;
    cudaGetSymbolAddress((void**)&qkvTh, g_qkvT_h);
    cudaGetSymbolAddress((void**)&qkvTl, g_qkvT_l);
    cudaGetSymbolAddress((void**)&projT, g_projT);
    cudaGetSymbolAddress((void**)&fc1T,  g_fc1T);
    cudaGetSymbolAddress((void**)&fc2T,  g_fc2T);
    cudaGetSymbolAddress((void**)&tokT,  g_tokT);

    const int GS11 = 3 * 20480;
    const int GS22 = 3 * 40960;
    cudaFuncSetAttribute(gemm_h<1, 1>, cudaFuncAttributeMaxDynamicSharedMemorySize, GS11);
    cudaFuncSetAttribute(gemm_qkv, cudaFuncAttributeMaxDynamicSharedMemorySize, GS22);
    cudaFuncSetAttribute(attn_mma, cudaFuncAttributeMaxDynamicSharedMemorySize, AT_SMEM);

    // ---- weight prep ----
    dim3 tb(32, 8);
    wtrans_pair<<<dim3(3 * Cz / 32, Cz / 64, Lz), tb>>>(qkv_w, qkvTh, qkvTl, Cz, 3 * Cz);
    wtrans_one<<<dim3(Cz / 32, Cz / 64, Lz), tb>>>(proj_w, projT, Cz, Cz);
    wtrans_one<<<dim3(HIDz / 32, Cz / 64, Lz), tb>>>(fc1_w, fc1T, Cz, HIDz);
    wtrans_one<<<dim3(Cz / 32, HIDz / 64, Lz), tb>>>(fc2_w, fc2T, HIDz, Cz);
    wsplit_one<<<(Vz * Cz + 255) / 256, 256>>>(tok_emb, tokT, Vz * Cz);

    embed_kernel<<<NTOK, 256>>>(idx, tok_emb, pos_emb, x);

    for (int l = 0; l < Lz; l++) {
        const __half* qwh = qkvTh + (size_t)l * 3 * Cz * Cz;
        const __half* qwl = qkvTl + (size_t)l * 3 * Cz * Cz;
        const __half* vwh = qwh + (size_t)2 * Cz * Cz;     // v rows [2048,3072)
        const __half* pw  = projT + (size_t)l * Cz * Cz;
        const __half* w1  = fc1T  + (size_t)l * Cz * HIDz;
        const __half* w2  = fc2T  + (size_t)l * Cz * HIDz;
        const float* pb = proj_b + (size_t)l * Cz;
        const float* b1 = fc1_b  + (size_t)l * HIDz;
        const float* b2 = fc2_b  + (size_t)l * Cz;

        ln_kernel<<<NTOK, 256>>>(x, hh, hl, ln1_g + l * Cz, ln1_b + l * Cz);
        gemm_qkv<<<dim3(24, NTOK / 128), 256, GS22>>>(
            hh, hl, qwh, qwl, vwh, qkvh, qkvl);
        attn_mma<<<dim3(Tz / 64, Bz * Hz), 128, AT_SMEM>>>(qkvh, qkvl, atth);
        gemm_h<1, 1><<<dim3(Cz / 128, NTOK / 128), 256, GS11>>>(
            atth, nullptr, pw, nullptr, x, nullptr, nullptr,
            Cz, Cz, Cz, pb, x, 0);
        ln_kernel<<<NTOK, 256>>>(x, hh, nullptr, ln2_g + l * Cz, ln2_b + l * Cz);
        gemm_h<1, 1><<<dim3(HIDz / 128, NTOK / 128), 256, GS11>>>(
            hh, nullptr, w1, nullptr, nullptr, ffnh, nullptr,
            HIDz, Cz, HIDz, b1, nullptr, 1);
        gemm_h<1, 1><<<dim3(Cz / 128, NTOK / 128), 256, GS11>>>(
            ffnh, nullptr, w2, nullptr, x, nullptr, nullptr,
            Cz, HIDz, Cz, b2, x, 0);
    }

    ln_kernel<<<NTOK, 256>>>(x, hh, nullptr, lnf_g, lnf_b);
    gemm_h<1, 1><<<dim3(Vz / 128, NTOK / 128), 256, GS11>>>(
        hh, nullptr, tokT, nullptr, out, nullptr, nullptr,
        Vz, Cz, Vz, nullptr, nullptr, 0);
}

// round 15
// speedup vs baseline: 4.1926x; 1.0190x over previous
#include <cuda_runtime.h>
#include <cuda_fp16.h>
#include <cstdint>
#include <math.h>

// Problem constants
#define Bz   2
#define Tz   1024
#define Cz   1024
#define Hz   16
#define Lz   8
#define Dz   64
#define HIDz 4096
#define Vz   32000
#define NTOK (Bz * Tz)          // 2048
#define EPSz 1e-5f

// ---------------------------------------------------------------------------
// PTX helpers (base ISA only)
// ---------------------------------------------------------------------------
__device__ __forceinline__ uint32_t smem_u32(const void* p) {
    uint32_t a;
    asm("{ .reg .u64 t; cvta.to.shared.u64 t, %1; cvt.u32.u64 %0, t; }"
        : "=r"(a) : "l"(p));
    return a;
}
__device__ __forceinline__ void ldsm_x4(uint32_t* r, uint32_t addr) {
    asm volatile("ldmatrix.sync.aligned.m8n8.x4.shared.b16 {%0,%1,%2,%3}, [%4];"
        : "=r"(r[0]), "=r"(r[1]), "=r"(r[2]), "=r"(r[3]) : "r"(addr));
}
__device__ __forceinline__ void ldsm_x4t(uint32_t* r, uint32_t addr) {
    asm volatile("ldmatrix.sync.aligned.m8n8.x4.trans.shared.b16 {%0,%1,%2,%3}, [%4];"
        : "=r"(r[0]), "=r"(r[1]), "=r"(r[2]), "=r"(r[3]) : "r"(addr));
}
__device__ __forceinline__ void mma_f16(float* d, const uint32_t* a, const uint32_t* b) {
    asm volatile("mma.sync.aligned.m16n8k16.row.col.f32.f16.f16.f32 "
        "{%0,%1,%2,%3}, {%4,%5,%6,%7}, {%8,%9}, {%0,%1,%2,%3};"
        : "+f"(d[0]), "+f"(d[1]), "+f"(d[2]), "+f"(d[3])
        : "r"(a[0]), "r"(a[1]), "r"(a[2]), "r"(a[3]), "r"(b[0]), "r"(b[1]));
}
__device__ __forceinline__ void cp16(uint32_t saddr, const void* gaddr) {
    asm volatile("cp.async.ca.shared.global [%0], [%1], 16;"
                 :: "r"(saddr), "l"(gaddr) : "memory");
}
#define CP_COMMIT() asm volatile("cp.async.commit_group;" ::: "memory")
#define CP_WAIT1()  asm volatile("cp.async.wait_group 1;" ::: "memory")
#define CP_WAIT0()  asm volatile("cp.async.wait_group 0;" ::: "memory")

__device__ __forceinline__ uint32_t packh(float x, float y) {
    __half2 t;
    t.x = __float2half(x);
    t.y = __float2half(y);
    return *(uint32_t*)&t;
}

// ---------------------------------------------------------------------------
// Scratch (device globals)
// ---------------------------------------------------------------------------
__device__ float g_x[NTOK * Cz];                 // residual stream
__device__ __half g_hh  [NTOK * Cz];
__device__ __half g_hl  [NTOK * Cz];
__device__ __half g_qkvh[NTOK * 3 * Cz];
__device__ __half g_qkvl[NTOK * 3 * Cz];
__device__ __half g_atth[NTOK * Cz];
__device__ __half g_ffnh[NTOK * HIDz];

// Weights, transposed to [N,K]. qkv = fp16 pair; rest = single fp16.
__device__ __half g_qkvT_h[Lz * 3 * Cz * Cz];
__device__ __half g_qkvT_l[Lz * 3 * Cz * Cz];
__device__ __half g_projT[Lz * Cz * Cz];
__device__ __half g_fc1T [Lz * HIDz * Cz];
__device__ __half g_fc2T [Lz * Cz * HIDz];
__device__ __half g_tokT [Vz * Cz];

// ---------------------------------------------------------------------------
// Weight prep (coalesced transpose, half2 writes)
// ---------------------------------------------------------------------------
__global__ void wtrans_pair(const float* __restrict__ W,
                            __half* __restrict__ Th, __half* __restrict__ Tl,
                            int K, int N) {
    __shared__ float t[64][33];
    const float* Wl = W + (size_t)blockIdx.z * K * N;
    __half* Thg = Th + (size_t)blockIdx.z * K * N;
    __half* Tlg = Tl + (size_t)blockIdx.z * K * N;
    int n0 = blockIdx.x * 32, k0 = blockIdx.y * 64;
    int tx = threadIdx.x, ty = threadIdx.y;
#pragma unroll
    for (int j = 0; j < 64; j += 8)
        t[ty + j][tx] = Wl[(size_t)(k0 + ty + j) * N + n0 + tx];
    __syncthreads();
#pragma unroll
    for (int p = 0; p < 4; p++) {
        int nloc = p * 8 + ty;
        float v0 = t[2 * tx][nloc], v1 = t[2 * tx + 1][nloc];
        __half2 h2, l2;
        h2.x = __float2half(v0);
        h2.y = __float2half(v1);
        l2.x = __float2half(v0 - __half2float(h2.x));
        l2.y = __float2half(v1 - __half2float(h2.y));
        size_t o = (size_t)(n0 + nloc) * K + k0 + 2 * tx;
        *(__half2*)(Thg + o) = h2;
        *(__half2*)(Tlg + o) = l2;
    }
}

__global__ void wtrans_one(const float* __restrict__ W,
                           __half* __restrict__ T, int K, int N) {
    __shared__ float t[64][33];
    const float* Wl = W + (size_t)blockIdx.z * K * N;
    __half* Tg = T + (size_t)blockIdx.z * K * N;
    int n0 = blockIdx.x * 32, k0 = blockIdx.y * 64;
    int tx = threadIdx.x, ty = threadIdx.y;
#pragma unroll
    for (int j = 0; j < 64; j += 8)
        t[ty + j][tx] = Wl[(size_t)(k0 + ty + j) * N + n0 + tx];
    __syncthreads();
#pragma unroll
    for (int p = 0; p < 4; p++) {
        int nloc = p * 8 + ty;
        __half2 h2;
        h2.x = __float2half(t[2 * tx][nloc]);
        h2.y = __float2half(t[2 * tx + 1][nloc]);
        *(__half2*)(Tg + (size_t)(n0 + nloc) * K + k0 + 2 * tx) = h2;
    }
}

__global__ void wsplit_one(const float* __restrict__ W, __half* __restrict__ T, int n) {
    int i = blockIdx.x * blockDim.x + threadIdx.x;
    if (i < n) T[i] = __float2half(W[i]);
}

// ---------------------------------------------------------------------------
// gemm_body<NA,NB>: fp16 mma GEMM core (device function).
// Block 128x128, 8 warps (64x32), BK=32, NSTG=3 cp.async pipeline.
// ---------------------------------------------------------------------------
#define HPITCH 80

template <int NA, int NB>
__device__ __forceinline__ void gemm_body(
    const __half* __restrict__ Ah, const __half* __restrict__ Al,
    const __half* __restrict__ Bh, const __half* __restrict__ Bl,
    float* __restrict__ Cf, __half* __restrict__ Ch, __half* __restrict__ Cl,
    int N, int K, int ldc,
    const float* __restrict__ bias, const float* __restrict__ res,
    int gelu, int m0, int n0, char* smem) {
    constexpr int STG = (NA + NB) * 10240;
    constexpr int O_AH = 0;
    constexpr int O_AL = 10240;
    constexpr int O_BH = NA * 10240;
    constexpr int O_BL = O_BH + 10240;
    uint32_t sb = smem_u32(smem);
    int tid = threadIdx.x, wid = tid >> 5, lane = tid & 31;
    int wm = wid & 1, wn = wid >> 1;

    const __half* Agh = Ah + (size_t)m0 * K;
    const __half* Agl = (NA == 2) ? (Al + (size_t)m0 * K) : nullptr;
    const __half* Bgh = Bh + (size_t)n0 * K;
    const __half* Bgl = (NB == 2) ? (Bl + (size_t)n0 * K) : nullptr;

    float acc[4][4][4];
#pragma unroll
    for (int i = 0; i < 4; i++)
#pragma unroll
        for (int j = 0; j < 4; j++)
#pragma unroll
            for (int r = 0; r < 4; r++) acc[i][j][r] = 0.f;

    const int NC = K >> 5;

#define ISSUE_H(c)                                                             \
    {                                                                          \
        uint32_t s0 = sb + ((c) % 3) * STG;                                    \
        _Pragma("unroll")                                                      \
        for (int it = 0; it < 2; it++) {                                       \
            int i = it * 256 + tid;                                            \
            int row = i >> 2, seg = i & 3;                                     \
            uint32_t so = row * HPITCH + seg * 16;                             \
            size_t go = (size_t)row * K + (size_t)(c) * 32 + seg * 8;          \
            cp16(s0 + O_AH + so, Agh + go);                                    \
            if (NA == 2) cp16(s0 + O_AL + so, Agl + go);                       \
            cp16(s0 + O_BH + so, Bgh + go);                                    \
            if (NB == 2) cp16(s0 + O_BL + so, Bgl + go);                       \
        }                                                                      \
        CP_COMMIT();                                                           \
    }

    ISSUE_H(0);
    ISSUE_H(1);

    int r16 = lane & 15, hsel = lane >> 4;
    int bg = lane >> 3;
    int browoff = ((bg & 2) << 2) + (lane & 7);
    int bkoff = (bg & 1) * 8;

    for (int c = 0; c < NC; c++) {
        if (c + 1 < NC) { CP_WAIT1(); } else { CP_WAIT0(); }
        __syncthreads();
        if (c + 2 < NC) ISSUE_H(c + 2);
        uint32_t base = sb + (c % 3) * STG;
#pragma unroll
        for (int kk = 0; kk < 32; kk += 16) {
            uint32_t ah[16], al[16], bh[8], bl[8];
#pragma unroll
            for (int mt = 0; mt < 4; mt++) {
                uint32_t ad = (uint32_t)((wm * 64 + mt * 16 + r16) * HPITCH +
                                         (kk + hsel * 8) * 2);
                ldsm_x4(ah + 4 * mt, base + O_AH + ad);
                if (NA == 2) ldsm_x4(al + 4 * mt, base + O_AL + ad);
            }
#pragma unroll
            for (int ntp = 0; ntp < 2; ntp++) {
                uint32_t bd = (uint32_t)((wn * 32 + ntp * 16 + browoff) * HPITCH +
                                         (kk + bkoff) * 2);
                ldsm_x4(bh + 4 * ntp, base + O_BH + bd);
                if (NB == 2) ldsm_x4(bl + 4 * ntp, base + O_BL + bd);
            }
#pragma unroll
            for (int mt = 0; mt < 4; mt++)
#pragma unroll
                for (int nt = 0; nt < 4; nt++) {
                    uint32_t* bp = bh + (nt >> 1) * 4 + (nt & 1) * 2;
                    mma_f16(acc[mt][nt], ah + 4 * mt, bp);
                    if (NA == 2) mma_f16(acc[mt][nt], al + 4 * mt, bp);
                    if (NB == 2) {
                        uint32_t* bp2 = bl + (nt >> 1) * 4 + (nt & 1) * 2;
                        mma_f16(acc[mt][nt], ah + 4 * mt, bp2);
                    }
                }
        }
        __syncthreads();
    }
#undef ISSUE_H

    int gid = lane >> 2, qid = lane & 3;
#pragma unroll
    for (int mt = 0; mt < 4; mt++) {
#pragma unroll
        for (int nt = 0; nt < 4; nt++) {
            int n = n0 + wn * 32 + nt * 8 + 2 * qid;
            float bsum0 = bias ? bias[n] : 0.f;
            float bsum1 = bias ? bias[n + 1] : 0.f;
#pragma unroll
            for (int half = 0; half < 2; half++) {
                int m = m0 + wm * 64 + mt * 16 + gid + half * 8;
                float v0 = acc[mt][nt][half * 2 + 0] + bsum0;
                float v1 = acc[mt][nt][half * 2 + 1] + bsum1;
                if (gelu) {
                    v0 = 0.5f * v0 * (1.f + erff(v0 * 0.70710678118654752f));
                    v1 = 0.5f * v1 * (1.f + erff(v1 * 0.70710678118654752f));
                }
                if (res) {
                    const float* rr = res + (size_t)m * ldc + n;
                    v0 += rr[0];
                    v1 += rr[1];
                }
                if (Cf) {
                    float2 o;
                    o.x = v0; o.y = v1;
                    *(float2*)(Cf + (size_t)m * ldc + n) = o;
                }
                if (Ch) {
                    __half2 oh;
                    oh.x = __float2half(v0);
                    oh.y = __float2half(v1);
                    *(__half2*)(Ch + (size_t)m * ldc + n) = oh;
                    if (Cl) {
                        __half2 ol;
                        ol.x = __float2half(v0 - __half2float(oh.x));
                        ol.y = __float2half(v1 - __half2float(oh.y));
                        *(__half2*)(Cl + (size_t)m * ldc + n) = ol;
                    }
                }
            }
        }
    }
}

// 1-pass GEMM, 2 CTAs/SM for wave smoothing + epilogue overlap
__global__ __launch_bounds__(256, 2)
void gemm_h11(const __half* __restrict__ Ah, const __half* __restrict__ Bh,
              float* __restrict__ Cf,
              __half* __restrict__ Ch, __half* __restrict__ Cl,
              int N, int K, int ldc,
              const float* __restrict__ bias, const float* __restrict__ res,
              int gelu) {
    extern __shared__ __align__(128) char smem[];
    gemm_body<1, 1>(Ah, nullptr, Bh, nullptr, Cf, Ch, Cl, N, K, ldc,
                    bias, res, gelu, blockIdx.y * 128, blockIdx.x * 128, smem);
}

// Fused qkv: blockIdx.x < 16 -> q,k (3-pass); else -> v (2-pass).
__global__ __launch_bounds__(256)
void gemm_qkv(const __half* __restrict__ hh, const __half* __restrict__ hl,
              const __half* __restrict__ qkwh, const __half* __restrict__ qkwl,
              const __half* __restrict__ vwh,
              __half* __restrict__ qkvh, __half* __restrict__ qkvl) {
    extern __shared__ __align__(128) char smem[];
    int m0 = blockIdx.y * 128;
    if (blockIdx.x < 16) {
        gemm_body<2, 2>(hh, hl, qkwh, qkwl, nullptr, qkvh, qkvl,
                        2 * Cz, Cz, 3 * Cz, nullptr, nullptr, 0,
                        m0, blockIdx.x * 128, smem);
    } else {
        gemm_body<2, 1>(hh, hl, vwh, nullptr, nullptr,
                        qkvh + 2 * Cz, qkvl + 2 * Cz,
                        Cz, Cz, 3 * Cz, nullptr, nullptr, 0,
                        m0, (blockIdx.x - 16) * 128, smem);
    }
}

// ---------------------------------------------------------------------------
// MMA flash attention. QK^T: 3-pass. P.V: 2-pass (Ph*Vh + Ph*Vl).
// Output: hi only.
// ---------------------------------------------------------------------------
#define APITCH  144
#define AT_TILE 9216
#define AT_Q    0
#define AT_KV0  (2 * AT_TILE)
#define AT_KVS  (4 * AT_TILE)
#define AT_SMEM (AT_KV0 + 2 * AT_KVS)

__global__ __launch_bounds__(128)
void attn_mma(const __half* __restrict__ qkvh,
              const __half* __restrict__ qkvl,
              __half* __restrict__ oh) {
    extern __shared__ __align__(128) char smem[];
    uint32_t sb = smem_u32(smem);
    int tid = threadIdx.x, w = tid >> 5, lane = tid & 31;
    int qi = (int)gridDim.x - 1 - (int)blockIdx.x;
    int bh = blockIdx.y;
    int b = bh >> 4, h = bh & 15;
    const int RS = 3 * Cz;
    const size_t tokbase = (size_t)(b * Tz) * RS + h * Dz;

    int gid = lane >> 2, qid = lane & 3;
    int r16 = lane & 15, hsel = lane >> 4;
    int bg = lane >> 3;
    int browoff = ((bg & 2) << 2) + (lane & 7);
    int bkoff = (bg & 1) * 8;
    int t_row = (bg & 1) * 8 + (lane & 7);
    int t_col = (bg >> 1) * 8;

#define ISSUE_KV(kt)                                                           \
    {                                                                          \
        uint32_t s0 = sb + AT_KV0 + ((kt) & 1) * AT_KVS;                       \
        const __half* srcs[4] = {                                              \
            qkvh + tokbase + Cz, qkvl + tokbase + Cz,                          \
            qkvh + tokbase + 2 * Cz, qkvl + tokbase + 2 * Cz };                \
        _Pragma("unroll")                                                      \
        for (int t = 0; t < 4; t++) {                                          \
            _Pragma("unroll")                                                  \
            for (int it = 0; it < 4; it++) {                                   \
                int i = it * 128 + tid;                                        \
                int r = i >> 3, s = i & 7;                                     \
                cp16(s0 + t * AT_TILE + r * APITCH + s * 16,                   \
                     srcs[t] + (size_t)((kt) * 64 + r) * RS + s * 8);          \
            }                                                                  \
        }                                                                      \
        CP_COMMIT();                                                           \
    }

    {
#pragma unroll
        for (int t = 0; t < 2; t++) {
            const __half* src = (t ? qkvl : qkvh) + tokbase;
            uint32_t dst = sb + AT_Q + t * AT_TILE;
#pragma unroll
            for (int it = 0; it < 4; it++) {
                int i = it * 128 + tid;
                int r = i >> 3, s = i & 7;
                cp16(dst + r * APITCH + s * 16,
                     src + (size_t)(qi * 64 + r) * RS + s * 8);
            }
        }
        uint32_t s0 = sb + AT_KV0;
        const __half* srcs[4] = {
            qkvh + tokbase + Cz, qkvl + tokbase + Cz,
            qkvh + tokbase + 2 * Cz, qkvl + tokbase + 2 * Cz };
#pragma unroll
        for (int t = 0; t < 4; t++) {
#pragma unroll
            for (int it = 0; it < 4; it++) {
                int i = it * 128 + tid;
                int r = i >> 3, s = i & 7;
                cp16(s0 + t * AT_TILE + r * APITCH + s * 16,
                     srcs[t] + (size_t)r * RS + s * 8);
            }
        }
        CP_COMMIT();
    }
    if (qi >= 1) ISSUE_KV(1);

    if (qi >= 1) { CP_WAIT1(); } else { CP_WAIT0(); }
    __syncthreads();

    uint32_t qfh[4][4], qfl[4][4];
#pragma unroll
    for (int kk = 0; kk < 4; kk++) {
        uint32_t ad = sb + AT_Q + (uint32_t)((w * 16 + r16) * APITCH +
                                             (kk * 16 + hsel * 8) * 2);
        ldsm_x4(qfh[kk], ad);
        ldsm_x4(qfl[kk], ad + AT_TILE);
    }

    float oacc[8][4];
#pragma unroll
    for (int i = 0; i < 8; i++)
#pragma unroll
        for (int j = 0; j < 4; j++) oacc[i][j] = 0.f;
    float mrow[2] = {-1e30f, -1e30f};
    float lrow[2] = {0.f, 0.f};

    for (int kt = 0; kt <= qi; kt++) {
        if (kt > 0) {
            if (kt < qi) { CP_WAIT1(); } else { CP_WAIT0(); }
            __syncthreads();
        }
        uint32_t kb = sb + AT_KV0 + (kt & 1) * AT_KVS;

        float s[8][4];
#pragma unroll
        for (int i = 0; i < 8; i++)
#pragma unroll
            for (int j = 0; j < 4; j++) s[i][j] = 0.f;
#pragma unroll
        for (int kk = 0; kk < 4; kk++) {
            uint32_t kh[16], kl[16];
#pragma unroll
            for (int np = 0; np < 4; np++) {
                uint32_t ad = kb + (uint32_t)((np * 16 + browoff) * APITCH +
                                              (kk * 16 + bkoff) * 2);
                ldsm_x4(kh + 4 * np, ad);
                ldsm_x4(kl + 4 * np, ad + AT_TILE);
            }
#pragma unroll
            for (int nt = 0; nt < 8; nt++) {
                uint32_t* bp = kh + (nt >> 1) * 4 + (nt & 1) * 2;
                uint32_t* bl2 = kl + (nt >> 1) * 4 + (nt & 1) * 2;
                mma_f16(s[nt], qfh[kk], bp);
                mma_f16(s[nt], qfh[kk], bl2);
                mma_f16(s[nt], qfl[kk], bp);
            }
        }
#pragma unroll
        for (int nt = 0; nt < 8; nt++)
#pragma unroll
            for (int j = 0; j < 4; j++) s[nt][j] *= 0.125f;
        if (kt == qi) {
#pragma unroll
            for (int nt = 0; nt < 8; nt++)
#pragma unroll
                for (int j = 0; j < 4; j++) {
                    int kc = 8 * nt + 2 * qid + (j & 1);
                    int qr = w * 16 + gid + (j >> 1) * 8;
                    if (kc > qr) s[nt][j] = -1e30f;
                }
        }
        float mt0 = -1e30f, mt1 = -1e30f;
#pragma unroll
        for (int nt = 0; nt < 8; nt++) {
            mt0 = fmaxf(mt0, fmaxf(s[nt][0], s[nt][1]));
            mt1 = fmaxf(mt1, fmaxf(s[nt][2], s[nt][3]));
        }
        mt0 = fmaxf(mt0, __shfl_xor_sync(0xffffffffu, mt0, 1));
        mt0 = fmaxf(mt0, __shfl_xor_sync(0xffffffffu, mt0, 2));
        mt1 = fmaxf(mt1, __shfl_xor_sync(0xffffffffu, mt1, 1));
        mt1 = fmaxf(mt1, __shfl_xor_sync(0xffffffffu, mt1, 2));
        float mn0 = fmaxf(mrow[0], mt0), mn1 = fmaxf(mrow[1], mt1);
        float c0 = __expf(mrow[0] - mn0), c1 = __expf(mrow[1] - mn1);
        mrow[0] = mn0; mrow[1] = mn1;
        float rs0 = 0.f, rs1 = 0.f;
#pragma unroll
        for (int nt = 0; nt < 8; nt++) {
            s[nt][0] = __expf(s[nt][0] - mn0);
            s[nt][1] = __expf(s[nt][1] - mn0);
            s[nt][2] = __expf(s[nt][2] - mn1);
            s[nt][3] = __expf(s[nt][3] - mn1);
            rs0 += s[nt][0] + s[nt][1];
            rs1 += s[nt][2] + s[nt][3];
        }
        rs0 += __shfl_xor_sync(0xffffffffu, rs0, 1);
        rs0 += __shfl_xor_sync(0xffffffffu, rs0, 2);
        rs1 += __shfl_xor_sync(0xffffffffu, rs1, 1);
        rs1 += __shfl_xor_sync(0xffffffffu, rs1, 2);
        lrow[0] = lrow[0] * c0 + rs0;
        lrow[1] = lrow[1] * c1 + rs1;
#pragma unroll
        for (int nt = 0; nt < 8; nt++) {
            oacc[nt][0] *= c0; oacc[nt][1] *= c0;
            oacc[nt][2] *= c1; oacc[nt][3] *= c1;
        }
#pragma unroll
        for (int k2 = 0; k2 < 4; k2++) {
            uint32_t pah[4];
            pah[0] = packh(s[2 * k2][0], s[2 * k2][1]);
            pah[1] = packh(s[2 * k2][2], s[2 * k2][3]);
            pah[2] = packh(s[2 * k2 + 1][0], s[2 * k2 + 1][1]);
            pah[3] = packh(s[2 * k2 + 1][2], s[2 * k2 + 1][3]);
            uint32_t vh[16], vl[16];
#pragma unroll
            for (int np = 0; np < 4; np++) {
                uint32_t ad = kb + 2 * AT_TILE +
                              (uint32_t)((k2 * 16 + t_row) * APITCH +
                                         (np * 16 + t_col) * 2);
                ldsm_x4t(vh + 4 * np, ad);
                ldsm_x4t(vl + 4 * np, ad + AT_TILE);
            }
#pragma unroll
            for (int nt = 0; nt < 8; nt++) {
                uint32_t* bp = vh + (nt >> 1) * 4 + (nt & 1) * 2;
                uint32_t* bl2 = vl + (nt >> 1) * 4 + (nt & 1) * 2;
                mma_f16(oacc[nt], pah, bp);
                mma_f16(oacc[nt], pah, bl2);
            }
        }
        __syncthreads();
        if (kt + 2 <= qi) ISSUE_KV(kt + 2);
    }
#undef ISSUE_KV

    float inv0 = 1.f / lrow[0], inv1 = 1.f / lrow[1];
    int tok0 = b * Tz + qi * 64 + w * 16 + gid;
#pragma unroll
    for (int nt = 0; nt < 8; nt++) {
        int col = h * Dz + 8 * nt + 2 * qid;
        __half2 ph;
        ph.x = __float2half(oacc[nt][0] * inv0);
        ph.y = __float2half(oacc[nt][1] * inv0);
        *(__half2*)(oh + (size_t)tok0 * Cz + col) = ph;
        ph.x = __float2half(oacc[nt][2] * inv1);
        ph.y = __float2half(oacc[nt][3] * inv1);
        *(__half2*)(oh + (size_t)(tok0 + 8) * Cz + col) = ph;
    }
}

// ---------------------------------------------------------------------------
// Embedding
// ---------------------------------------------------------------------------
__global__ void embed_kernel(const int* __restrict__ idx,
                             const float* __restrict__ tok,
                             const float* __restrict__ pos,
                             float* __restrict__ x) {
    int row = blockIdx.x;
    int t   = row & (Tz - 1);
    int tokid = idx[row];
    const float* te = tok + (size_t)tokid * Cz;
    const float* pe = pos + (size_t)t * Cz;
    float* xr = x + (size_t)row * Cz;
    for (int i = threadIdx.x; i < Cz; i += blockDim.x)
        xr[i] = te[i] + pe[i];
}

// ---------------------------------------------------------------------------
// LayerNorm per row, writes fp16 hi/lo pair (lo optional)
// ---------------------------------------------------------------------------
__global__ void ln_kernel(const float* __restrict__ x,
                          __half* __restrict__ yh, __half* __restrict__ yl,
                          const float* __restrict__ g, const float* __restrict__ b) {
    int row = blockIdx.x;
    const float* xr = x + (size_t)row * Cz;
    float s = 0.f, s2 = 0.f;
    for (int i = threadIdx.x; i < Cz; i += blockDim.x) {
        float v = xr[i];
        s += v; s2 += v * v;
    }
    __shared__ float sh_s[8], sh_s2[8];
    for (int off = 16; off > 0; off >>= 1) {
        s  += __shfl_down_sync(0xffffffffu, s,  off);
        s2 += __shfl_down_sync(0xffffffffu, s2, off);
    }
    int lane = threadIdx.x & 31, wid = threadIdx.x >> 5;
    if (lane == 0) { sh_s[wid] = s; sh_s2[wid] = s2; }
    __syncthreads();
    if (wid == 0) {
        s  = (lane < 8) ? sh_s[lane]  : 0.f;
        s2 = (lane < 8) ? sh_s2[lane] : 0.f;
        for (int off = 4; off > 0; off >>= 1) {
            s  += __shfl_down_sync(0xffffffffu, s,  off);
            s2 += __shfl_down_sync(0xffffffffu, s2, off);
        }
        if (lane == 0) { sh_s[0] = s; sh_s2[0] = s2; }
    }
    __syncthreads();
    float mean = sh_s[0] * (1.f / Cz);
    float var  = sh_s2[0] * (1.f / Cz) - mean * mean;
    float rstd = rsqrtf(var + EPSz);
    __half* yhr = yh + (size_t)row * Cz;
    __half* ylr = yl ? (yl + (size_t)row * Cz) : nullptr;
    for (int i = threadIdx.x; i < Cz; i += blockDim.x) {
        float v = (xr[i] - mean) * rstd * g[i] + b[i];
        __half h = __float2half(v);
        yhr[i] = h;
        if (ylr) ylr[i] = __float2half(v - __half2float(h));
    }
}

// ---------------------------------------------------------------------------
// Launch
// ---------------------------------------------------------------------------
extern "C" void kernel_launch(void* const* d_in, const int* in_sizes, int n_in,
                              void* d_out, int out_size) {
    const int*   idx     = (const int*)  d_in[0];
    const float* tok_emb = (const float*)d_in[1];
    const float* pos_emb = (const float*)d_in[2];
    const float* qkv_w   = (const float*)d_in[3];
    const float* proj_w  = (const float*)d_in[4];
    const float* proj_b  = (const float*)d_in[5];
    const float* ln1_g   = (const float*)d_in[6];
    const float* ln1_b   = (const float*)d_in[7];
    const float* ln2_g   = (const float*)d_in[8];
    const float* ln2_b   = (const float*)d_in[9];
    const float* fc1_w   = (const float*)d_in[10];
    const float* fc1_b   = (const float*)d_in[11];
    const float* fc2_w   = (const float*)d_in[12];
    const float* fc2_b   = (const float*)d_in[13];
    const float* lnf_g   = (const float*)d_in[14];
    const float* lnf_b   = (const float*)d_in[15];
    float* out = (float*)d_out;

    float* x;
    cudaGetSymbolAddress((void**)&x, g_x);
    __half *hh, *hl, *qkvh, *qkvl, *atth, *ffnh;
    cudaGetSymbolAddress((void**)&hh,   g_hh);
    cudaGetSymbolAddress((void**)&hl,   g_hl);
    cudaGetSymbolAddress((void**)&qkvh, g_qkvh);
    cudaGetSymbolAddress((void**)&qkvl, g_qkvl);
    cudaGetSymbolAddress((void**)&atth, g_atth);
    cudaGetSymbolAddress((void**)&ffnh, g_ffnh);
    __half *qkvTh, *qkvTl, *projT, *fc1T, *fc2T, *tokT;
    cudaGetSymbolAddress((void**)&qkvTh, g_qkvT_h);
    cudaGetSymbolAddress((void**)&qkvTl, g_qkvT_l);
    cudaGetSymbolAddress((void**)&projT, g_projT);
    cudaGetSymbolAddress((void**)&fc1T,  g_fc1T);
    cudaGetSymbolAddress((void**)&fc2T,  g_fc2T);
    cudaGetSymbolAddress((void**)&tokT,  g_tokT);

    const int GS11 = 3 * 20480;
    const int GS22 = 3 * 40960;
    cudaFuncSetAttribute(gemm_h11, cudaFuncAttributeMaxDynamicSharedMemorySize, GS11);
    cudaFuncSetAttribute(gemm_qkv, cudaFuncAttributeMaxDynamicSharedMemorySize, GS22);
    cudaFuncSetAttribute(attn_mma, cudaFuncAttributeMaxDynamicSharedMemorySize, AT_SMEM);

    // ---- weight prep ----
    dim3 tb(32, 8);
    wtrans_pair<<<dim3(3 * Cz / 32, Cz / 64, Lz), tb>>>(qkv_w, qkvTh, qkvTl, Cz, 3 * Cz);
    wtrans_one<<<dim3(Cz / 32, Cz / 64, Lz), tb>>>(proj_w, projT, Cz, Cz);
    wtrans_one<<<dim3(HIDz / 32, Cz / 64, Lz), tb>>>(fc1_w, fc1T, Cz, HIDz);
    wtrans_one<<<dim3(Cz / 32, HIDz / 64, Lz), tb>>>(fc2_w, fc2T, HIDz, Cz);
    wsplit_one<<<(Vz * Cz + 255) / 256, 256>>>(tok_emb, tokT, Vz * Cz);

    embed_kernel<<<NTOK, 256>>>(idx, tok_emb, pos_emb, x);

    for (int l = 0; l < Lz; l++) {
        const __half* qwh = qkvTh + (size_t)l * 3 * Cz * Cz;
        const __half* qwl = qkvTl + (size_t)l * 3 * Cz * Cz;
        const __half* vwh = qwh + (size_t)2 * Cz * Cz;     // v rows [2048,3072)
        const __half* pw  = projT + (size_t)l * Cz * Cz;
        const __half* w1  = fc1T  + (size_t)l * Cz * HIDz;
        const __half* w2  = fc2T  + (size_t)l * Cz * HIDz;
        const float* pb = proj_b + (size_t)l * Cz;
        const float* b1 = fc1_b  + (size_t)l * HIDz;
        const float* b2 = fc2_b  + (size_t)l * Cz;

        ln_kernel<<<NTOK, 256>>>(x, hh, hl, ln1_g + l * Cz, ln1_b + l * Cz);
        gemm_qkv<<<dim3(24, NTOK / 128), 256, GS22>>>(
            hh, hl, qwh, qwl, vwh, qkvh, qkvl);
        attn_mma<<<dim3(Tz / 64, Bz * Hz), 128, AT_SMEM>>>(qkvh, qkvl, atth);
        gemm_h11<<<dim3(Cz / 128, NTOK / 128), 256, GS11>>>(
            atth, pw, x, nullptr, nullptr,
            Cz, Cz, Cz, pb, x, 0);
        ln_kernel<<<NTOK, 256>>>(x, hh, nullptr, ln2_g + l * Cz, ln2_b + l * Cz);
        gemm_h11<<<dim3(HIDz / 128, NTOK / 128), 256, GS11>>>(
            hh, w1, nullptr, ffnh, nullptr,
            HIDz, Cz, HIDz, b1, nullptr, 1);
        gemm_h11<<<dim3(Cz / 128, NTOK / 128), 256, GS11>>>(
            ffnh, w2, x, nullptr, nullptr,
            Cz, HIDz, Cz, b2, x, 0);
    }

    ln_kernel<<<NTOK, 256>>>(x, hh, nullptr, lnf_g, lnf_b);
    gemm_h11<<<dim3(Vz / 128, NTOK / 128), 256, GS11>>>(
        hh, tokT, out, nullptr, nullptr,
        Vz, Cz, Vz, nullptr, nullptr, 0);
}

// round 16
// speedup vs baseline: 4.3123x; 1.0285x over previous
#include <cuda_runtime.h>
#include <cuda_fp16.h>
#include <cstdint>
#include <math.h>

// Problem constants
#define Bz   2
#define Tz   1024
#define Cz   1024
#define Hz   16
#define Lz   8
#define Dz   64
#define HIDz 4096
#define Vz   32000
#define NTOK (Bz * Tz)          // 2048
#define EPSz 1e-5f

// ---------------------------------------------------------------------------
// PTX helpers (base ISA only)
// ---------------------------------------------------------------------------
__device__ __forceinline__ uint32_t smem_u32(const void* p) {
    uint32_t a;
    asm("{ .reg .u64 t; cvta.to.shared.u64 t, %1; cvt.u32.u64 %0, t; }"
        : "=r"(a) : "l"(p));
    return a;
}
__device__ __forceinline__ void ldsm_x4(uint32_t* r, uint32_t addr) {
    asm volatile("ldmatrix.sync.aligned.m8n8.x4.shared.b16 {%0,%1,%2,%3}, [%4];"
        : "=r"(r[0]), "=r"(r[1]), "=r"(r[2]), "=r"(r[3]) : "r"(addr));
}
__device__ __forceinline__ void ldsm_x4t(uint32_t* r, uint32_t addr) {
    asm volatile("ldmatrix.sync.aligned.m8n8.x4.trans.shared.b16 {%0,%1,%2,%3}, [%4];"
        : "=r"(r[0]), "=r"(r[1]), "=r"(r[2]), "=r"(r[3]) : "r"(addr));
}
__device__ __forceinline__ void mma_f16(float* d, const uint32_t* a, const uint32_t* b) {
    asm volatile("mma.sync.aligned.m16n8k16.row.col.f32.f16.f16.f32 "
        "{%0,%1,%2,%3}, {%4,%5,%6,%7}, {%8,%9}, {%0,%1,%2,%3};"
        : "+f"(d[0]), "+f"(d[1]), "+f"(d[2]), "+f"(d[3])
        : "r"(a[0]), "r"(a[1]), "r"(a[2]), "r"(a[3]), "r"(b[0]), "r"(b[1]));
}
__device__ __forceinline__ void cp16(uint32_t saddr, const void* gaddr) {
    asm volatile("cp.async.ca.shared.global [%0], [%1], 16;"
                 :: "r"(saddr), "l"(gaddr) : "memory");
}
#define CP_COMMIT() asm volatile("cp.async.commit_group;" ::: "memory")
#define CP_WAIT1()  asm volatile("cp.async.wait_group 1;" ::: "memory")
#define CP_WAIT0()  asm volatile("cp.async.wait_group 0;" ::: "memory")

__device__ __forceinline__ uint32_t packh(float x, float y) {
    __half2 t;
    t.x = __float2half(x);
    t.y = __float2half(y);
    return *(uint32_t*)&t;
}

// ---------------------------------------------------------------------------
// Scratch (device globals)
// ---------------------------------------------------------------------------
__device__ float g_x[NTOK * Cz];                 // residual stream
__device__ __half g_hh  [NTOK * Cz];
__device__ __half g_hl  [NTOK * Cz];
__device__ __half g_qkvh[NTOK * 3 * Cz];
__device__ __half g_qkvl[NTOK * 3 * Cz];
__device__ __half g_atth[NTOK * Cz];
__device__ __half g_ffnh[NTOK * HIDz];

// Weights, transposed to [N,K]. qkv = fp16 pair; rest = single fp16.
__device__ __half g_qkvT_h[Lz * 3 * Cz * Cz];
__device__ __half g_qkvT_l[Lz * 3 * Cz * Cz];
__device__ __half g_projT[Lz * Cz * Cz];
__device__ __half g_fc1T [Lz * HIDz * Cz];
__device__ __half g_fc2T [Lz * Cz * HIDz];
__device__ __half g_tokT [Vz * Cz];

// ---------------------------------------------------------------------------
// Weight prep (coalesced transpose, half2 writes)
// ---------------------------------------------------------------------------
__global__ void wtrans_pair(const float* __restrict__ W,
                            __half* __restrict__ Th, __half* __restrict__ Tl,
                            int K, int N) {
    __shared__ float t[64][33];
    const float* Wl = W + (size_t)blockIdx.z * K * N;
    __half* Thg = Th + (size_t)blockIdx.z * K * N;
    __half* Tlg = Tl + (size_t)blockIdx.z * K * N;
    int n0 = blockIdx.x * 32, k0 = blockIdx.y * 64;
    int tx = threadIdx.x, ty = threadIdx.y;
#pragma unroll
    for (int j = 0; j < 64; j += 8)
        t[ty + j][tx] = Wl[(size_t)(k0 + ty + j) * N + n0 + tx];
    __syncthreads();
#pragma unroll
    for (int p = 0; p < 4; p++) {
        int nloc = p * 8 + ty;
        float v0 = t[2 * tx][nloc], v1 = t[2 * tx + 1][nloc];
        __half2 h2, l2;
        h2.x = __float2half(v0);
        h2.y = __float2half(v1);
        l2.x = __float2half(v0 - __half2float(h2.x));
        l2.y = __float2half(v1 - __half2float(h2.y));
        size_t o = (size_t)(n0 + nloc) * K + k0 + 2 * tx;
        *(__half2*)(Thg + o) = h2;
        *(__half2*)(Tlg + o) = l2;
    }
}

__global__ void wtrans_one(const float* __restrict__ W,
                           __half* __restrict__ T, int K, int N) {
    __shared__ float t[64][33];
    const float* Wl = W + (size_t)blockIdx.z * K * N;
    __half* Tg = T + (size_t)blockIdx.z * K * N;
    int n0 = blockIdx.x * 32, k0 = blockIdx.y * 64;
    int tx = threadIdx.x, ty = threadIdx.y;
#pragma unroll
    for (int j = 0; j < 64; j += 8)
        t[ty + j][tx] = Wl[(size_t)(k0 + ty + j) * N + n0 + tx];
    __syncthreads();
#pragma unroll
    for (int p = 0; p < 4; p++) {
        int nloc = p * 8 + ty;
        __half2 h2;
        h2.x = __float2half(t[2 * tx][nloc]);
        h2.y = __float2half(t[2 * tx + 1][nloc]);
        *(__half2*)(Tg + (size_t)(n0 + nloc) * K + k0 + 2 * tx) = h2;
    }
}

__global__ void wsplit_one(const float* __restrict__ W, __half* __restrict__ T, int n) {
    int i = blockIdx.x * blockDim.x + threadIdx.x;
    if (i < n) T[i] = __float2half(W[i]);
}

// ---------------------------------------------------------------------------
// gemm_body<NA,NB,NSTG_>: fp16 mma GEMM core (device function).
// Block 128x128, 8 warps (64x32), BK=32, cp.async pipeline with NSTG_ stages.
// NSTG_=3: prefetch issued before compute (deep pipeline, 1 CTA/SM configs).
// NSTG_=2: prefetch issued after compute barrier (80KB/CTA -> 2 CTAs/SM).
// ---------------------------------------------------------------------------
#define HPITCH 80

template <int NA, int NB, int NSTG_>
__device__ __forceinline__ void gemm_body(
    const __half* __restrict__ Ah, const __half* __restrict__ Al,
    const __half* __restrict__ Bh, const __half* __restrict__ Bl,
    float* __restrict__ Cf, __half* __restrict__ Ch, __half* __restrict__ Cl,
    int N, int K, int ldc,
    const float* __restrict__ bias, const float* __restrict__ res,
    int gelu, int m0, int n0, char* smem) {
    constexpr int STG = (NA + NB) * 10240;
    constexpr int O_AH = 0;
    constexpr int O_AL = 10240;
    constexpr int O_BH = NA * 10240;
    constexpr int O_BL = O_BH + 10240;
    uint32_t sb = smem_u32(smem);
    int tid = threadIdx.x, wid = tid >> 5, lane = tid & 31;
    int wm = wid & 1, wn = wid >> 1;

    const __half* Agh = Ah + (size_t)m0 * K;
    const __half* Agl = (NA == 2) ? (Al + (size_t)m0 * K) : nullptr;
    const __half* Bgh = Bh + (size_t)n0 * K;
    const __half* Bgl = (NB == 2) ? (Bl + (size_t)n0 * K) : nullptr;

    float acc[4][4][4];
#pragma unroll
    for (int i = 0; i < 4; i++)
#pragma unroll
        for (int j = 0; j < 4; j++)
#pragma unroll
            for (int r = 0; r < 4; r++) acc[i][j][r] = 0.f;

    const int NC = K >> 5;

#define ISSUE_H(c)                                                             \
    {                                                                          \
        uint32_t s0 = sb + ((c) % NSTG_) * STG;                                \
        _Pragma("unroll")                                                      \
        for (int it = 0; it < 2; it++) {                                       \
            int i = it * 256 + tid;                                            \
            int row = i >> 2, seg = i & 3;                                     \
            uint32_t so = row * HPITCH + seg * 16;                             \
            size_t go = (size_t)row * K + (size_t)(c) * 32 + seg * 8;          \
            cp16(s0 + O_AH + so, Agh + go);                                    \
            if (NA == 2) cp16(s0 + O_AL + so, Agl + go);                       \
            cp16(s0 + O_BH + so, Bgh + go);                                    \
            if (NB == 2) cp16(s0 + O_BL + so, Bgl + go);                       \
        }                                                                      \
        CP_COMMIT();                                                           \
    }

    ISSUE_H(0);
    ISSUE_H(1);

    int r16 = lane & 15, hsel = lane >> 4;
    int bg = lane >> 3;
    int browoff = ((bg & 2) << 2) + (lane & 7);
    int bkoff = (bg & 1) * 8;

    for (int c = 0; c < NC; c++) {
        if (c + 1 < NC) { CP_WAIT1(); } else { CP_WAIT0(); }
        __syncthreads();
        if (NSTG_ == 3 && c + 2 < NC) ISSUE_H(c + 2);
        uint32_t base = sb + (c % NSTG_) * STG;
#pragma unroll
        for (int kk = 0; kk < 32; kk += 16) {
            uint32_t ah[16], al[16], bh[8], bl[8];
#pragma unroll
            for (int mt = 0; mt < 4; mt++) {
                uint32_t ad = (uint32_t)((wm * 64 + mt * 16 + r16) * HPITCH +
                                         (kk + hsel * 8) * 2);
                ldsm_x4(ah + 4 * mt, base + O_AH + ad);
                if (NA == 2) ldsm_x4(al + 4 * mt, base + O_AL + ad);
            }
#pragma unroll
            for (int ntp = 0; ntp < 2; ntp++) {
                uint32_t bd = (uint32_t)((wn * 32 + ntp * 16 + browoff) * HPITCH +
                                         (kk + bkoff) * 2);
                ldsm_x4(bh + 4 * ntp, base + O_BH + bd);
                if (NB == 2) ldsm_x4(bl + 4 * ntp, base + O_BL + bd);
            }
#pragma unroll
            for (int mt = 0; mt < 4; mt++)
#pragma unroll
                for (int nt = 0; nt < 4; nt++) {
                    uint32_t* bp = bh + (nt >> 1) * 4 + (nt & 1) * 2;
                    mma_f16(acc[mt][nt], ah + 4 * mt, bp);
                    if (NA == 2) mma_f16(acc[mt][nt], al + 4 * mt, bp);
                    if (NB == 2) {
                        uint32_t* bp2 = bl + (nt >> 1) * 4 + (nt & 1) * 2;
                        mma_f16(acc[mt][nt], ah + 4 * mt, bp2);
                    }
                }
        }
        __syncthreads();
        if (NSTG_ == 2 && c + 2 < NC) ISSUE_H(c + 2);
    }
#undef ISSUE_H

    int gid = lane >> 2, qid = lane & 3;
#pragma unroll
    for (int mt = 0; mt < 4; mt++) {
#pragma unroll
        for (int nt = 0; nt < 4; nt++) {
            int n = n0 + wn * 32 + nt * 8 + 2 * qid;
            float bsum0 = bias ? bias[n] : 0.f;
            float bsum1 = bias ? bias[n + 1] : 0.f;
#pragma unroll
            for (int half = 0; half < 2; half++) {
                int m = m0 + wm * 64 + mt * 16 + gid + half * 8;
                float v0 = acc[mt][nt][half * 2 + 0] + bsum0;
                float v1 = acc[mt][nt][half * 2 + 1] + bsum1;
                if (gelu) {
                    v0 = 0.5f * v0 * (1.f + erff(v0 * 0.70710678118654752f));
                    v1 = 0.5f * v1 * (1.f + erff(v1 * 0.70710678118654752f));
                }
                if (res) {
                    const float* rr = res + (size_t)m * ldc + n;
                    v0 += rr[0];
                    v1 += rr[1];
                }
                if (Cf) {
                    float2 o;
                    o.x = v0; o.y = v1;
                    *(float2*)(Cf + (size_t)m * ldc + n) = o;
                }
                if (Ch) {
                    __half2 oh;
                    oh.x = __float2half(v0);
                    oh.y = __float2half(v1);
                    *(__half2*)(Ch + (size_t)m * ldc + n) = oh;
                    if (Cl) {
                        __half2 ol;
                        ol.x = __float2half(v0 - __half2float(oh.x));
                        ol.y = __float2half(v1 - __half2float(oh.y));
                        *(__half2*)(Cl + (size_t)m * ldc + n) = ol;
                    }
                }
            }
        }
    }
}

// 1-pass GEMM, 2 CTAs/SM for wave smoothing + epilogue overlap
__global__ __launch_bounds__(256, 2)
void gemm_h11(const __half* __restrict__ Ah, const __half* __restrict__ Bh,
              float* __restrict__ Cf,
              __half* __restrict__ Ch, __half* __restrict__ Cl,
              int N, int K, int ldc,
              const float* __restrict__ bias, const float* __restrict__ res,
              int gelu) {
    extern __shared__ __align__(128) char smem[];
    gemm_body<1, 1, 3>(Ah, nullptr, Bh, nullptr, Cf, Ch, Cl, N, K, ldc,
                       bias, res, gelu, blockIdx.y * 128, blockIdx.x * 128, smem);
}

// Fused qkv: blockIdx.x < 16 -> q,k (3-pass); else -> v (2-pass).
// NSTG_=2 stages (80KB/CTA) so 2 CTAs/SM co-reside: waves 2.6 -> 1.3.
__global__ __launch_bounds__(256, 2)
void gemm_qkv(const __half* __restrict__ hh, const __half* __restrict__ hl,
              const __half* __restrict__ qkwh, const __half* __restrict__ qkwl,
              const __half* __restrict__ vwh,
              __half* __restrict__ qkvh, __half* __restrict__ qkvl) {
    extern __shared__ __align__(128) char smem[];
    int m0 = blockIdx.y * 128;
    if (blockIdx.x < 16) {
        gemm_body<2, 2, 2>(hh, hl, qkwh, qkwl, nullptr, qkvh, qkvl,
                           2 * Cz, Cz, 3 * Cz, nullptr, nullptr, 0,
                           m0, blockIdx.x * 128, smem);
    } else {
        gemm_body<2, 1, 2>(hh, hl, vwh, nullptr, nullptr,
                           qkvh + 2 * Cz, qkvl + 2 * Cz,
                           Cz, Cz, 3 * Cz, nullptr, nullptr, 0,
                           m0, (blockIdx.x - 16) * 128, smem);
    }
}

// ---------------------------------------------------------------------------
// MMA flash attention. QK^T: 3-pass. P.V: 2-pass (Ph*Vh + Ph*Vl).
// Output: hi only.
// ---------------------------------------------------------------------------
#define APITCH  144
#define AT_TILE 9216
#define AT_Q    0
#define AT_KV0  (2 * AT_TILE)
#define AT_KVS  (4 * AT_TILE)
#define AT_SMEM (AT_KV0 + 2 * AT_KVS)

__global__ __launch_bounds__(128)
void attn_mma(const __half* __restrict__ qkvh,
              const __half* __restrict__ qkvl,
              __half* __restrict__ oh) {
    extern __shared__ __align__(128) char smem[];
    uint32_t sb = smem_u32(smem);
    int tid = threadIdx.x, w = tid >> 5, lane = tid & 31;
    int qi = (int)gridDim.x - 1 - (int)blockIdx.x;
    int bh = blockIdx.y;
    int b = bh >> 4, h = bh & 15;
    const int RS = 3 * Cz;
    const size_t tokbase = (size_t)(b * Tz) * RS + h * Dz;

    int gid = lane >> 2, qid = lane & 3;
    int r16 = lane & 15, hsel = lane >> 4;
    int bg = lane >> 3;
    int browoff = ((bg & 2) << 2) + (lane & 7);
    int bkoff = (bg & 1) * 8;
    int t_row = (bg & 1) * 8 + (lane & 7);
    int t_col = (bg >> 1) * 8;

#define ISSUE_KV(kt)                                                           \
    {                                                                          \
        uint32_t s0 = sb + AT_KV0 + ((kt) & 1) * AT_KVS;                       \
        const __half* srcs[4] = {                                              \
            qkvh + tokbase + Cz, qkvl + tokbase + Cz,                          \
            qkvh + tokbase + 2 * Cz, qkvl + tokbase + 2 * Cz };                \
        _Pragma("unroll")                                                      \
        for (int t = 0; t < 4; t++) {                                          \
            _Pragma("unroll")                                                  \
            for (int it = 0; it < 4; it++) {                                   \
                int i = it * 128 + tid;                                        \
                int r = i >> 3, s = i & 7;                                     \
                cp16(s0 + t * AT_TILE + r * APITCH + s * 16,                   \
                     srcs[t] + (size_t)((kt) * 64 + r) * RS + s * 8);          \
            }                                                                  \
        }                                                                      \
        CP_COMMIT();                                                           \
    }

    {
#pragma unroll
        for (int t = 0; t < 2; t++) {
            const __half* src = (t ? qkvl : qkvh) + tokbase;
            uint32_t dst = sb + AT_Q + t * AT_TILE;
#pragma unroll
            for (int it = 0; it < 4; it++) {
                int i = it * 128 + tid;
                int r = i >> 3, s = i & 7;
                cp16(dst + r * APITCH + s * 16,
                     src + (size_t)(qi * 64 + r) * RS + s * 8);
            }
        }
        uint32_t s0 = sb + AT_KV0;
        const __half* srcs[4] = {
            qkvh + tokbase + Cz, qkvl + tokbase + Cz,
            qkvh + tokbase + 2 * Cz, qkvl + tokbase + 2 * Cz };
#pragma unroll
        for (int t = 0; t < 4; t++) {
#pragma unroll
            for (int it = 0; it < 4; it++) {
                int i = it * 128 + tid;
                int r = i >> 3, s = i & 7;
                cp16(s0 + t * AT_TILE + r * APITCH + s * 16,
                     srcs[t] + (size_t)r * RS + s * 8);
            }
        }
        CP_COMMIT();
    }
    if (qi >= 1) ISSUE_KV(1);

    if (qi >= 1) { CP_WAIT1(); } else { CP_WAIT0(); }
    __syncthreads();

    uint32_t qfh[4][4], qfl[4][4];
#pragma unroll
    for (int kk = 0; kk < 4; kk++) {
        uint32_t ad = sb + AT_Q + (uint32_t)((w * 16 + r16) * APITCH +
                                             (kk * 16 + hsel * 8) * 2);
        ldsm_x4(qfh[kk], ad);
        ldsm_x4(qfl[kk], ad + AT_TILE);
    }

    float oacc[8][4];
#pragma unroll
    for (int i = 0; i < 8; i++)
#pragma unroll
        for (int j = 0; j < 4; j++) oacc[i][j] = 0.f;
    float mrow[2] = {-1e30f, -1e30f};
    float lrow[2] = {0.f, 0.f};

    for (int kt = 0; kt <= qi; kt++) {
        if (kt > 0) {
            if (kt < qi) { CP_WAIT1(); } else { CP_WAIT0(); }
            __syncthreads();
        }
        uint32_t kb = sb + AT_KV0 + (kt & 1) * AT_KVS;

        float s[8][4];
#pragma unroll
        for (int i = 0; i < 8; i++)
#pragma unroll
            for (int j = 0; j < 4; j++) s[i][j] = 0.f;
#pragma unroll
        for (int kk = 0; kk < 4; kk++) {
            uint32_t kh[16], kl[16];
#pragma unroll
            for (int np = 0; np < 4; np++) {
                uint32_t ad = kb + (uint32_t)((np * 16 + browoff) * APITCH +
                                              (kk * 16 + bkoff) * 2);
                ldsm_x4(kh + 4 * np, ad);
                ldsm_x4(kl + 4 * np, ad + AT_TILE);
            }
#pragma unroll
            for (int nt = 0; nt < 8; nt++) {
                uint32_t* bp = kh + (nt >> 1) * 4 + (nt & 1) * 2;
                uint32_t* bl2 = kl + (nt >> 1) * 4 + (nt & 1) * 2;
                mma_f16(s[nt], qfh[kk], bp);
                mma_f16(s[nt], qfh[kk], bl2);
                mma_f16(s[nt], qfl[kk], bp);
            }
        }
#pragma unroll
        for (int nt = 0; nt < 8; nt++)
#pragma unroll
            for (int j = 0; j < 4; j++) s[nt][j] *= 0.125f;
        if (kt == qi) {
#pragma unroll
            for (int nt = 0; nt < 8; nt++)
#pragma unroll
                for (int j = 0; j < 4; j++) {
                    int kc = 8 * nt + 2 * qid + (j & 1);
                    int qr = w * 16 + gid + (j >> 1) * 8;
                    if (kc > qr) s[nt][j] = -1e30f;
                }
        }
        float mt0 = -1e30f, mt1 = -1e30f;
#pragma unroll
        for (int nt = 0; nt < 8; nt++) {
            mt0 = fmaxf(mt0, fmaxf(s[nt][0], s[nt][1]));
            mt1 = fmaxf(mt1, fmaxf(s[nt][2], s[nt][3]));
        }
        mt0 = fmaxf(mt0, __shfl_xor_sync(0xffffffffu, mt0, 1));
        mt0 = fmaxf(mt0, __shfl_xor_sync(0xffffffffu, mt0, 2));
        mt1 = fmaxf(mt1, __shfl_xor_sync(0xffffffffu, mt1, 1));
        mt1 = fmaxf(mt1, __shfl_xor_sync(0xffffffffu, mt1, 2));
        float mn0 = fmaxf(mrow[0], mt0), mn1 = fmaxf(mrow[1], mt1);
        float c0 = __expf(mrow[0] - mn0), c1 = __expf(mrow[1] - mn1);
        mrow[0] = mn0; mrow[1] = mn1;
        float rs0 = 0.f, rs1 = 0.f;
#pragma unroll
        for (int nt = 0; nt < 8; nt++) {
            s[nt][0] = __expf(s[nt][0] - mn0);
            s[nt][1] = __expf(s[nt][1] - mn0);
            s[nt][2] = __expf(s[nt][2] - mn1);
            s[nt][3] = __expf(s[nt][3] - mn1);
            rs0 += s[nt][0] + s[nt][1];
            rs1 += s[nt][2] + s[nt][3];
        }
        rs0 += __shfl_xor_sync(0xffffffffu, rs0, 1);
        rs0 += __shfl_xor_sync(0xffffffffu, rs0, 2);
        rs1 += __shfl_xor_sync(0xffffffffu, rs1, 1);
        rs1 += __shfl_xor_sync(0xffffffffu, rs1, 2);
        lrow[0] = lrow[0] * c0 + rs0;
        lrow[1] = lrow[1] * c1 + rs1;
#pragma unroll
        for (int nt = 0; nt < 8; nt++) {
            oacc[nt][0] *= c0; oacc[nt][1] *= c0;
            oacc[nt][2] *= c1; oacc[nt][3] *= c1;
        }
#pragma unroll
        for (int k2 = 0; k2 < 4; k2++) {
            uint32_t pah[4];
            pah[0] = packh(s[2 * k2][0], s[2 * k2][1]);
            pah[1] = packh(s[2 * k2][2], s[2 * k2][3]);
            pah[2] = packh(s[2 * k2 + 1][0], s[2 * k2 + 1][1]);
            pah[3] = packh(s[2 * k2 + 1][2], s[2 * k2 + 1][3]);
            uint32_t vh[16], vl[16];
#pragma unroll
            for (int np = 0; np < 4; np++) {
                uint32_t ad = kb + 2 * AT_TILE +
                              (uint32_t)((k2 * 16 + t_row) * APITCH +
                                         (np * 16 + t_col) * 2);
                ldsm_x4t(vh + 4 * np, ad);
                ldsm_x4t(vl + 4 * np, ad + AT_TILE);
            }
#pragma unroll
            for (int nt = 0; nt < 8; nt++) {
                uint32_t* bp = vh + (nt >> 1) * 4 + (nt & 1) * 2;
                uint32_t* bl2 = vl + (nt >> 1) * 4 + (nt & 1) * 2;
                mma_f16(oacc[nt], pah, bp);
                mma_f16(oacc[nt], pah, bl2);
            }
        }
        __syncthreads();
        if (kt + 2 <= qi) ISSUE_KV(kt + 2);
    }
#undef ISSUE_KV

    float inv0 = 1.f / lrow[0], inv1 = 1.f / lrow[1];
    int tok0 = b * Tz + qi * 64 + w * 16 + gid;
#pragma unroll
    for (int nt = 0; nt < 8; nt++) {
        int col = h * Dz + 8 * nt + 2 * qid;
        __half2 ph;
        ph.x = __float2half(oacc[nt][0] * inv0);
        ph.y = __float2half(oacc[nt][1] * inv0);
        *(__half2*)(oh + (size_t)tok0 * Cz + col) = ph;
        ph.x = __float2half(oacc[nt][2] * inv1);
        ph.y = __float2half(oacc[nt][3] * inv1);
        *(__half2*)(oh + (size_t)(tok0 + 8) * Cz + col) = ph;
    }
}

// ---------------------------------------------------------------------------
// Embedding
// ---------------------------------------------------------------------------
__global__ void embed_kernel(const int* __restrict__ idx,
                             const float* __restrict__ tok,
                             const float* __restrict__ pos,
                             float* __restrict__ x) {
    int row = blockIdx.x;
    int t   = row & (Tz - 1);
    int tokid = idx[row];
    const float* te = tok + (size_t)tokid * Cz;
    const float* pe = pos + (size_t)t * Cz;
    float* xr = x + (size_t)row * Cz;
    for (int i = threadIdx.x; i < Cz; i += blockDim.x)
        xr[i] = te[i] + pe[i];
}

// ---------------------------------------------------------------------------
// LayerNorm per row, writes fp16 hi/lo pair (lo optional)
// ---------------------------------------------------------------------------
__global__ void ln_kernel(const float* __restrict__ x,
                          __half* __restrict__ yh, __half* __restrict__ yl,
                          const float* __restrict__ g, const float* __restrict__ b) {
    int row = blockIdx.x;
    const float* xr = x + (size_t)row * Cz;
    float s = 0.f, s2 = 0.f;
    for (int i = threadIdx.x; i < Cz; i += blockDim.x) {
        float v = xr[i];
        s += v; s2 += v * v;
    }
    __shared__ float sh_s[8], sh_s2[8];
    for (int off = 16; off > 0; off >>= 1) {
        s  += __shfl_down_sync(0xffffffffu, s,  off);
        s2 += __shfl_down_sync(0xffffffffu, s2, off);
    }
    int lane = threadIdx.x & 31, wid = threadIdx.x >> 5;
    if (lane == 0) { sh_s[wid] = s; sh_s2[wid] = s2; }
    __syncthreads();
    if (wid == 0) {
        s  = (lane < 8) ? sh_s[lane]  : 0.f;
        s2 = (lane < 8) ? sh_s2[lane] : 0.f;
        for (int off = 4; off > 0; off >>= 1) {
            s  += __shfl_down_sync(0xffffffffu, s,  off);
            s2 += __shfl_down_sync(0xffffffffu, s2, off);
        }
        if (lane == 0) { sh_s[0] = s; sh_s2[0] = s2; }
    }
    __syncthreads();
    float mean = sh_s[0] * (1.f / Cz);
    float var  = sh_s2[0] * (1.f / Cz) - mean * mean;
    float rstd = rsqrtf(var + EPSz);
    __half* yhr = yh + (size_t)row * Cz;
    __half* ylr = yl ? (yl + (size_t)row * Cz) : nullptr;
    for (int i = threadIdx.x; i < Cz; i += blockDim.x) {
        float v = (xr[i] - mean) * rstd * g[i] + b[i];
        __half h = __float2half(v);
        yhr[i] = h;
        if (ylr) ylr[i] = __float2half(v - __half2float(h));
    }
}

// ---------------------------------------------------------------------------
// Launch
// ---------------------------------------------------------------------------
extern "C" void kernel_launch(void* const* d_in, const int* in_sizes, int n_in,
                              void* d_out, int out_size) {
    const int*   idx     = (const int*)  d_in[0];
    const float* tok_emb = (const float*)d_in[1];
    const float* pos_emb = (const float*)d_in[2];
    const float* qkv_w   = (const float*)d_in[3];
    const float* proj_w  = (const float*)d_in[4];
    const float* proj_b  = (const float*)d_in[5];
    const float* ln1_g   = (const float*)d_in[6];
    const float* ln1_b   = (const float*)d_in[7];
    const float* ln2_g   = (const float*)d_in[8];
    const float* ln2_b   = (const float*)d_in[9];
    const float* fc1_w   = (const float*)d_in[10];
    const float* fc1_b   = (const float*)d_in[11];
    const float* fc2_w   = (const float*)d_in[12];
    const float* fc2_b   = (const float*)d_in[13];
    const float* lnf_g   = (const float*)d_in[14];
    const float* lnf_b   = (const float*)d_in[15];
    float* out = (float*)d_out;

    float* x;
    cudaGetSymbolAddress((void**)&x, g_x);
    __half *hh, *hl, *qkvh, *qkvl, *atth, *ffnh;
    cudaGetSymbolAddress((void**)&hh,   g_hh);
    cudaGetSymbolAddress((void**)&hl,   g_hl);
    cudaGetSymbolAddress((void**)&qkvh, g_qkvh);
    cudaGetSymbolAddress((void**)&qkvl, g_qkvl);
    cudaGetSymbolAddress((void**)&atth, g_atth);
    cudaGetSymbolAddress((void**)&ffnh, g_ffnh);
    __half *qkvTh, *qkvTl, *projT, *fc1T, *fc2T, *tokT;
    cudaGetSymbolAddress((void**)&qkvTh, g_qkvT_h);
    cudaGetSymbolAddress((void**)&qkvTl, g_qkvT_l);
    cudaGetSymbolAddress((void**)&projT, g_projT);
    cudaGetSymbolAddress((void**)&fc1T,  g_fc1T);
    cudaGetSymbolAddress((void**)&fc2T,  g_fc2T);
    cudaGetSymbolAddress((void**)&tokT,  g_tokT);

    const int GS11 = 3 * 20480;
    const int GSQ  = 2 * 40960;       // NSTG_=2 stages for the fused qkv
    cudaFuncSetAttribute(gemm_h11, cudaFuncAttributeMaxDynamicSharedMemorySize, GS11);
    cudaFuncSetAttribute(gemm_qkv, cudaFuncAttributeMaxDynamicSharedMemorySize, GSQ);
    cudaFuncSetAttribute(attn_mma, cudaFuncAttributeMaxDynamicSharedMemorySize, AT_SMEM);

    // ---- weight prep ----
    dim3 tb(32, 8);
    wtrans_pair<<<dim3(3 * Cz / 32, Cz / 64, Lz), tb>>>(qkv_w, qkvTh, qkvTl, Cz, 3 * Cz);
    wtrans_one<<<dim3(Cz / 32, Cz / 64, Lz), tb>>>(proj_w, projT, Cz, Cz);
    wtrans_one<<<dim3(HIDz / 32, Cz / 64, Lz), tb>>>(fc1_w, fc1T, Cz, HIDz);
    wtrans_one<<<dim3(Cz / 32, HIDz / 64, Lz), tb>>>(fc2_w, fc2T, HIDz, Cz);
    wsplit_one<<<(Vz * Cz + 255) / 256, 256>>>(tok_emb, tokT, Vz * Cz);

    embed_kernel<<<NTOK, 256>>>(idx, tok_emb, pos_emb, x);

    for (int l = 0; l < Lz; l++) {
        const __half* qwh = qkvTh + (size_t)l * 3 * Cz * Cz;
        const __half* qwl = qkvTl + (size_t)l * 3 * Cz * Cz;
        const __half* vwh = qwh + (size_t)2 * Cz * Cz;     // v rows [2048,3072)
        const __half* pw  = projT + (size_t)l * Cz * Cz;
        const __half* w1  = fc1T  + (size_t)l * Cz * HIDz;
        const __half* w2  = fc2T  + (size_t)l * Cz * HIDz;
        const float* pb = proj_b + (size_t)l * Cz;
        const float* b1 = fc1_b  + (size_t)l * HIDz;
        const float* b2 = fc2_b  + (size_t)l * Cz;

        ln_kernel<<<NTOK, 256>>>(x, hh, hl, ln1_g + l * Cz, ln1_b + l * Cz);
        gemm_qkv<<<dim3(24, NTOK / 128), 256, GSQ>>>(
            hh, hl, qwh, qwl, vwh, qkvh, qkvl);
        attn_mma<<<dim3(Tz / 64, Bz * Hz), 128, AT_SMEM>>>(qkvh, qkvl, atth);
        gemm_h11<<<dim3(Cz / 128, NTOK / 128), 256, GS11>>>(
            atth, pw, x, nullptr, nullptr,
            Cz, Cz, Cz, pb, x, 0);
        ln_kernel<<<NTOK, 256>>>(x, hh, nullptr, ln2_g + l * Cz, ln2_b + l * Cz);
        gemm_h11<<<dim3(HIDz / 128, NTOK / 128), 256, GS11>>>(
            hh, w1, nullptr, ffnh, nullptr,
            HIDz, Cz, HIDz, b1, nullptr, 1);
        gemm_h11<<<dim3(Cz / 128, NTOK / 128), 256, GS11>>>(
            ffnh, w2, x, nullptr, nullptr,
            Cz, HIDz, Cz, b2, x, 0);
    }

    ln_kernel<<<NTOK, 256>>>(x, hh, nullptr, lnf_g, lnf_b);
    gemm_h11<<<dim3(Vz / 128, NTOK / 128), 256, GS11>>>(
        hh, tokT, out, nullptr, nullptr,
        Vz, Cz, Vz, nullptr, nullptr, 0);
}